// round 8
// baseline (speedup 1.0000x reference)
#include <cuda_runtime.h>
#include <cuda_fp16.h>
#include <math.h>
#include <stddef.h>
#include <stdint.h>

// Problem constants
#define Bc 2
#define Lc 2048
#define Dc 1024
#define Hc 16
#define Mrows (Bc*Lc)            /* 4096 */
#define BHc (Bc*Hc)              /* 32 */

// ---------------------------------------------------------------------------
// Scratch (device globals -- no allocation allowed)
// ---------------------------------------------------------------------------
__device__ __align__(16) __half g_QH[(size_t)BHc*Lc*64];    // [B,H,L,64] fp16
__device__ __align__(16) __half g_KH[(size_t)BHc*Lc*64];    // [B,H,L,64] fp16
__device__ __align__(16) __half g_VT[(size_t)BHc*64*Lc];    // [B,H,64,L] fp16
__device__ __align__(16) float  g_OH[(size_t)Mrows*Dc];     // [B,L,H*DV]
__device__ __align__(16) float  g_OPRE[(size_t)Mrows*Dc];   // pre-LayerNorm
__device__ __align__(16) __half g_WTQ[(size_t)Dc*Dc];       // [N,K] fp16
__device__ __align__(16) __half g_WTK[(size_t)Dc*Dc];
__device__ __align__(16) __half g_WTV[(size_t)Dc*Dc];
__device__ __align__(16) __half g_WTO[(size_t)Dc*Dc];
__device__ __align__(16) uint32_t g_BM[(size_t)Mrows*64];   // mask bits [B*L][64]

// ---------------------------------------------------------------------------
// helpers
// ---------------------------------------------------------------------------
__device__ __forceinline__ uint32_t h2(float a, float b) {
    __half2 h = __floats2half2_rn(a, b);
    return *(uint32_t*)&h;
}
__device__ __forceinline__ float ex2(float x) {
    float r;
    asm("ex2.approx.ftz.f32 %0, %1;" : "=f"(r) : "f"(x));
    return r;
}
__device__ __forceinline__ void mma16(float* c, const uint32_t* a, const uint32_t* b) {
    asm volatile(
        "mma.sync.aligned.m16n8k16.row.col.f32.f16.f16.f32 "
        "{%0,%1,%2,%3}, {%4,%5,%6,%7}, {%8,%9}, {%0,%1,%2,%3};"
        : "+f"(c[0]), "+f"(c[1]), "+f"(c[2]), "+f"(c[3])
        : "r"(a[0]), "r"(a[1]), "r"(a[2]), "r"(a[3]), "r"(b[0]), "r"(b[1]));
}

// ---------------------------------------------------------------------------
// fp16 warp-MMA GEMM for projections (unchanged from round 7).
// ---------------------------------------------------------------------------
#define SPAD2 20

template<int EPI, int KTOT>
__global__ void __launch_bounds__(256, 2)
gemm_h(const float* __restrict__ A, const __half* __restrict__ Bh,
       void* __restrict__ Cv, const float* __restrict__ resid, float scale)
{
    constexpr int NC = KTOT / 32;
    __shared__ uint32_t As[128 * SPAD2];
    __shared__ uint32_t Bs[64 * SPAD2];

    const int tid = threadIdx.x;
    const int wid = tid >> 5, lane = tid & 31;
    const int wm  = wid >> 1, wn = wid & 1;
    const int g   = lane >> 2, tq = lane & 3;
    const int m0  = blockIdx.y * 128;
    const int n0  = blockIdx.x * 64;

    const int arow = tid >> 3, ac4 = (tid & 7) * 4;
    const int brow = tid >> 2, bc4 = (tid & 3) * 4;
    const uint32_t* Bg = (const uint32_t*)Bh;

    float4 pa[4];
    uint4  pb;
    float acc[2][4][4] = {};

    auto g2r = [&](int c) {
        const int kc = c * 32;
#pragma unroll
        for (int j = 0; j < 4; j++)
            pa[j] = *(const float4*)(A + (size_t)(m0 + arow + j * 32) * KTOT + kc + ac4);
        pb = *(const uint4*)(Bg + (size_t)(n0 + brow) * (KTOT / 2) + c * 16 + bc4);
    };
    auto r2s = [&]() {
#pragma unroll
        for (int j = 0; j < 4; j++) {
            uint2 t = { h2(pa[j].x, pa[j].y), h2(pa[j].z, pa[j].w) };
            *(uint2*)&As[(arow + j * 32) * SPAD2 + ac4 / 2] = t;
        }
        *(uint4*)&Bs[brow * SPAD2 + bc4] = pb;
    };

    g2r(0);
    for (int c = 0; c < NC; c++) {
        r2s();
        __syncthreads();
        if (c + 1 < NC) g2r(c + 1);

#pragma unroll
        for (int ks = 0; ks < 2; ks++) {
            uint32_t af[2][4], bf[4][2];
#pragma unroll
            for (int mi = 0; mi < 2; mi++) {
                int rb = (wm * 32 + mi * 16 + g) * SPAD2 + ks * 8 + tq;
                af[mi][0] = As[rb];
                af[mi][1] = As[rb + 8 * SPAD2];
                af[mi][2] = As[rb + 4];
                af[mi][3] = As[rb + 8 * SPAD2 + 4];
            }
#pragma unroll
            for (int ni = 0; ni < 4; ni++) {
                int rb = (wn * 32 + ni * 8 + g) * SPAD2 + ks * 8 + tq;
                bf[ni][0] = Bs[rb];
                bf[ni][1] = Bs[rb + 4];
            }
#pragma unroll
            for (int mi = 0; mi < 2; mi++)
#pragma unroll
                for (int ni = 0; ni < 4; ni++)
                    mma16(acc[mi][ni], af[mi], bf[ni]);
        }
        __syncthreads();
    }

#pragma unroll
    for (int mi = 0; mi < 2; mi++) {
#pragma unroll
        for (int ni = 0; ni < 4; ni++) {
            const float* a = acc[mi][ni];
            int r0  = m0 + wm * 32 + mi * 16 + g;
            int col = n0 + wn * 32 + ni * 8 + 2 * tq;

            if (EPI == 0) {
                uint32_t* C = (uint32_t*)Cv;
                int h = col >> 6, dk = col & 63;
#pragma unroll
                for (int p = 0; p < 2; p++) {
                    int m = r0 + p * 8;
                    int b_ = m >> 11, l = m & (Lc - 1);
                    C[((((size_t)b_ * Hc + h) * Lc + l) * 64 + dk) >> 1] =
                        h2(a[2*p] * scale, a[2*p+1] * scale);
                }
            } else if (EPI == 1) {
                __half* C = (__half*)Cv;
                int h = col >> 6, dv = col & 63;
#pragma unroll
                for (int p = 0; p < 2; p++) {
                    int m = r0 + p * 8;
                    int b_ = m >> 11, l = m & (Lc - 1);
                    size_t base = ((size_t)b_ * Hc + h) * 64;
                    C[(base + dv)     * Lc + l] = __float2half(a[2*p]);
                    C[(base + dv + 1) * Lc + l] = __float2half(a[2*p+1]);
                }
            } else {
                float* C = (float*)Cv;
#pragma unroll
                for (int p = 0; p < 2; p++) {
                    int m = r0 + p * 8;
                    size_t off = (size_t)m * Dc + col;
                    float2 r4 = *(const float2*)&resid[off];
                    float2 o = { a[2*p] + r4.x, a[2*p+1] + r4.y };
                    *(float2*)&C[off] = o;
                }
            }
        }
    }
}

// ---------------------------------------------------------------------------
// Mask compress: int32 [B*L][2048] -> bits [B*L][64]
// ---------------------------------------------------------------------------
__global__ void __launch_bounds__(256)
maskbits_k(const int* __restrict__ mask, uint32_t* __restrict__ bm)
{
    const int w = threadIdx.x >> 5, lane = threadIdx.x & 31;
    const int row = blockIdx.x * 8 + w;
    const int* mr = mask + (size_t)row * Lc;
    uint32_t* br = bm + (size_t)row * 64;
#pragma unroll 8
    for (int it = 0; it < 64; it++) {
        int v = mr[it * 32 + lane];
        uint32_t bits = __ballot_sync(0xffffffffu, v != 0);
        if (lane == 0) br[it] = bits;
    }
}

// ---------------------------------------------------------------------------
// Flash v4: block = (z, 32 queries). Full 32x2048 fp16 unnormalized-P row
// resident in smem. One score pass (MMA+mask+exp2+rowsum), then normalized
// attn written straight from smem, then PV (split-k over 4 warp groups) with
// smem reduction. No rescale kernel, exp evaluated exactly once per element.
// ---------------------------------------------------------------------------
#define SSP 1028   /* sS u32 row stride (1024 + 4) */
#define KS  36     /* K/Q u32 row stride (32 + 4)  */
#define VS  68     /* V u32 row stride (64 + 4)    */
// u32 layout:
#define OFF_S  0
#define OFF_Q  (32*SSP)                 /* 32896 */
#define OFF_KV (OFF_Q + 32*KS)          /* 34048, two bufs of 4608 */
#define OFF_B  (OFF_KV + 2*4608)        /* 43264, two bufs of 128  */
#define OFF_SU (OFF_B + 256)            /* 43520, [8][32] floats   */
#define OFF_IV (OFF_SU + 256)           /* 43776, [32] floats      */
#define FSMEM2 ((OFF_IV + 32) * 4)      /* 175232 bytes            */

__global__ void __launch_bounds__(256, 1)
flash_k(const __half* __restrict__ QH, const __half* __restrict__ KH,
        const __half* __restrict__ VT, const uint32_t* __restrict__ BM,
        float* __restrict__ OH, float* __restrict__ attn, int write_attn)
{
    extern __shared__ uint32_t fs[];
    uint32_t* sS  = fs + OFF_S;
    uint32_t* sQ  = fs + OFF_Q;
    uint32_t* sKV = fs + OFF_KV;
    uint32_t* sB  = fs + OFF_B;
    float*  sSum  = (float*)(fs + OFF_SU);
    float*  sInv  = (float*)(fs + OFF_IV);

    const int tid = threadIdx.x, wid = tid >> 5, lane = tid & 31;
    const int g = lane >> 2, tq = lane & 3;
    const int z = blockIdx.y, m0 = blockIdx.x * 32;
    const int b_ = z >> 4, h = z & 15;

    // ---- Q tile: 32 rows x 8 uint4 = 256 ----
    {
        const uint4* Qz = (const uint4*)(QH + ((size_t)z * Lc + m0) * 64);
        int row = tid >> 3, q4 = tid & 7;
        uint4 v = Qz[row * 8 + q4];
        *(uint4*)&sQ[row * KS + q4 * 4] = v;
    }

    const uint4* Kz0 = (const uint4*)(KH + (size_t)z * Lc * 64);
    const uint32_t* BMb = BM + ((size_t)b_ * Lc + m0) * 64;

    uint4 pk[4];
    uint32_t pbw;
    auto ldgK = [&](int kt) {
        const uint4* Kz = Kz0 + (size_t)kt * 128 * 8;
#pragma unroll
        for (int i = 0; i < 4; i++) {
            int slot = tid + i * 256, row = slot >> 3, q4 = slot & 7;
            pk[i] = Kz[row * 8 + q4];
        }
    };
    auto stsK = [&](int buf) {
        uint32_t* d = sKV + buf * 4608;
#pragma unroll
        for (int i = 0; i < 4; i++) {
            int slot = tid + i * 256, row = slot >> 3, q4 = slot & 7;
            *(uint4*)&d[row * KS + q4 * 4] = pk[i];
        }
    };
    auto ldgB = [&](int kt) {
        if (tid < 128)
            pbw = BMb[(size_t)(tid >> 2) * 64 + kt * 4 + (tid & 3)];
    };
    auto stsB = [&](int buf) {
        if (tid < 128) sB[buf * 128 + tid] = pbw;
    };

    float rs[4] = { 0.f, 0.f, 0.f, 0.f };

    // ================= phase A: scores + exp + P stage + rowsums ==========
    ldgK(0); ldgB(0); stsK(0);
    for (int kt = 0; kt < 16; kt++) {
        stsB(kt & 1);
        __syncthreads();
        if (kt + 1 < 16) { ldgK(kt + 1); ldgB(kt + 1); }

        const uint32_t* Kb = sKV + (kt & 1) * 4608;
        float acc[2][2][4];
#pragma unroll
        for (int mi = 0; mi < 2; mi++)
#pragma unroll
            for (int ni = 0; ni < 2; ni++)
#pragma unroll
                for (int q = 0; q < 4; q++) acc[mi][ni][q] = 0.f;

#pragma unroll
        for (int ks = 0; ks < 4; ks++) {
            uint32_t af[2][4];
#pragma unroll
            for (int mi = 0; mi < 2; mi++) {
                int r = mi * 16 + g;
                af[mi][0] = sQ[r * KS + ks * 8 + tq];
                af[mi][1] = sQ[(r + 8) * KS + ks * 8 + tq];
                af[mi][2] = sQ[r * KS + ks * 8 + tq + 4];
                af[mi][3] = sQ[(r + 8) * KS + ks * 8 + tq + 4];
            }
#pragma unroll
            for (int ni = 0; ni < 2; ni++) {
                int n = wid * 16 + ni * 8 + g;
                uint32_t bf[2] = { Kb[n * KS + ks * 8 + tq], Kb[n * KS + ks * 8 + tq + 4] };
                mma16(acc[0][ni], af[0], bf);
                mma16(acc[1][ni], af[1], bf);
            }
        }
        if (kt + 1 < 16) stsK((kt + 1) & 1);

        const uint32_t* Bb = sB + (kt & 1) * 128;
#pragma unroll
        for (int mi = 0; mi < 2; mi++) {
            int r0 = mi * 16 + g, r1 = r0 + 8;
#pragma unroll
            for (int ni = 0; ni < 2; ni++) {
                int cw = wid * 16 + ni * 8;
                int word = cw >> 5, sh = (cw & 31) + 2 * tq;
                uint32_t w0 = Bb[r0 * 4 + word] >> sh;
                uint32_t w1 = Bb[r1 * 4 + word] >> sh;
                float p0 = (w0 & 1) ? ex2(acc[mi][ni][0]) : 0.f;
                float p1 = (w0 & 2) ? ex2(acc[mi][ni][1]) : 0.f;
                float p2 = (w1 & 1) ? ex2(acc[mi][ni][2]) : 0.f;
                float p3 = (w1 & 2) ? ex2(acc[mi][ni][3]) : 0.f;
                rs[mi * 2]     += p0 + p1;
                rs[mi * 2 + 1] += p2 + p3;
                int cp = kt * 64 + wid * 8 + ni * 4 + tq;
                sS[r0 * SSP + cp] = h2(p0, p1);
                sS[r1 * SSP + cp] = h2(p2, p3);
            }
        }
    }

    // rowsum reduce: quads, then across warps
#pragma unroll
    for (int s = 0; s < 4; s++) {
        rs[s] += __shfl_xor_sync(0xffffffffu, rs[s], 1);
        rs[s] += __shfl_xor_sync(0xffffffffu, rs[s], 2);
    }
    if (tq == 0) {
        sSum[wid * 32 + g]      = rs[0];
        sSum[wid * 32 + g + 8]  = rs[1];
        sSum[wid * 32 + g + 16] = rs[2];
        sSum[wid * 32 + g + 24] = rs[3];
    }
    __syncthreads();
    if (tid < 32) {
        float s = 0.f;
#pragma unroll
        for (int w = 0; w < 8; w++) s += sSum[w * 32 + tid];
        sInv[tid] = 1.f / s;
    }
    __syncthreads();

    // ================= phase C: normalized attn write =====================
    if (write_attn) {
        float* abase = attn + ((size_t)z * Lc + m0) * Lc;
#pragma unroll 4
        for (int i = 0; i < 64; i++) {
            int idx = tid + i * 256;            // uint2 groups (4 fp16 each)
            int row = idx >> 9;
            int cp2 = (idx & 511) * 2;
            uint2 v = *(uint2*)&sS[row * SSP + cp2];
            float inv = sInv[row];
            __half2 ha = *reinterpret_cast<__half2*>(&v.x);
            __half2 hb = *reinterpret_cast<__half2*>(&v.y);
            float2 f0 = __half22float2(ha), f1 = __half22float2(hb);
            float4 o = { f0.x * inv, f0.y * inv, f1.x * inv, f1.y * inv };
            *(float4*)&abase[(size_t)row * Lc + cp2 * 2] = o;
        }
    }

    // ================= phase D: PV (split-k over 4 warp groups) ===========
    const uint4* Vz0 = (const uint4*)(VT + (size_t)z * 64 * Lc);
    uint4 pv[4];
    auto ldgV = [&](int kt) {
#pragma unroll
        for (int i = 0; i < 4; i++) {
            int slot = tid + i * 256, dv = slot >> 4, q4 = slot & 15;
            pv[i] = Vz0[(size_t)dv * (Lc / 8) + kt * 16 + q4];
        }
    };
    auto stsV = [&](int buf) {
        uint32_t* d = sKV + buf * 4608;
#pragma unroll
        for (int i = 0; i < 4; i++) {
            int slot = tid + i * 256, dv = slot >> 4, q4 = slot & 15;
            *(uint4*)&d[dv * VS + q4 * 4] = pv[i];
        }
    };

    const int kg = wid >> 1, dvg = wid & 1;
    float oacc[2][4][4] = {};

    ldgV(0); stsV(0);
    for (int kt = 0; kt < 16; kt++) {
        __syncthreads();
        if (kt + 1 < 16) ldgV(kt + 1);
        const uint32_t* Vb = sKV + (kt & 1) * 4608;
#pragma unroll
        for (int s = 0; s < 2; s++) {
            int ksb = kg * 2 + s;
            int cpb = kt * 64 + ksb * 8;
            uint32_t ap[2][4];
#pragma unroll
            for (int mi = 0; mi < 2; mi++) {
                int r = mi * 16 + g;
                ap[mi][0] = sS[r * SSP + cpb + tq];
                ap[mi][1] = sS[(r + 8) * SSP + cpb + tq];
                ap[mi][2] = sS[r * SSP + cpb + tq + 4];
                ap[mi][3] = sS[(r + 8) * SSP + cpb + tq + 4];
            }
#pragma unroll
            for (int ni = 0; ni < 4; ni++) {
                int dv = dvg * 32 + ni * 8 + g;
                uint32_t bv[2] = { Vb[dv * VS + ksb * 8 + tq], Vb[dv * VS + ksb * 8 + tq + 4] };
                mma16(oacc[0][ni], ap[0], bv);
                mma16(oacc[1][ni], ap[1], bv);
            }
        }
        if (kt + 1 < 16) stsV((kt + 1) & 1);
    }

    // reduce 4 k-partials via smem (reuse sKV region: [4][32][64] floats)
    __syncthreads();
    float* Ored = (float*)sKV;
#pragma unroll
    for (int mi = 0; mi < 2; mi++) {
        int r = mi * 16 + g;
#pragma unroll
        for (int ni = 0; ni < 4; ni++) {
            int col = dvg * 32 + ni * 8 + 2 * tq;
            float2 t0 = { oacc[mi][ni][0], oacc[mi][ni][1] };
            float2 t1 = { oacc[mi][ni][2], oacc[mi][ni][3] };
            *(float2*)&Ored[(kg * 32 + r) * 64 + col] = t0;
            *(float2*)&Ored[(kg * 32 + r + 8) * 64 + col] = t1;
        }
    }
    __syncthreads();
#pragma unroll
    for (int i = 0; i < 8; i++) {
        int idx = tid + i * 256;
        int m = idx >> 6, dv = idx & 63;
        float s = Ored[m * 64 + dv] + Ored[(32 + m) * 64 + dv]
                + Ored[(64 + m) * 64 + dv] + Ored[(96 + m) * 64 + dv];
        OH[((size_t)b_ * Lc + m0 + m) * Dc + h * 64 + dv] = s * sInv[m];
    }
}

// ---------------------------------------------------------------------------
// 1024x1024 transpose + fp16 convert
// ---------------------------------------------------------------------------
__global__ void __launch_bounds__(256)
transpose_k(const float* __restrict__ in, __half* __restrict__ out)
{
    __shared__ float t[32][33];
    int x = blockIdx.x * 32 + threadIdx.x;
    int y0 = blockIdx.y * 32;
#pragma unroll
    for (int j = 0; j < 4; j++)
        t[threadIdx.y + j * 8][threadIdx.x] = in[(size_t)(y0 + threadIdx.y + j * 8) * 1024 + x];
    __syncthreads();
    int x2 = blockIdx.y * 32 + threadIdx.x;
    int y2 = blockIdx.x * 32;
#pragma unroll
    for (int j = 0; j < 4; j++)
        out[(size_t)(y2 + threadIdx.y + j * 8) * 1024 + x2] =
            __float2half(t[threadIdx.x][threadIdx.y + j * 8]);
}

// ---------------------------------------------------------------------------
// LayerNorm over rows of D=1024
// ---------------------------------------------------------------------------
__global__ void __launch_bounds__(256)
ln_k(const float* __restrict__ X, const float* __restrict__ g,
     const float* __restrict__ bta, float* __restrict__ O)
{
    const int t = threadIdx.x;
    const float* x = X + (size_t)blockIdx.x * Dc;
    float4 v = *(const float4*)&x[t * 4];
    float s  = v.x + v.y + v.z + v.w;
    float s2 = v.x * v.x + v.y * v.y + v.z * v.z + v.w * v.w;
#pragma unroll
    for (int o = 16; o; o >>= 1) {
        s  += __shfl_xor_sync(0xffffffffu, s, o);
        s2 += __shfl_xor_sync(0xffffffffu, s2, o);
    }
    __shared__ float rs[8], rs2[8];
    if ((t & 31) == 0) { rs[t >> 5] = s; rs2[t >> 5] = s2; }
    __syncthreads();
    float S = 0.f, S2 = 0.f;
#pragma unroll
    for (int i = 0; i < 8; i++) { S += rs[i]; S2 += rs2[i]; }
    float mean = S * (1.0f / Dc);
    float var  = S2 * (1.0f / Dc) - mean * mean;
    float inv  = rsqrtf(var + 1e-6f);

    float4 gg = *(const float4*)&g[t * 4];
    float4 bb = *(const float4*)&bta[t * 4];
    float4 r;
    r.x = (v.x - mean) * inv * gg.x + bb.x;
    r.y = (v.y - mean) * inv * gg.y + bb.y;
    r.z = (v.z - mean) * inv * gg.z + bb.z;
    r.w = (v.w - mean) * inv * gg.w + bb.w;
    *(float4*)&O[(size_t)blockIdx.x * Dc + t * 4] = r;
}

// ---------------------------------------------------------------------------
// Launch
// ---------------------------------------------------------------------------
extern "C" void kernel_launch(void* const* d_in, const int* in_sizes, int n_in,
                              void* d_out, int out_size)
{
    const float* q    = (const float*)d_in[0];
    const float* k    = (const float*)d_in[1];
    const float* v    = (const float*)d_in[2];
    const int*   mask = (const int*)d_in[3];
    const float* w_q  = (const float*)d_in[4];
    const float* w_k  = (const float*)d_in[5];
    const float* w_v  = (const float*)d_in[6];
    const float* w_o  = (const float*)d_in[7];
    const float* ln_g = (const float*)d_in[8];
    const float* ln_b = (const float*)d_in[9];
    float* out = (float*)d_out;

    __half *pQH, *pKH, *pVT, *pWTQ, *pWTK, *pWTV, *pWTO;
    float *pOH, *pOPRE;
    uint32_t* pBM;
    cudaGetSymbolAddress((void**)&pQH,   g_QH);
    cudaGetSymbolAddress((void**)&pKH,   g_KH);
    cudaGetSymbolAddress((void**)&pVT,   g_VT);
    cudaGetSymbolAddress((void**)&pOH,   g_OH);
    cudaGetSymbolAddress((void**)&pOPRE, g_OPRE);
    cudaGetSymbolAddress((void**)&pWTQ,  g_WTQ);
    cudaGetSymbolAddress((void**)&pWTK,  g_WTK);
    cudaGetSymbolAddress((void**)&pWTV,  g_WTV);
    cudaGetSymbolAddress((void**)&pWTO,  g_WTO);
    cudaGetSymbolAddress((void**)&pBM,   g_BM);

    const long long bld  = (long long)Bc * Lc * Dc;
    const long long bhll = (long long)BHc * Lc * Lc;
    int write_attn = ((long long)out_size >= bld + bhll) ? 1 : 0;
    float* attn_out = out + bld;

    // 1) weight transposes -> fp16 [N,K]; mask bit-compress
    dim3 tb(32, 8), tg(32, 32);
    transpose_k<<<tg, tb>>>(w_q, pWTQ);
    transpose_k<<<tg, tb>>>(w_k, pWTK);
    transpose_k<<<tg, tb>>>(w_v, pWTV);
    transpose_k<<<tg, tb>>>(w_o, pWTO);
    maskbits_k<<<Mrows / 8, 256>>>(mask, pBM);

    // 2) projections (q pre-scaled by log2(e)/8 for exp2-domain softmax)
    dim3 gp(16, 32);
    gemm_h<0,1024><<<gp, 256>>>(q, pWTQ, pQH, nullptr, 0.125f * 1.44269504088896f);
    gemm_h<0,1024><<<gp, 256>>>(k, pWTK, pKH, nullptr, 1.0f);
    gemm_h<1,1024><<<gp, 256>>>(v, pWTV, pVT, nullptr, 1.0f);

    // 3) fully-fused flash: scores + exp + normalized attn + PV (no rescale)
    cudaFuncSetAttribute(flash_k, cudaFuncAttributeMaxDynamicSharedMemorySize, FSMEM2);
    dim3 gf(Lc / 32, BHc);
    flash_k<<<gf, 256, FSMEM2>>>(pQH, pKH, pVT, pBM, pOH, attn_out, write_attn);

    // 4) output projection + residual, then layernorm
    gemm_h<4,1024><<<gp, 256>>>(pOH, pWTO, pOPRE, q, 1.0f);
    ln_k<<<Mrows, 256>>>(pOPRE, ln_g, ln_b, out);
}

// round 9
// speedup vs baseline: 1.0807x; 1.0807x over previous
#include <cuda_runtime.h>
#include <cuda_fp16.h>
#include <math.h>
#include <stddef.h>
#include <stdint.h>

// Problem constants
#define Bc 2
#define Lc 2048
#define Dc 1024
#define Hc 16
#define Mrows (Bc*Lc)            /* 4096 */
#define BHc (Bc*Hc)              /* 32 */

// ---------------------------------------------------------------------------
// Scratch (device globals -- no allocation allowed)
// ---------------------------------------------------------------------------
__device__ __align__(16) __half g_QH[(size_t)BHc*Lc*64];    // [B,H,L,64] fp16
__device__ __align__(16) __half g_KH[(size_t)BHc*Lc*64];    // [B,H,L,64] fp16
__device__ __align__(16) __half g_VT[(size_t)BHc*64*Lc];    // [B,H,64,L] fp16
__device__ __align__(16) float  g_OH[(size_t)Mrows*Dc];     // [B,L,H*DV]
__device__ __align__(16) float  g_OPRE[(size_t)Mrows*Dc];   // pre-LayerNorm
__device__ __align__(16) __half g_WTQ[(size_t)Dc*Dc];       // [N,K] fp16
__device__ __align__(16) __half g_WTK[(size_t)Dc*Dc];
__device__ __align__(16) __half g_WTV[(size_t)Dc*Dc];
__device__ __align__(16) __half g_WTO[(size_t)Dc*Dc];
__device__ __align__(16) uint32_t g_BM[(size_t)Mrows*64];   // mask bits [B*L][64]
__device__ __align__(16) float  g_L[(size_t)BHc*Lc];        // 1/rowsum
__device__ __align__(16) __half g_PU[(size_t)BHc*Lc*Lc];    // unnormalized P fp16

// ---------------------------------------------------------------------------
// helpers
// ---------------------------------------------------------------------------
__device__ __forceinline__ uint32_t h2(float a, float b) {
    __half2 h = __floats2half2_rn(a, b);
    return *(uint32_t*)&h;
}
__device__ __forceinline__ uint32_t ex2h2(uint32_t s) {
    uint32_t r;
    asm("ex2.approx.f16x2 %0, %1;" : "=r"(r) : "r"(s));
    return r;
}
__device__ __forceinline__ void mma16(float* c, const uint32_t* a, const uint32_t* b) {
    asm volatile(
        "mma.sync.aligned.m16n8k16.row.col.f32.f16.f16.f32 "
        "{%0,%1,%2,%3}, {%4,%5,%6,%7}, {%8,%9}, {%0,%1,%2,%3};"
        : "+f"(c[0]), "+f"(c[1]), "+f"(c[2]), "+f"(c[3])
        : "r"(a[0]), "r"(a[1]), "r"(a[2]), "r"(a[3]), "r"(b[0]), "r"(b[1]));
}

// ---------------------------------------------------------------------------
// fp16 warp-MMA GEMM for projections (round-7 engine, unchanged).
// ---------------------------------------------------------------------------
#define SPAD2 20

template<int EPI, int KTOT>
__global__ void __launch_bounds__(256, 2)
gemm_h(const float* __restrict__ A, const __half* __restrict__ Bh,
       void* __restrict__ Cv, const float* __restrict__ resid, float scale)
{
    constexpr int NC = KTOT / 32;
    __shared__ uint32_t As[128 * SPAD2];
    __shared__ uint32_t Bs[64 * SPAD2];

    const int tid = threadIdx.x;
    const int wid = tid >> 5, lane = tid & 31;
    const int wm  = wid >> 1, wn = wid & 1;
    const int g   = lane >> 2, tq = lane & 3;
    const int m0  = blockIdx.y * 128;
    const int n0  = blockIdx.x * 64;

    const int arow = tid >> 3, ac4 = (tid & 7) * 4;
    const int brow = tid >> 2, bc4 = (tid & 3) * 4;
    const uint32_t* Bg = (const uint32_t*)Bh;

    float4 pa[4];
    uint4  pb;
    float acc[2][4][4] = {};

    auto g2r = [&](int c) {
        const int kc = c * 32;
#pragma unroll
        for (int j = 0; j < 4; j++)
            pa[j] = *(const float4*)(A + (size_t)(m0 + arow + j * 32) * KTOT + kc + ac4);
        pb = *(const uint4*)(Bg + (size_t)(n0 + brow) * (KTOT / 2) + c * 16 + bc4);
    };
    auto r2s = [&]() {
#pragma unroll
        for (int j = 0; j < 4; j++) {
            uint2 t = { h2(pa[j].x, pa[j].y), h2(pa[j].z, pa[j].w) };
            *(uint2*)&As[(arow + j * 32) * SPAD2 + ac4 / 2] = t;
        }
        *(uint4*)&Bs[brow * SPAD2 + bc4] = pb;
    };

    g2r(0);
    for (int c = 0; c < NC; c++) {
        r2s();
        __syncthreads();
        if (c + 1 < NC) g2r(c + 1);

#pragma unroll
        for (int ks = 0; ks < 2; ks++) {
            uint32_t af[2][4], bf[4][2];
#pragma unroll
            for (int mi = 0; mi < 2; mi++) {
                int rb = (wm * 32 + mi * 16 + g) * SPAD2 + ks * 8 + tq;
                af[mi][0] = As[rb];
                af[mi][1] = As[rb + 8 * SPAD2];
                af[mi][2] = As[rb + 4];
                af[mi][3] = As[rb + 8 * SPAD2 + 4];
            }
#pragma unroll
            for (int ni = 0; ni < 4; ni++) {
                int rb = (wn * 32 + ni * 8 + g) * SPAD2 + ks * 8 + tq;
                bf[ni][0] = Bs[rb];
                bf[ni][1] = Bs[rb + 4];
            }
#pragma unroll
            for (int mi = 0; mi < 2; mi++)
#pragma unroll
                for (int ni = 0; ni < 4; ni++)
                    mma16(acc[mi][ni], af[mi], bf[ni]);
        }
        __syncthreads();
    }

#pragma unroll
    for (int mi = 0; mi < 2; mi++) {
#pragma unroll
        for (int ni = 0; ni < 4; ni++) {
            const float* a = acc[mi][ni];
            int r0  = m0 + wm * 32 + mi * 16 + g;
            int col = n0 + wn * 32 + ni * 8 + 2 * tq;

            if (EPI == 0) {
                uint32_t* C = (uint32_t*)Cv;
                int h = col >> 6, dk = col & 63;
#pragma unroll
                for (int p = 0; p < 2; p++) {
                    int m = r0 + p * 8;
                    int b_ = m >> 11, l = m & (Lc - 1);
                    C[((((size_t)b_ * Hc + h) * Lc + l) * 64 + dk) >> 1] =
                        h2(a[2*p] * scale, a[2*p+1] * scale);
                }
            } else if (EPI == 1) {
                __half* C = (__half*)Cv;
                int h = col >> 6, dv = col & 63;
#pragma unroll
                for (int p = 0; p < 2; p++) {
                    int m = r0 + p * 8;
                    int b_ = m >> 11, l = m & (Lc - 1);
                    size_t base = ((size_t)b_ * Hc + h) * 64;
                    C[(base + dv)     * Lc + l] = __float2half(a[2*p]);
                    C[(base + dv + 1) * Lc + l] = __float2half(a[2*p+1]);
                }
            } else {
                float* C = (float*)Cv;
#pragma unroll
                for (int p = 0; p < 2; p++) {
                    int m = r0 + p * 8;
                    size_t off = (size_t)m * Dc + col;
                    float2 r4 = *(const float2*)&resid[off];
                    float2 o = { a[2*p] + r4.x, a[2*p+1] + r4.y };
                    *(float2*)&C[off] = o;
                }
            }
        }
    }
}

// ---------------------------------------------------------------------------
// Mask compress: int32 [B*L][2048] -> bits [B*L][64]
// ---------------------------------------------------------------------------
__global__ void __launch_bounds__(256)
maskbits_k(const int* __restrict__ mask, uint32_t* __restrict__ bm)
{
    const int w = threadIdx.x >> 5, lane = threadIdx.x & 31;
    const int row = blockIdx.x * 8 + w;
    const int* mr = mask + (size_t)row * Lc;
    uint32_t* br = bm + (size_t)row * 64;
#pragma unroll 8
    for (int it = 0; it < 64; it++) {
        int v = mr[it * 32 + lane];
        uint32_t bits = __ballot_sync(0xffffffffu, v != 0);
        if (lane == 0) br[it] = bits;
    }
}

// ---------------------------------------------------------------------------
// Flash v5 (R7 structure): 128 queries/block, 8 warps 4x2, single pass,
// exp via ex2.approx.f16x2 (one MUFU op per probability PAIR), unnormalized
// P written fp16 to g_PU, O scaled by 1/l in registers.
// ---------------------------------------------------------------------------
#define QS2 36   /* sQ/sK u32 row stride (32 data + 4) */
#define PS2 68   /* sP/sV u32 row stride (64 data + 4) */
#define FSMEM ((4608 + 9216 + 4352 + 8704 + 1024 + 256 + 128) * 4)

__global__ void __launch_bounds__(256, 1)
flash_k(const __half* __restrict__ QH, const __half* __restrict__ KH,
        const __half* __restrict__ VT, const uint32_t* __restrict__ BM,
        float* __restrict__ OH, __half* __restrict__ PU,
        float* __restrict__ Linv, int write_attn)
{
    extern __shared__ uint32_t fs[];
    uint32_t* sQ  = fs;                     // [128][QS2]
    uint32_t* sK  = sQ + 128 * QS2;         // [2][128][QS2]
    uint32_t* sV  = sK + 2 * 128 * QS2;     // [64][PS2]
    uint32_t* sP  = sV + 64 * PS2;          // [128][PS2]
    uint32_t* sB  = sP + 128 * PS2;         // [2][512]
    float*  sSum  = (float*)(sB + 1024);    // [128][2]
    float*  sInv  = sSum + 256;             // [128]

    const int tid = threadIdx.x, wid = tid >> 5, lane = tid & 31;
    const int g = lane >> 2, tq = lane & 3;
    const int wr = wid >> 1, wc = wid & 1;
    const int z = blockIdx.y, m0 = blockIdx.x * 128;
    const int b_ = z >> 4, h = z & 15;

    // ---- Q tile ----
    {
        const uint4* Qz = (const uint4*)(QH + ((size_t)z * Lc + m0) * 64);
#pragma unroll
        for (int i = 0; i < 4; i++) {
            int slot = tid + i * 256, row = slot >> 3, q4 = slot & 7;
            uint4 v = Qz[row * 8 + q4];
            *(uint4*)&sQ[row * QS2 + q4 * 4] = v;
        }
    }

    const uint4* Kz0 = (const uint4*)(KH + (size_t)z * Lc * 64);
    const uint4* Vz0 = (const uint4*)(VT + (size_t)z * 64 * Lc);
    const uint32_t* BMbase = BM + ((size_t)b_ * Lc + m0) * 64;

    uint4 pk[4], pv[4];
    uint32_t pb0, pb1;

    auto ldgK = [&](int kt) {
        const uint4* Kz = Kz0 + (size_t)kt * 128 * 8;
#pragma unroll
        for (int i = 0; i < 4; i++) {
            int slot = tid + i * 256, row = slot >> 3, q4 = slot & 7;
            pk[i] = Kz[row * 8 + q4];
        }
    };
    auto stsK = [&](int buf) {
        uint32_t* d = sK + buf * 128 * QS2;
#pragma unroll
        for (int i = 0; i < 4; i++) {
            int slot = tid + i * 256, row = slot >> 3, q4 = slot & 7;
            *(uint4*)&d[row * QS2 + q4 * 4] = pk[i];
        }
    };
    auto ldgV = [&](int kt) {
#pragma unroll
        for (int i = 0; i < 4; i++) {
            int slot = tid + i * 256, dv = slot >> 4, q4 = slot & 15;
            pv[i] = Vz0[(size_t)dv * (Lc / 8) + kt * 16 + q4];
        }
    };
    auto stsV = [&]() {
#pragma unroll
        for (int i = 0; i < 4; i++) {
            int slot = tid + i * 256, dv = slot >> 4, q4 = slot & 15;
            *(uint4*)&sV[dv * PS2 + q4 * 4] = pv[i];
        }
    };
    auto ldgB = [&](int kt) {
        int idx = tid * 2;
        uint2 t = *(const uint2*)&BMbase[(size_t)(idx >> 2) * 64 + kt * 4 + (idx & 3)];
        pb0 = t.x; pb1 = t.y;
    };
    auto stsB = [&](int buf) {
        uint2 t = { pb0, pb1 };
        *(uint2*)&sB[buf * 512 + tid * 2] = t;
    };

    float acc[2][8][4];
    auto computeS = [&](int buf) {
        const uint32_t* Kb = sK + buf * 128 * QS2;
#pragma unroll
        for (int mi = 0; mi < 2; mi++)
#pragma unroll
            for (int ni = 0; ni < 8; ni++)
#pragma unroll
                for (int q = 0; q < 4; q++) acc[mi][ni][q] = 0.f;
#pragma unroll
        for (int ks = 0; ks < 4; ks++) {
            uint32_t af[2][4];
#pragma unroll
            for (int mi = 0; mi < 2; mi++) {
                int r = wr * 32 + mi * 16 + g;
                af[mi][0] = sQ[r * QS2 + ks * 8 + tq];
                af[mi][1] = sQ[(r + 8) * QS2 + ks * 8 + tq];
                af[mi][2] = sQ[r * QS2 + ks * 8 + tq + 4];
                af[mi][3] = sQ[(r + 8) * QS2 + ks * 8 + tq + 4];
            }
#pragma unroll
            for (int ni = 0; ni < 8; ni++) {
                int n = wc * 64 + ni * 8 + g;
                uint32_t bf[2] = { Kb[n * QS2 + ks * 8 + tq], Kb[n * QS2 + ks * 8 + tq + 4] };
                mma16(acc[0][ni], af[0], bf);
                mma16(acc[1][ni], af[1], bf);
            }
        }
    };

    float rs[4] = { 0.f, 0.f, 0.f, 0.f };
    float oacc[2][4][4] = {};

    ldgK(0); ldgV(0); ldgB(0); stsK(0);
    for (int kt = 0; kt < 16; kt++) {
        stsB(kt & 1);
        __syncthreads();                          // K/B ready; prev PV done
        if (kt + 1 < 16) { ldgK(kt + 1); ldgB(kt + 1); }
        computeS(kt & 1);
        stsV();                                   // V[kt]
        if (kt + 1 < 16) { ldgV(kt + 1); stsK((kt + 1) & 1); }

        // ---- p-pair = ex2h2(pack(s0,s1)) & maskbits ; rowsum ; stage ----
        const uint32_t* Bb = sB + (kt & 1) * 512;
#pragma unroll
        for (int mi = 0; mi < 2; mi++) {
            int r = wr * 32 + mi * 16 + g;
            uint32_t w0a = Bb[r * 4 + wc * 2],       w0b = Bb[r * 4 + wc * 2 + 1];
            uint32_t w1a = Bb[(r + 8) * 4 + wc * 2], w1b = Bb[(r + 8) * 4 + wc * 2 + 1];
            uint32_t* pu0 = (uint32_t*)(PU + ((size_t)z * Lc + m0 + r) * Lc)
                          + kt * 64 + wc * 32;
            uint32_t* pu1 = (uint32_t*)(PU + ((size_t)z * Lc + m0 + r + 8) * Lc)
                          + kt * 64 + wc * 32;
#pragma unroll
            for (int ni = 0; ni < 8; ni++) {
                int sh = (ni & 3) * 8 + 2 * tq;
                uint32_t ba = ((ni >> 2) ? w0b : w0a) >> sh;
                uint32_t bb = ((ni >> 2) ? w1b : w1a) >> sh;
                uint32_t e01 = ex2h2(h2(acc[mi][ni][0], acc[mi][ni][1]));
                uint32_t e23 = ex2h2(h2(acc[mi][ni][2], acc[mi][ni][3]));
                e01 &= ((ba & 1) ? 0x0000FFFFu : 0u) | ((ba & 2) ? 0xFFFF0000u : 0u);
                e23 &= ((bb & 1) ? 0x0000FFFFu : 0u) | ((bb & 2) ? 0xFFFF0000u : 0u);
                float2 f01 = __half22float2(*(__half2*)&e01);
                float2 f23 = __half22float2(*(__half2*)&e23);
                rs[mi * 2]     += f01.x + f01.y;
                rs[mi * 2 + 1] += f23.x + f23.y;
                if (write_attn) {
                    pu0[ni * 4 + tq] = e01;
                    pu1[ni * 4 + tq] = e23;
                }
                sP[r * PS2 + wc * 32 + ni * 4 + tq]       = e01;
                sP[(r + 8) * PS2 + wc * 32 + ni * 4 + tq] = e23;
            }
        }
        __syncthreads();                          // sP, sV ready

        // ---- PV: O += P @ V^T ----
#pragma unroll
        for (int ks = 0; ks < 8; ks++) {
            uint32_t ap[2][4];
#pragma unroll
            for (int mi = 0; mi < 2; mi++) {
                int r = wr * 32 + mi * 16 + g;
                ap[mi][0] = sP[r * PS2 + ks * 8 + tq];
                ap[mi][1] = sP[(r + 8) * PS2 + ks * 8 + tq];
                ap[mi][2] = sP[r * PS2 + ks * 8 + tq + 4];
                ap[mi][3] = sP[(r + 8) * PS2 + ks * 8 + tq + 4];
            }
#pragma unroll
            for (int ni = 0; ni < 4; ni++) {
                int dv = wc * 32 + ni * 8 + g;
                uint32_t bv[2] = { sV[dv * PS2 + ks * 8 + tq], sV[dv * PS2 + ks * 8 + tq + 4] };
                mma16(oacc[0][ni], ap[0], bv);
                mma16(oacc[1][ni], ap[1], bv);
            }
        }
    }

    // ---- row sums -> 1/l ----
#pragma unroll
    for (int s = 0; s < 4; s++) {
        rs[s] += __shfl_xor_sync(0xffffffffu, rs[s], 1);
        rs[s] += __shfl_xor_sync(0xffffffffu, rs[s], 2);
    }
    if (tq == 0) {
#pragma unroll
        for (int s = 0; s < 4; s++) {
            int r = wr * 32 + (s >> 1) * 16 + g + (s & 1) * 8;
            sSum[r * 2 + wc] = rs[s];
        }
    }
    __syncthreads();
    if (tid < 128) {
        float inv = 1.f / (sSum[tid * 2] + sSum[tid * 2 + 1]);
        sInv[tid] = inv;
        Linv[(size_t)z * Lc + m0 + tid] = inv;
    }
    __syncthreads();

    // ---- O scaled by 1/l -> OH ----
#pragma unroll
    for (int mi = 0; mi < 2; mi++) {
        int r = wr * 32 + mi * 16 + g;
        float iv0 = sInv[r], iv1 = sInv[r + 8];
        float* O0 = OH + ((size_t)b_ * Lc + m0 + r) * Dc + h * 64 + wc * 32;
        float* O1 = O0 + (size_t)8 * Dc;
#pragma unroll
        for (int ni = 0; ni < 4; ni++) {
            float2 t0 = { oacc[mi][ni][0] * iv0, oacc[mi][ni][1] * iv0 };
            float2 t1 = { oacc[mi][ni][2] * iv1, oacc[mi][ni][3] * iv1 };
            *(float2*)(O0 + ni * 8 + 2 * tq) = t0;
            *(float2*)(O1 + ni * 8 + 2 * tq) = t1;
        }
    }
}

// ---------------------------------------------------------------------------
// rescale+expand: attn[row,:] = (float)PU[row,:] * Linv[row]
// ---------------------------------------------------------------------------
__global__ void __launch_bounds__(256)
rescale_k(const __half* __restrict__ pu, float* __restrict__ attn,
          const float* __restrict__ Linv)
{
    const float inv = Linv[blockIdx.x];
    const uint2* src = (const uint2*)(pu + (size_t)blockIdx.x * Lc);  // 512 uint2
    float4* dst = (float4*)(attn + (size_t)blockIdx.x * Lc);          // 512 float4
#pragma unroll
    for (int i = 0; i < 2; i++) {
        int idx = threadIdx.x + i * 256;
        uint2 v = src[idx];
        float2 f0 = __half22float2(*(__half2*)&v.x);
        float2 f1 = __half22float2(*(__half2*)&v.y);
        float4 o = { f0.x * inv, f0.y * inv, f1.x * inv, f1.y * inv };
        dst[idx] = o;
    }
}

// ---------------------------------------------------------------------------
// 1024x1024 transpose + fp16 convert
// ---------------------------------------------------------------------------
__global__ void __launch_bounds__(256)
transpose_k(const float* __restrict__ in, __half* __restrict__ out)
{
    __shared__ float t[32][33];
    int x = blockIdx.x * 32 + threadIdx.x;
    int y0 = blockIdx.y * 32;
#pragma unroll
    for (int j = 0; j < 4; j++)
        t[threadIdx.y + j * 8][threadIdx.x] = in[(size_t)(y0 + threadIdx.y + j * 8) * 1024 + x];
    __syncthreads();
    int x2 = blockIdx.y * 32 + threadIdx.x;
    int y2 = blockIdx.x * 32;
#pragma unroll
    for (int j = 0; j < 4; j++)
        out[(size_t)(y2 + threadIdx.y + j * 8) * 1024 + x2] =
            __float2half(t[threadIdx.x][threadIdx.y + j * 8]);
}

// ---------------------------------------------------------------------------
// LayerNorm over rows of D=1024
// ---------------------------------------------------------------------------
__global__ void __launch_bounds__(256)
ln_k(const float* __restrict__ X, const float* __restrict__ g,
     const float* __restrict__ bta, float* __restrict__ O)
{
    const int t = threadIdx.x;
    const float* x = X + (size_t)blockIdx.x * Dc;
    float4 v = *(const float4*)&x[t * 4];
    float s  = v.x + v.y + v.z + v.w;
    float s2 = v.x * v.x + v.y * v.y + v.z * v.z + v.w * v.w;
#pragma unroll
    for (int o = 16; o; o >>= 1) {
        s  += __shfl_xor_sync(0xffffffffu, s, o);
        s2 += __shfl_xor_sync(0xffffffffu, s2, o);
    }
    __shared__ float rs[8], rs2[8];
    if ((t & 31) == 0) { rs[t >> 5] = s; rs2[t >> 5] = s2; }
    __syncthreads();
    float S = 0.f, S2 = 0.f;
#pragma unroll
    for (int i = 0; i < 8; i++) { S += rs[i]; S2 += rs2[i]; }
    float mean = S * (1.0f / Dc);
    float var  = S2 * (1.0f / Dc) - mean * mean;
    float inv  = rsqrtf(var + 1e-6f);

    float4 gg = *(const float4*)&g[t * 4];
    float4 bb = *(const float4*)&bta[t * 4];
    float4 r;
    r.x = (v.x - mean) * inv * gg.x + bb.x;
    r.y = (v.y - mean) * inv * gg.y + bb.y;
    r.z = (v.z - mean) * inv * gg.z + bb.z;
    r.w = (v.w - mean) * inv * gg.w + bb.w;
    *(float4*)&O[(size_t)blockIdx.x * Dc + t * 4] = r;
}

// ---------------------------------------------------------------------------
// Launch
// ---------------------------------------------------------------------------
extern "C" void kernel_launch(void* const* d_in, const int* in_sizes, int n_in,
                              void* d_out, int out_size)
{
    const float* q    = (const float*)d_in[0];
    const float* k    = (const float*)d_in[1];
    const float* v    = (const float*)d_in[2];
    const int*   mask = (const int*)d_in[3];
    const float* w_q  = (const float*)d_in[4];
    const float* w_k  = (const float*)d_in[5];
    const float* w_v  = (const float*)d_in[6];
    const float* w_o  = (const float*)d_in[7];
    const float* ln_g = (const float*)d_in[8];
    const float* ln_b = (const float*)d_in[9];
    float* out = (float*)d_out;

    __half *pQH, *pKH, *pVT, *pWTQ, *pWTK, *pWTV, *pWTO, *pPU;
    float *pOH, *pOPRE, *pL;
    uint32_t* pBM;
    cudaGetSymbolAddress((void**)&pQH,   g_QH);
    cudaGetSymbolAddress((void**)&pKH,   g_KH);
    cudaGetSymbolAddress((void**)&pVT,   g_VT);
    cudaGetSymbolAddress((void**)&pOH,   g_OH);
    cudaGetSymbolAddress((void**)&pOPRE, g_OPRE);
    cudaGetSymbolAddress((void**)&pWTQ,  g_WTQ);
    cudaGetSymbolAddress((void**)&pWTK,  g_WTK);
    cudaGetSymbolAddress((void**)&pWTV,  g_WTV);
    cudaGetSymbolAddress((void**)&pWTO,  g_WTO);
    cudaGetSymbolAddress((void**)&pBM,   g_BM);
    cudaGetSymbolAddress((void**)&pL,    g_L);
    cudaGetSymbolAddress((void**)&pPU,   g_PU);

    const long long bld  = (long long)Bc * Lc * Dc;
    const long long bhll = (long long)BHc * Lc * Lc;
    int write_attn = ((long long)out_size >= bld + bhll) ? 1 : 0;
    float* attn_out = out + bld;

    // 1) weight transposes -> fp16 [N,K]; mask bit-compress
    dim3 tb(32, 8), tg(32, 32);
    transpose_k<<<tg, tb>>>(w_q, pWTQ);
    transpose_k<<<tg, tb>>>(w_k, pWTK);
    transpose_k<<<tg, tb>>>(w_v, pWTV);
    transpose_k<<<tg, tb>>>(w_o, pWTO);
    maskbits_k<<<Mrows / 8, 256>>>(mask, pBM);

    // 2) projections (q pre-scaled by log2(e)/8 for exp2-domain softmax)
    dim3 gp(16, 32);
    gemm_h<0,1024><<<gp, 256>>>(q, pWTQ, pQH, nullptr, 0.125f * 1.44269504088896f);
    gemm_h<0,1024><<<gp, 256>>>(k, pWTK, pKH, nullptr, 1.0f);
    gemm_h<1,1024><<<gp, 256>>>(v, pWTV, pVT, nullptr, 1.0f);

    // 3) single-pass flash (f16x2 exp; unnormalized fp16 P -> g_PU)
    cudaFuncSetAttribute(flash_k, cudaFuncAttributeMaxDynamicSharedMemorySize, FSMEM);
    dim3 gf(Lc / 128, BHc);
    flash_k<<<gf, 256, FSMEM>>>(pQH, pKH, pVT, pBM, pOH, pPU, pL, write_attn);

    // 4) normalize + expand attn (fp16 read, f32 write)
    if (write_attn)
        rescale_k<<<BHc * Lc, 256>>>(pPU, attn_out, pL);

    // 5) output projection + residual, then layernorm
    gemm_h<4,1024><<<gp, 256>>>(pOH, pWTO, pOPRE, q, 1.0f);
    ln_k<<<Mrows, 256>>>(pOPRE, ln_g, ln_b, out);
}

// round 11
// speedup vs baseline: 1.1399x; 1.0548x over previous
#include <cuda_runtime.h>
#include <cuda_fp16.h>
#include <math.h>
#include <stddef.h>
#include <stdint.h>

// Problem constants
#define Bc 2
#define Lc 2048
#define Dc 1024
#define Hc 16
#define Mrows (Bc*Lc)            /* 4096 */
#define BHc (Bc*Hc)              /* 32 */

// ---------------------------------------------------------------------------
// Scratch (device globals -- no allocation allowed)
// ---------------------------------------------------------------------------
__device__ __align__(16) __half g_QH[(size_t)BHc*Lc*64];    // [B,H,L,64] fp16
__device__ __align__(16) __half g_KH[(size_t)BHc*Lc*64];    // [B,H,L,64] fp16
__device__ __align__(16) __half g_VT[(size_t)BHc*64*Lc];    // [B,H,64,L] fp16
__device__ __align__(16) float  g_OH[(size_t)Mrows*Dc];     // [B,L,H*DV]
__device__ __align__(16) float  g_OPRE[(size_t)Mrows*Dc];   // pre-LayerNorm
__device__ __align__(16) __half g_WTQ[(size_t)Dc*Dc];       // [N,K] fp16
__device__ __align__(16) __half g_WTK[(size_t)Dc*Dc];
__device__ __align__(16) __half g_WTV[(size_t)Dc*Dc];
__device__ __align__(16) __half g_WTO[(size_t)Dc*Dc];
__device__ __align__(16) uint32_t g_BM[(size_t)Mrows*64];   // mask bits [B*L][64]
__device__ __align__(16) float  g_L[(size_t)BHc*Lc];        // 1/rowsum
__device__ __align__(16) __half g_PU[(size_t)BHc*Lc*Lc];    // unnormalized P fp16

// ---------------------------------------------------------------------------
// helpers
// ---------------------------------------------------------------------------
__device__ __forceinline__ uint32_t h2(float a, float b) {
    __half2 h = __floats2half2_rn(a, b);
    return *(uint32_t*)&h;
}
__device__ __forceinline__ uint32_t ex2h2(uint32_t s) {
    uint32_t r;
    asm("ex2.approx.f16x2 %0, %1;" : "=r"(r) : "r"(s));
    return r;
}
__device__ __forceinline__ void mma16(float* c, const uint32_t* a, const uint32_t* b) {
    asm volatile(
        "mma.sync.aligned.m16n8k16.row.col.f32.f16.f16.f32 "
        "{%0,%1,%2,%3}, {%4,%5,%6,%7}, {%8,%9}, {%0,%1,%2,%3};"
        : "+f"(c[0]), "+f"(c[1]), "+f"(c[2]), "+f"(c[3])
        : "r"(a[0]), "r"(a[1]), "r"(a[2]), "r"(a[3]), "r"(b[0]), "r"(b[1]));
}
__device__ __forceinline__ uint32_t smem_u32(const void* p) {
    uint32_t a;
    asm("{ .reg .u64 t; cvta.to.shared.u64 t, %1; cvt.u32.u64 %0, t; }"
        : "=r"(a) : "l"(p));
    return a;
}
__device__ __forceinline__ void cpa16(uint32_t d, const void* s) {
    asm volatile("cp.async.cg.shared.global [%0], [%1], 16;" :: "r"(d), "l"(s));
}
__device__ __forceinline__ void cpa8(uint32_t d, const void* s) {
    asm volatile("cp.async.ca.shared.global [%0], [%1], 8;" :: "r"(d), "l"(s));
}
#define CPA_COMMIT() asm volatile("cp.async.commit_group;" ::: "memory")
#define CPA_WAIT0()  asm volatile("cp.async.wait_group 0;" ::: "memory")

// ---------------------------------------------------------------------------
// fp16 warp-MMA GEMM for projections (round-7 engine, unchanged).
// ---------------------------------------------------------------------------
#define SPAD2 20

template<int EPI, int KTOT>
__global__ void __launch_bounds__(256, 2)
gemm_h(const float* __restrict__ A, const __half* __restrict__ Bh,
       void* __restrict__ Cv, const float* __restrict__ resid, float scale)
{
    constexpr int NC = KTOT / 32;
    __shared__ uint32_t As[128 * SPAD2];
    __shared__ uint32_t Bs[64 * SPAD2];

    const int tid = threadIdx.x;
    const int wid = tid >> 5, lane = tid & 31;
    const int wm  = wid >> 1, wn = wid & 1;
    const int g   = lane >> 2, tq = lane & 3;
    const int m0  = blockIdx.y * 128;
    const int n0  = blockIdx.x * 64;

    const int arow = tid >> 3, ac4 = (tid & 7) * 4;
    const int brow = tid >> 2, bc4 = (tid & 3) * 4;
    const uint32_t* Bg = (const uint32_t*)Bh;

    float4 pa[4];
    uint4  pb;
    float acc[2][4][4] = {};

    auto g2r = [&](int c) {
        const int kc = c * 32;
#pragma unroll
        for (int j = 0; j < 4; j++)
            pa[j] = *(const float4*)(A + (size_t)(m0 + arow + j * 32) * KTOT + kc + ac4);
        pb = *(const uint4*)(Bg + (size_t)(n0 + brow) * (KTOT / 2) + c * 16 + bc4);
    };
    auto r2s = [&]() {
#pragma unroll
        for (int j = 0; j < 4; j++) {
            uint2 t = { h2(pa[j].x, pa[j].y), h2(pa[j].z, pa[j].w) };
            *(uint2*)&As[(arow + j * 32) * SPAD2 + ac4 / 2] = t;
        }
        *(uint4*)&Bs[brow * SPAD2 + bc4] = pb;
    };

    g2r(0);
    for (int c = 0; c < NC; c++) {
        r2s();
        __syncthreads();
        if (c + 1 < NC) g2r(c + 1);

#pragma unroll
        for (int ks = 0; ks < 2; ks++) {
            uint32_t af[2][4], bf[4][2];
#pragma unroll
            for (int mi = 0; mi < 2; mi++) {
                int rb = (wm * 32 + mi * 16 + g) * SPAD2 + ks * 8 + tq;
                af[mi][0] = As[rb];
                af[mi][1] = As[rb + 8 * SPAD2];
                af[mi][2] = As[rb + 4];
                af[mi][3] = As[rb + 8 * SPAD2 + 4];
            }
#pragma unroll
            for (int ni = 0; ni < 4; ni++) {
                int rb = (wn * 32 + ni * 8 + g) * SPAD2 + ks * 8 + tq;
                bf[ni][0] = Bs[rb];
                bf[ni][1] = Bs[rb + 4];
            }
#pragma unroll
            for (int mi = 0; mi < 2; mi++)
#pragma unroll
                for (int ni = 0; ni < 4; ni++)
                    mma16(acc[mi][ni], af[mi], bf[ni]);
        }
        __syncthreads();
    }

#pragma unroll
    for (int mi = 0; mi < 2; mi++) {
#pragma unroll
        for (int ni = 0; ni < 4; ni++) {
            const float* a = acc[mi][ni];
            int r0  = m0 + wm * 32 + mi * 16 + g;
            int col = n0 + wn * 32 + ni * 8 + 2 * tq;

            if (EPI == 0) {
                uint32_t* C = (uint32_t*)Cv;
                int h = col >> 6, dk = col & 63;
#pragma unroll
                for (int p = 0; p < 2; p++) {
                    int m = r0 + p * 8;
                    int b_ = m >> 11, l = m & (Lc - 1);
                    C[((((size_t)b_ * Hc + h) * Lc + l) * 64 + dk) >> 1] =
                        h2(a[2*p] * scale, a[2*p+1] * scale);
                }
            } else if (EPI == 1) {
                __half* C = (__half*)Cv;
                int h = col >> 6, dv = col & 63;
#pragma unroll
                for (int p = 0; p < 2; p++) {
                    int m = r0 + p * 8;
                    int b_ = m >> 11, l = m & (Lc - 1);
                    size_t base = ((size_t)b_ * Hc + h) * 64;
                    C[(base + dv)     * Lc + l] = __float2half(a[2*p]);
                    C[(base + dv + 1) * Lc + l] = __float2half(a[2*p+1]);
                }
            } else {
                float* C = (float*)Cv;
#pragma unroll
                for (int p = 0; p < 2; p++) {
                    int m = r0 + p * 8;
                    size_t off = (size_t)m * Dc + col;
                    float2 r4 = *(const float2*)&resid[off];
                    float2 o = { a[2*p] + r4.x, a[2*p+1] + r4.y };
                    *(float2*)&C[off] = o;
                }
            }
        }
    }
}

// ---------------------------------------------------------------------------
// Mask compress: int32 [B*L][2048] -> bits [B*L][64]
// ---------------------------------------------------------------------------
__global__ void __launch_bounds__(256)
maskbits_k(const int* __restrict__ mask, uint32_t* __restrict__ bm)
{
    const int w = threadIdx.x >> 5, lane = threadIdx.x & 31;
    const int row = blockIdx.x * 8 + w;
    const int* mr = mask + (size_t)row * Lc;
    uint32_t* br = bm + (size_t)row * 64;
#pragma unroll 8
    for (int it = 0; it < 64; it++) {
        int v = mr[it * 32 + lane];
        uint32_t bits = __ballot_sync(0xffffffffu, v != 0);
        if (lane == 0) br[it] = bits;
    }
}

// ---------------------------------------------------------------------------
// Flash v6.1 (FA2 register-P, mask-load fix): 128 queries/block, 8 warps,
// warp owns 16 rows x all 128 chunk-cols. Score accumulators -> exp2 -> PV
// A-fragments directly in registers (no P smem). Q in registers. K/V/mask
// double-buffered via cp.async. One __syncthreads per chunk. 2 CTAs/SM.
// ---------------------------------------------------------------------------
#define KS3 36     /* K row stride (u32): 32 data + 4 pad */
#define VS3 68     /* V row stride (u32): 64 data + 4 pad */
#define OFF3_K   0                       /* [2][128][36] = 9216 u32 */
#define OFF3_V   9216                    /* [2][64][68]  = 8704 u32 */
#define OFF3_B   (9216 + 8704)           /* [2][512]     = 1024 u32 */
#define OFF3_SUM (OFF3_B + 1024)         /* [128] floats */
#define OFF3_INV (OFF3_SUM + 128)        /* [128] floats */
#define FSMEM3   ((OFF3_INV + 128) * 4)  /* 76800 bytes  */

__global__ void __launch_bounds__(256, 2)
flash_k(const __half* __restrict__ QH, const __half* __restrict__ KH,
        const __half* __restrict__ VT, const uint32_t* __restrict__ BM,
        float* __restrict__ OH, __half* __restrict__ PU,
        float* __restrict__ Linv, int write_attn)
{
    extern __shared__ uint32_t fs[];
    const uint32_t sb = smem_u32(fs);

    const int tid = threadIdx.x, w = tid >> 5, lane = tid & 31;
    const int g = lane >> 2, tq = lane & 3;
    const int z = blockIdx.y, m0 = blockIdx.x * 128;
    const int b_ = z >> 4, h = z & 15;
    const int r = w * 16 + g;               // local rows r, r+8

    const uint32_t* Ku  = (const uint32_t*)KH + (size_t)z * Lc * 32;
    const uint32_t* Vu  = (const uint32_t*)VT + (size_t)z * 64 * (Lc / 2);
    const uint32_t* BMb = BM + ((size_t)b_ * Lc + m0) * 64;

    auto issue = [&](int kt, int buf) {
#pragma unroll
        for (int i = 0; i < 4; i++) {
            int slot = tid + i * 256, row = slot >> 3, q4 = slot & 7;
            cpa16(sb + (OFF3_K + buf * 4608 + row * KS3 + q4 * 4) * 4,
                  Ku + (size_t)kt * 128 * 32 + row * 32 + q4 * 4);
        }
#pragma unroll
        for (int i = 0; i < 4; i++) {
            int slot = tid + i * 256, dv = slot >> 4, q16 = slot & 15;
            cpa16(sb + (OFF3_V + buf * 4352 + dv * VS3 + q16 * 4) * 4,
                  Vu + (size_t)dv * (Lc / 2) + kt * 64 + q16 * 4);
        }
        {
            // mask bits: 128 rows x 4 words = 512 u32; 256 thr x 1 uint2 each
            int row = tid >> 1, wsel = (tid & 1) * 2;
            cpa8(sb + (OFF3_B + buf * 512 + row * 4 + wsel) * 4,
                 BMb + (size_t)row * 64 + kt * 4 + wsel);
        }
        CPA_COMMIT();
    };

    issue(0, 0);

    // ---- Q fragments (registers, loaded once from gmem) ----
    uint32_t af[4][4];
    {
        const uint32_t* QHu = (const uint32_t*)QH + ((size_t)z * Lc + m0) * 32;
#pragma unroll
        for (int ks = 0; ks < 4; ks++) {
            af[ks][0] = QHu[(size_t)r * 32 + ks * 8 + tq];
            af[ks][1] = QHu[(size_t)(r + 8) * 32 + ks * 8 + tq];
            af[ks][2] = QHu[(size_t)r * 32 + ks * 8 + tq + 4];
            af[ks][3] = QHu[(size_t)(r + 8) * 32 + ks * 8 + tq + 4];
        }
    }

    uint32_t* pu0 = (uint32_t*)PU + ((size_t)z * Lc + m0 + r) * (Lc / 2);
    uint32_t* pu1 = pu0 + (size_t)8 * (Lc / 2);

    CPA_WAIT0();
    __syncthreads();

    float rs0 = 0.f, rs1 = 0.f;
    float oacc[8][4] = {};

    for (int kt = 0; kt < 16; kt++) {
        const int buf = kt & 1;
        if (kt + 1 < 16) issue(kt + 1, buf ^ 1);

        const uint32_t* Kb = fs + OFF3_K + buf * 4608;
        const uint32_t* Vb = fs + OFF3_V + buf * 4352;
        const uint32_t* Bb = fs + OFF3_B + buf * 512;

        uint32_t mw0[4], mw1[4];
#pragma unroll
        for (int i = 0; i < 4; i++) {
            mw0[i] = Bb[r * 4 + i];
            mw1[i] = Bb[(r + 8) * 4 + i];
        }

        uint32_t ap[8][4];
#pragma unroll
        for (int ni = 0; ni < 16; ni++) {
            float a4[4] = { 0.f, 0.f, 0.f, 0.f };
            const int n = ni * 8 + g;
#pragma unroll
            for (int ks = 0; ks < 4; ks++) {
                uint32_t bf[2] = { Kb[n * KS3 + ks * 8 + tq],
                                   Kb[n * KS3 + ks * 8 + tq + 4] };
                mma16(a4, af[ks], bf);
            }
            const int sh = (ni & 3) * 8 + 2 * tq;
            uint32_t ba = mw0[ni >> 2] >> sh;
            uint32_t bb = mw1[ni >> 2] >> sh;
            uint32_t e01 = ex2h2(h2(a4[0], a4[1]));
            uint32_t e23 = ex2h2(h2(a4[2], a4[3]));
            e01 &= ((ba & 1) ? 0x0000FFFFu : 0u) | ((ba & 2) ? 0xFFFF0000u : 0u);
            e23 &= ((bb & 1) ? 0x0000FFFFu : 0u) | ((bb & 2) ? 0xFFFF0000u : 0u);
            float2 f01 = __half22float2(*(__half2*)&e01);
            float2 f23 = __half22float2(*(__half2*)&e23);
            rs0 += f01.x + f01.y;
            rs1 += f23.x + f23.y;
            if (write_attn) {
                pu0[kt * 64 + ni * 4 + tq] = e01;
                pu1[kt * 64 + ni * 4 + tq] = e23;
            }
            // FA2 trick: C-layout pair == A-fragment of the k16 block ni>>1
            ap[ni >> 1][(ni & 1) * 2]     = e01;
            ap[ni >> 1][(ni & 1) * 2 + 1] = e23;
        }

        // ---- PV: O += P @ V^T, A from registers ----
#pragma unroll
        for (int ksb = 0; ksb < 8; ksb++) {
#pragma unroll
            for (int nv = 0; nv < 8; nv++) {
                const int dv = nv * 8 + g;
                uint32_t bv[2] = { Vb[dv * VS3 + ksb * 8 + tq],
                                   Vb[dv * VS3 + ksb * 8 + tq + 4] };
                mma16(oacc[nv], ap[ksb], bv);
            }
        }

        if (kt + 1 < 16) CPA_WAIT0();
        __syncthreads();
    }

    // ---- rowsums -> 1/l (warp-local rows; quad reduce only) ----
    rs0 += __shfl_xor_sync(0xffffffffu, rs0, 1);
    rs0 += __shfl_xor_sync(0xffffffffu, rs0, 2);
    rs1 += __shfl_xor_sync(0xffffffffu, rs1, 1);
    rs1 += __shfl_xor_sync(0xffffffffu, rs1, 2);
    float* sSum = (float*)(fs + OFF3_SUM);
    float* sInv = (float*)(fs + OFF3_INV);
    if (tq == 0) { sSum[r] = rs0; sSum[r + 8] = rs1; }
    __syncthreads();
    if (tid < 128) {
        float inv = 1.f / sSum[tid];
        sInv[tid] = inv;
        Linv[(size_t)z * Lc + m0 + tid] = inv;
    }
    __syncthreads();

    // ---- O scaled by 1/l -> OH ----
    const float iv0 = sInv[r], iv1 = sInv[r + 8];
    float* O0 = OH + ((size_t)b_ * Lc + m0 + r) * Dc + h * 64;
    float* O1 = O0 + (size_t)8 * Dc;
#pragma unroll
    for (int nv = 0; nv < 8; nv++) {
        float2 t0 = { oacc[nv][0] * iv0, oacc[nv][1] * iv0 };
        float2 t1 = { oacc[nv][2] * iv1, oacc[nv][3] * iv1 };
        *(float2*)(O0 + nv * 8 + 2 * tq) = t0;
        *(float2*)(O1 + nv * 8 + 2 * tq) = t1;
    }
}

// ---------------------------------------------------------------------------
// rescale+expand: attn[row,:] = (float)PU[row,:] * Linv[row]
// ---------------------------------------------------------------------------
__global__ void __launch_bounds__(256)
rescale_k(const __half* __restrict__ pu, float* __restrict__ attn,
          const float* __restrict__ Linv)
{
    const float inv = Linv[blockIdx.x];
    const uint2* src = (const uint2*)(pu + (size_t)blockIdx.x * Lc);
    float4* dst = (float4*)(attn + (size_t)blockIdx.x * Lc);
#pragma unroll
    for (int i = 0; i < 2; i++) {
        int idx = threadIdx.x + i * 256;
        uint2 v = src[idx];
        float2 f0 = __half22float2(*(__half2*)&v.x);
        float2 f1 = __half22float2(*(__half2*)&v.y);
        float4 o = { f0.x * inv, f0.y * inv, f1.x * inv, f1.y * inv };
        dst[idx] = o;
    }
}

// ---------------------------------------------------------------------------
// 1024x1024 transpose + fp16 convert
// ---------------------------------------------------------------------------
__global__ void __launch_bounds__(256)
transpose_k(const float* __restrict__ in, __half* __restrict__ out)
{
    __shared__ float t[32][33];
    int x = blockIdx.x * 32 + threadIdx.x;
    int y0 = blockIdx.y * 32;
#pragma unroll
    for (int j = 0; j < 4; j++)
        t[threadIdx.y + j * 8][threadIdx.x] = in[(size_t)(y0 + threadIdx.y + j * 8) * 1024 + x];
    __syncthreads();
    int x2 = blockIdx.y * 32 + threadIdx.x;
    int y2 = blockIdx.x * 32;
#pragma unroll
    for (int j = 0; j < 4; j++)
        out[(size_t)(y2 + threadIdx.y + j * 8) * 1024 + x2] =
            __float2half(t[threadIdx.x][threadIdx.y + j * 8]);
}

// ---------------------------------------------------------------------------
// LayerNorm over rows of D=1024
// ---------------------------------------------------------------------------
__global__ void __launch_bounds__(256)
ln_k(const float* __restrict__ X, const float* __restrict__ g,
     const float* __restrict__ bta, float* __restrict__ O)
{
    const int t = threadIdx.x;
    const float* x = X + (size_t)blockIdx.x * Dc;
    float4 v = *(const float4*)&x[t * 4];
    float s  = v.x + v.y + v.z + v.w;
    float s2 = v.x * v.x + v.y * v.y + v.z * v.z + v.w * v.w;
#pragma unroll
    for (int o = 16; o; o >>= 1) {
        s  += __shfl_xor_sync(0xffffffffu, s, o);
        s2 += __shfl_xor_sync(0xffffffffu, s2, o);
    }
    __shared__ float rs[8], rs2[8];
    if ((t & 31) == 0) { rs[t >> 5] = s; rs2[t >> 5] = s2; }
    __syncthreads();
    float S = 0.f, S2 = 0.f;
#pragma unroll
    for (int i = 0; i < 8; i++) { S += rs[i]; S2 += rs2[i]; }
    float mean = S * (1.0f / Dc);
    float var  = S2 * (1.0f / Dc) - mean * mean;
    float inv  = rsqrtf(var + 1e-6f);

    float4 gg = *(const float4*)&g[t * 4];
    float4 bb = *(const float4*)&bta[t * 4];
    float4 r;
    r.x = (v.x - mean) * inv * gg.x + bb.x;
    r.y = (v.y - mean) * inv * gg.y + bb.y;
    r.z = (v.z - mean) * inv * gg.z + bb.z;
    r.w = (v.w - mean) * inv * gg.w + bb.w;
    *(float4*)&O[(size_t)blockIdx.x * Dc + t * 4] = r;
}

// ---------------------------------------------------------------------------
// Launch
// ---------------------------------------------------------------------------
extern "C" void kernel_launch(void* const* d_in, const int* in_sizes, int n_in,
                              void* d_out, int out_size)
{
    const float* q    = (const float*)d_in[0];
    const float* k    = (const float*)d_in[1];
    const float* v    = (const float*)d_in[2];
    const int*   mask = (const int*)d_in[3];
    const float* w_q  = (const float*)d_in[4];
    const float* w_k  = (const float*)d_in[5];
    const float* w_v  = (const float*)d_in[6];
    const float* w_o  = (const float*)d_in[7];
    const float* ln_g = (const float*)d_in[8];
    const float* ln_b = (const float*)d_in[9];
    float* out = (float*)d_out;

    __half *pQH, *pKH, *pVT, *pWTQ, *pWTK, *pWTV, *pWTO, *pPU;
    float *pOH, *pOPRE, *pL;
    uint32_t* pBM;
    cudaGetSymbolAddress((void**)&pQH,   g_QH);
    cudaGetSymbolAddress((void**)&pKH,   g_KH);
    cudaGetSymbolAddress((void**)&pVT,   g_VT);
    cudaGetSymbolAddress((void**)&pOH,   g_OH);
    cudaGetSymbolAddress((void**)&pOPRE, g_OPRE);
    cudaGetSymbolAddress((void**)&pWTQ,  g_WTQ);
    cudaGetSymbolAddress((void**)&pWTK,  g_WTK);
    cudaGetSymbolAddress((void**)&pWTV,  g_WTV);
    cudaGetSymbolAddress((void**)&pWTO,  g_WTO);
    cudaGetSymbolAddress((void**)&pBM,   g_BM);
    cudaGetSymbolAddress((void**)&pL,    g_L);
    cudaGetSymbolAddress((void**)&pPU,   g_PU);

    const long long bld  = (long long)Bc * Lc * Dc;
    const long long bhll = (long long)BHc * Lc * Lc;
    int write_attn = ((long long)out_size >= bld + bhll) ? 1 : 0;
    float* attn_out = out + bld;

    // 1) weight transposes -> fp16 [N,K]; mask bit-compress
    dim3 tb(32, 8), tg(32, 32);
    transpose_k<<<tg, tb>>>(w_q, pWTQ);
    transpose_k<<<tg, tb>>>(w_k, pWTK);
    transpose_k<<<tg, tb>>>(w_v, pWTV);
    transpose_k<<<tg, tb>>>(w_o, pWTO);
    maskbits_k<<<Mrows / 8, 256>>>(mask, pBM);

    // 2) projections (q pre-scaled by log2(e)/8 for exp2-domain softmax)
    dim3 gp(16, 32);
    gemm_h<0,1024><<<gp, 256>>>(q, pWTQ, pQH, nullptr, 0.125f * 1.44269504088896f);
    gemm_h<0,1024><<<gp, 256>>>(k, pWTK, pKH, nullptr, 1.0f);
    gemm_h<1,1024><<<gp, 256>>>(v, pWTV, pVT, nullptr, 1.0f);

    // 3) single-pass flash v6.1 (register-P, cp.async, 2 CTA/SM)
    cudaFuncSetAttribute(flash_k, cudaFuncAttributeMaxDynamicSharedMemorySize, FSMEM3);
    dim3 gf(Lc / 128, BHc);
    flash_k<<<gf, 256, FSMEM3>>>(pQH, pKH, pVT, pBM, pOH, pPU, pL, write_attn);

    // 4) normalize + expand attn (fp16 read, f32 write)
    if (write_attn)
        rescale_k<<<BHc * Lc, 256>>>(pPU, attn_out, pL);

    // 5) output projection + residual, then layernorm
    gemm_h<4,1024><<<gp, 256>>>(pOH, pWTO, pOPRE, q, 1.0f);
    ln_k<<<Mrows, 256>>>(pOPRE, ln_g, ln_b, out);
}

// round 12
// speedup vs baseline: 1.2414x; 1.0891x over previous
#include <cuda_runtime.h>
#include <cuda_fp16.h>
#include <math.h>
#include <stddef.h>
#include <stdint.h>

// Problem constants
#define Bc 2
#define Lc 2048
#define Dc 1024
#define Hc 16
#define Mrows (Bc*Lc)            /* 4096 */
#define BHc (Bc*Hc)              /* 32 */

// ---------------------------------------------------------------------------
// Scratch (device globals -- no allocation allowed)
// ---------------------------------------------------------------------------
__device__ __align__(16) __half g_QH[(size_t)BHc*Lc*64];    // [B,H,L,64] fp16
__device__ __align__(16) __half g_KH[(size_t)BHc*Lc*64];    // [B,H,L,64] fp16
__device__ __align__(16) __half g_VT[(size_t)BHc*64*Lc];    // [B,H,64,L] fp16
__device__ __align__(16) float  g_OH[(size_t)Mrows*Dc];     // [B,L,H*DV]
__device__ __align__(16) float  g_OPRE[(size_t)Mrows*Dc];   // pre-LayerNorm
__device__ __align__(16) __half g_WTQ[(size_t)Dc*Dc];       // [N,K] fp16
__device__ __align__(16) __half g_WTK[(size_t)Dc*Dc];
__device__ __align__(16) __half g_WTV[(size_t)Dc*Dc];
__device__ __align__(16) __half g_WTO[(size_t)Dc*Dc];
__device__ __align__(16) uint32_t g_BM[(size_t)Mrows*64];   // mask bits [B*L][64]
__device__ __align__(16) float  g_L[(size_t)BHc*Lc];        // 1/rowsum
__device__ __align__(16) __half g_PU[(size_t)BHc*Lc*Lc];    // unnormalized P fp16

// ---------------------------------------------------------------------------
// helpers
// ---------------------------------------------------------------------------
__device__ __forceinline__ uint32_t h2(float a, float b) {
    __half2 h = __floats2half2_rn(a, b);
    return *(uint32_t*)&h;
}
__device__ __forceinline__ uint32_t ex2h2(uint32_t s) {
    uint32_t r;
    asm("ex2.approx.f16x2 %0, %1;" : "=r"(r) : "r"(s));
    return r;
}
__device__ __forceinline__ void mma16(float* c, const uint32_t* a, const uint32_t* b) {
    asm volatile(
        "mma.sync.aligned.m16n8k16.row.col.f32.f16.f16.f32 "
        "{%0,%1,%2,%3}, {%4,%5,%6,%7}, {%8,%9}, {%0,%1,%2,%3};"
        : "+f"(c[0]), "+f"(c[1]), "+f"(c[2]), "+f"(c[3])
        : "r"(a[0]), "r"(a[1]), "r"(a[2]), "r"(a[3]), "r"(b[0]), "r"(b[1]));
}
__device__ __forceinline__ uint32_t smem_u32(const void* p) {
    uint32_t a;
    asm("{ .reg .u64 t; cvta.to.shared.u64 t, %1; cvt.u32.u64 %0, t; }"
        : "=r"(a) : "l"(p));
    return a;
}
__device__ __forceinline__ void cpa16(uint32_t d, const void* s) {
    asm volatile("cp.async.cg.shared.global [%0], [%1], 16;" :: "r"(d), "l"(s));
}
__device__ __forceinline__ void cpa8(uint32_t d, const void* s) {
    asm volatile("cp.async.ca.shared.global [%0], [%1], 8;" :: "r"(d), "l"(s));
}
#define CPA_COMMIT() asm volatile("cp.async.commit_group;" ::: "memory")
#define CPA_WAIT0()  asm volatile("cp.async.wait_group 0;" ::: "memory")

// ---------------------------------------------------------------------------
// fp16 warp-MMA GEMM for projections (round-7 engine, unchanged).
// ---------------------------------------------------------------------------
#define SPAD2 20

template<int EPI, int KTOT>
__global__ void __launch_bounds__(256, 2)
gemm_h(const float* __restrict__ A, const __half* __restrict__ Bh,
       void* __restrict__ Cv, const float* __restrict__ resid, float scale)
{
    constexpr int NC = KTOT / 32;
    __shared__ uint32_t As[128 * SPAD2];
    __shared__ uint32_t Bs[64 * SPAD2];

    const int tid = threadIdx.x;
    const int wid = tid >> 5, lane = tid & 31;
    const int wm  = wid >> 1, wn = wid & 1;
    const int g   = lane >> 2, tq = lane & 3;
    const int m0  = blockIdx.y * 128;
    const int n0  = blockIdx.x * 64;

    const int arow = tid >> 3, ac4 = (tid & 7) * 4;
    const int brow = tid >> 2, bc4 = (tid & 3) * 4;
    const uint32_t* Bg = (const uint32_t*)Bh;

    float4 pa[4];
    uint4  pb;
    float acc[2][4][4] = {};

    auto g2r = [&](int c) {
        const int kc = c * 32;
#pragma unroll
        for (int j = 0; j < 4; j++)
            pa[j] = *(const float4*)(A + (size_t)(m0 + arow + j * 32) * KTOT + kc + ac4);
        pb = *(const uint4*)(Bg + (size_t)(n0 + brow) * (KTOT / 2) + c * 16 + bc4);
    };
    auto r2s = [&]() {
#pragma unroll
        for (int j = 0; j < 4; j++) {
            uint2 t = { h2(pa[j].x, pa[j].y), h2(pa[j].z, pa[j].w) };
            *(uint2*)&As[(arow + j * 32) * SPAD2 + ac4 / 2] = t;
        }
        *(uint4*)&Bs[brow * SPAD2 + bc4] = pb;
    };

    g2r(0);
    for (int c = 0; c < NC; c++) {
        r2s();
        __syncthreads();
        if (c + 1 < NC) g2r(c + 1);

#pragma unroll
        for (int ks = 0; ks < 2; ks++) {
            uint32_t af[2][4], bf[4][2];
#pragma unroll
            for (int mi = 0; mi < 2; mi++) {
                int rb = (wm * 32 + mi * 16 + g) * SPAD2 + ks * 8 + tq;
                af[mi][0] = As[rb];
                af[mi][1] = As[rb + 8 * SPAD2];
                af[mi][2] = As[rb + 4];
                af[mi][3] = As[rb + 8 * SPAD2 + 4];
            }
#pragma unroll
            for (int ni = 0; ni < 4; ni++) {
                int rb = (wn * 32 + ni * 8 + g) * SPAD2 + ks * 8 + tq;
                bf[ni][0] = Bs[rb];
                bf[ni][1] = Bs[rb + 4];
            }
#pragma unroll
            for (int mi = 0; mi < 2; mi++)
#pragma unroll
                for (int ni = 0; ni < 4; ni++)
                    mma16(acc[mi][ni], af[mi], bf[ni]);
        }
        __syncthreads();
    }

#pragma unroll
    for (int mi = 0; mi < 2; mi++) {
#pragma unroll
        for (int ni = 0; ni < 4; ni++) {
            const float* a = acc[mi][ni];
            int r0  = m0 + wm * 32 + mi * 16 + g;
            int col = n0 + wn * 32 + ni * 8 + 2 * tq;

            if (EPI == 0) {
                uint32_t* C = (uint32_t*)Cv;
                int h = col >> 6, dk = col & 63;
#pragma unroll
                for (int p = 0; p < 2; p++) {
                    int m = r0 + p * 8;
                    int b_ = m >> 11, l = m & (Lc - 1);
                    C[((((size_t)b_ * Hc + h) * Lc + l) * 64 + dk) >> 1] =
                        h2(a[2*p] * scale, a[2*p+1] * scale);
                }
            } else if (EPI == 1) {
                __half* C = (__half*)Cv;
                int h = col >> 6, dv = col & 63;
#pragma unroll
                for (int p = 0; p < 2; p++) {
                    int m = r0 + p * 8;
                    int b_ = m >> 11, l = m & (Lc - 1);
                    size_t base = ((size_t)b_ * Hc + h) * 64;
                    C[(base + dv)     * Lc + l] = __float2half(a[2*p]);
                    C[(base + dv + 1) * Lc + l] = __float2half(a[2*p+1]);
                }
            } else {
                float* C = (float*)Cv;
#pragma unroll
                for (int p = 0; p < 2; p++) {
                    int m = r0 + p * 8;
                    size_t off = (size_t)m * Dc + col;
                    float2 r4 = *(const float2*)&resid[off];
                    float2 o = { a[2*p] + r4.x, a[2*p+1] + r4.y };
                    *(float2*)&C[off] = o;
                }
            }
        }
    }
}

// ---------------------------------------------------------------------------
// Mask compress: int32 [B*L][2048] -> bits [B*L][64]
// ---------------------------------------------------------------------------
__global__ void __launch_bounds__(256)
maskbits_k(const int* __restrict__ mask, uint32_t* __restrict__ bm)
{
    const int w = threadIdx.x >> 5, lane = threadIdx.x & 31;
    const int row = blockIdx.x * 8 + w;
    const int* mr = mask + (size_t)row * Lc;
    uint32_t* br = bm + (size_t)row * 64;
#pragma unroll 8
    for (int it = 0; it < 64; it++) {
        int v = mr[it * 32 + lane];
        uint32_t bits = __ballot_sync(0xffffffffu, v != 0);
        if (lane == 0) br[it] = bits;
    }
}

// ---------------------------------------------------------------------------
// Flash v6.1 (FA2 register-P): unchanged from round 11.
// ---------------------------------------------------------------------------
#define KS3 36     /* K row stride (u32): 32 data + 4 pad */
#define VS3 68     /* V row stride (u32): 64 data + 4 pad */
#define OFF3_K   0                       /* [2][128][36] = 9216 u32 */
#define OFF3_V   9216                    /* [2][64][68]  = 8704 u32 */
#define OFF3_B   (9216 + 8704)           /* [2][512]     = 1024 u32 */
#define OFF3_SUM (OFF3_B + 1024)         /* [128] floats */
#define OFF3_INV (OFF3_SUM + 128)        /* [128] floats */
#define FSMEM3   ((OFF3_INV + 128) * 4)  /* 76800 bytes  */

__global__ void __launch_bounds__(256, 2)
flash_k(const __half* __restrict__ QH, const __half* __restrict__ KH,
        const __half* __restrict__ VT, const uint32_t* __restrict__ BM,
        float* __restrict__ OH, __half* __restrict__ PU,
        float* __restrict__ Linv, int write_attn)
{
    extern __shared__ uint32_t fs[];
    const uint32_t sb = smem_u32(fs);

    const int tid = threadIdx.x, w = tid >> 5, lane = tid & 31;
    const int g = lane >> 2, tq = lane & 3;
    const int z = blockIdx.y, m0 = blockIdx.x * 128;
    const int b_ = z >> 4, h = z & 15;
    const int r = w * 16 + g;               // local rows r, r+8

    const uint32_t* Ku  = (const uint32_t*)KH + (size_t)z * Lc * 32;
    const uint32_t* Vu  = (const uint32_t*)VT + (size_t)z * 64 * (Lc / 2);
    const uint32_t* BMb = BM + ((size_t)b_ * Lc + m0) * 64;

    auto issue = [&](int kt, int buf) {
#pragma unroll
        for (int i = 0; i < 4; i++) {
            int slot = tid + i * 256, row = slot >> 3, q4 = slot & 7;
            cpa16(sb + (OFF3_K + buf * 4608 + row * KS3 + q4 * 4) * 4,
                  Ku + (size_t)kt * 128 * 32 + row * 32 + q4 * 4);
        }
#pragma unroll
        for (int i = 0; i < 4; i++) {
            int slot = tid + i * 256, dv = slot >> 4, q16 = slot & 15;
            cpa16(sb + (OFF3_V + buf * 4352 + dv * VS3 + q16 * 4) * 4,
                  Vu + (size_t)dv * (Lc / 2) + kt * 64 + q16 * 4);
        }
        {
            // mask bits: 128 rows x 4 words = 512 u32; 256 thr x 1 uint2 each
            int row = tid >> 1, wsel = (tid & 1) * 2;
            cpa8(sb + (OFF3_B + buf * 512 + row * 4 + wsel) * 4,
                 BMb + (size_t)row * 64 + kt * 4 + wsel);
        }
        CPA_COMMIT();
    };

    issue(0, 0);

    // ---- Q fragments (registers, loaded once from gmem) ----
    uint32_t af[4][4];
    {
        const uint32_t* QHu = (const uint32_t*)QH + ((size_t)z * Lc + m0) * 32;
#pragma unroll
        for (int ks = 0; ks < 4; ks++) {
            af[ks][0] = QHu[(size_t)r * 32 + ks * 8 + tq];
            af[ks][1] = QHu[(size_t)(r + 8) * 32 + ks * 8 + tq];
            af[ks][2] = QHu[(size_t)r * 32 + ks * 8 + tq + 4];
            af[ks][3] = QHu[(size_t)(r + 8) * 32 + ks * 8 + tq + 4];
        }
    }

    uint32_t* pu0 = (uint32_t*)PU + ((size_t)z * Lc + m0 + r) * (Lc / 2);
    uint32_t* pu1 = pu0 + (size_t)8 * (Lc / 2);

    CPA_WAIT0();
    __syncthreads();

    float rs0 = 0.f, rs1 = 0.f;
    float oacc[8][4] = {};

    for (int kt = 0; kt < 16; kt++) {
        const int buf = kt & 1;
        if (kt + 1 < 16) issue(kt + 1, buf ^ 1);

        const uint32_t* Kb = fs + OFF3_K + buf * 4608;
        const uint32_t* Vb = fs + OFF3_V + buf * 4352;
        const uint32_t* Bb = fs + OFF3_B + buf * 512;

        uint32_t mw0[4], mw1[4];
#pragma unroll
        for (int i = 0; i < 4; i++) {
            mw0[i] = Bb[r * 4 + i];
            mw1[i] = Bb[(r + 8) * 4 + i];
        }

        uint32_t ap[8][4];
#pragma unroll
        for (int ni = 0; ni < 16; ni++) {
            float a4[4] = { 0.f, 0.f, 0.f, 0.f };
            const int n = ni * 8 + g;
#pragma unroll
            for (int ks = 0; ks < 4; ks++) {
                uint32_t bf[2] = { Kb[n * KS3 + ks * 8 + tq],
                                   Kb[n * KS3 + ks * 8 + tq + 4] };
                mma16(a4, af[ks], bf);
            }
            const int sh = (ni & 3) * 8 + 2 * tq;
            uint32_t ba = mw0[ni >> 2] >> sh;
            uint32_t bb = mw1[ni >> 2] >> sh;
            uint32_t e01 = ex2h2(h2(a4[0], a4[1]));
            uint32_t e23 = ex2h2(h2(a4[2], a4[3]));
            e01 &= ((ba & 1) ? 0x0000FFFFu : 0u) | ((ba & 2) ? 0xFFFF0000u : 0u);
            e23 &= ((bb & 1) ? 0x0000FFFFu : 0u) | ((bb & 2) ? 0xFFFF0000u : 0u);
            float2 f01 = __half22float2(*(__half2*)&e01);
            float2 f23 = __half22float2(*(__half2*)&e23);
            rs0 += f01.x + f01.y;
            rs1 += f23.x + f23.y;
            if (write_attn) {
                pu0[kt * 64 + ni * 4 + tq] = e01;
                pu1[kt * 64 + ni * 4 + tq] = e23;
            }
            // FA2 trick: C-layout pair == A-fragment of the k16 block ni>>1
            ap[ni >> 1][(ni & 1) * 2]     = e01;
            ap[ni >> 1][(ni & 1) * 2 + 1] = e23;
        }

        // ---- PV: O += P @ V^T, A from registers ----
#pragma unroll
        for (int ksb = 0; ksb < 8; ksb++) {
#pragma unroll
            for (int nv = 0; nv < 8; nv++) {
                const int dv = nv * 8 + g;
                uint32_t bv[2] = { Vb[dv * VS3 + ksb * 8 + tq],
                                   Vb[dv * VS3 + ksb * 8 + tq + 4] };
                mma16(oacc[nv], ap[ksb], bv);
            }
        }

        if (kt + 1 < 16) CPA_WAIT0();
        __syncthreads();
    }

    // ---- rowsums -> 1/l (warp-local rows; quad reduce only) ----
    rs0 += __shfl_xor_sync(0xffffffffu, rs0, 1);
    rs0 += __shfl_xor_sync(0xffffffffu, rs0, 2);
    rs1 += __shfl_xor_sync(0xffffffffu, rs1, 1);
    rs1 += __shfl_xor_sync(0xffffffffu, rs1, 2);
    float* sSum = (float*)(fs + OFF3_SUM);
    float* sInv = (float*)(fs + OFF3_INV);
    if (tq == 0) { sSum[r] = rs0; sSum[r + 8] = rs1; }
    __syncthreads();
    if (tid < 128) {
        float inv = 1.f / sSum[tid];
        sInv[tid] = inv;
        Linv[(size_t)z * Lc + m0 + tid] = inv;
    }
    __syncthreads();

    // ---- O scaled by 1/l -> OH ----
    const float iv0 = sInv[r], iv1 = sInv[r + 8];
    float* O0 = OH + ((size_t)b_ * Lc + m0 + r) * Dc + h * 64;
    float* O1 = O0 + (size_t)8 * Dc;
#pragma unroll
    for (int nv = 0; nv < 8; nv++) {
        float2 t0 = { oacc[nv][0] * iv0, oacc[nv][1] * iv0 };
        float2 t1 = { oacc[nv][2] * iv1, oacc[nv][3] * iv1 };
        *(float2*)(O0 + nv * 8 + 2 * tq) = t0;
        *(float2*)(O1 + nv * 8 + 2 * tq) = t1;
    }
}

// ---------------------------------------------------------------------------
// rescale+expand: attn[row,:] = (float)PU[row,:] * Linv[row]
// ---------------------------------------------------------------------------
__global__ void __launch_bounds__(256)
rescale_k(const __half* __restrict__ pu, float* __restrict__ attn,
          const float* __restrict__ Linv)
{
    const float inv = Linv[blockIdx.x];
    const uint2* src = (const uint2*)(pu + (size_t)blockIdx.x * Lc);
    float4* dst = (float4*)(attn + (size_t)blockIdx.x * Lc);
#pragma unroll
    for (int i = 0; i < 2; i++) {
        int idx = threadIdx.x + i * 256;
        uint2 v = src[idx];
        float2 f0 = __half22float2(*(__half2*)&v.x);
        float2 f1 = __half22float2(*(__half2*)&v.y);
        float4 o = { f0.x * inv, f0.y * inv, f1.x * inv, f1.y * inv };
        dst[idx] = o;
    }
}

// ---------------------------------------------------------------------------
// 1024x1024 transpose + fp16 convert
// ---------------------------------------------------------------------------
__global__ void __launch_bounds__(256)
transpose_k(const float* __restrict__ in, __half* __restrict__ out)
{
    __shared__ float t[32][33];
    int x = blockIdx.x * 32 + threadIdx.x;
    int y0 = blockIdx.y * 32;
#pragma unroll
    for (int j = 0; j < 4; j++)
        t[threadIdx.y + j * 8][threadIdx.x] = in[(size_t)(y0 + threadIdx.y + j * 8) * 1024 + x];
    __syncthreads();
    int x2 = blockIdx.y * 32 + threadIdx.x;
    int y2 = blockIdx.x * 32;
#pragma unroll
    for (int j = 0; j < 4; j++)
        out[(size_t)(y2 + threadIdx.y + j * 8) * 1024 + x2] =
            __float2half(t[threadIdx.x][threadIdx.y + j * 8]);
}

// ---------------------------------------------------------------------------
// LayerNorm over rows of D=1024
// ---------------------------------------------------------------------------
__global__ void __launch_bounds__(256)
ln_k(const float* __restrict__ X, const float* __restrict__ g,
     const float* __restrict__ bta, float* __restrict__ O)
{
    const int t = threadIdx.x;
    const float* x = X + (size_t)blockIdx.x * Dc;
    float4 v = *(const float4*)&x[t * 4];
    float s  = v.x + v.y + v.z + v.w;
    float s2 = v.x * v.x + v.y * v.y + v.z * v.z + v.w * v.w;
#pragma unroll
    for (int o = 16; o; o >>= 1) {
        s  += __shfl_xor_sync(0xffffffffu, s, o);
        s2 += __shfl_xor_sync(0xffffffffu, s2, o);
    }
    __shared__ float rs[8], rs2[8];
    if ((t & 31) == 0) { rs[t >> 5] = s; rs2[t >> 5] = s2; }
    __syncthreads();
    float S = 0.f, S2 = 0.f;
#pragma unroll
    for (int i = 0; i < 8; i++) { S += rs[i]; S2 += rs2[i]; }
    float mean = S * (1.0f / Dc);
    float var  = S2 * (1.0f / Dc) - mean * mean;
    float inv  = rsqrtf(var + 1e-6f);

    float4 gg = *(const float4*)&g[t * 4];
    float4 bb = *(const float4*)&bta[t * 4];
    float4 r;
    r.x = (v.x - mean) * inv * gg.x + bb.x;
    r.y = (v.y - mean) * inv * gg.y + bb.y;
    r.z = (v.z - mean) * inv * gg.z + bb.z;
    r.w = (v.w - mean) * inv * gg.w + bb.w;
    *(float4*)&O[(size_t)blockIdx.x * Dc + t * 4] = r;
}

// ---------------------------------------------------------------------------
// Launch: fork-join DAG via capture-compatible events + side streams.
// Streams/events are created once (non-blocking, timing-disabled; no device
// memory involved) and reused; all work launched is identical on every call.
// ---------------------------------------------------------------------------
extern "C" void kernel_launch(void* const* d_in, const int* in_sizes, int n_in,
                              void* d_out, int out_size)
{
    const float* q    = (const float*)d_in[0];
    const float* k    = (const float*)d_in[1];
    const float* v    = (const float*)d_in[2];
    const int*   mask = (const int*)d_in[3];
    const float* w_q  = (const float*)d_in[4];
    const float* w_k  = (const float*)d_in[5];
    const float* w_v  = (const float*)d_in[6];
    const float* w_o  = (const float*)d_in[7];
    const float* ln_g = (const float*)d_in[8];
    const float* ln_b = (const float*)d_in[9];
    float* out = (float*)d_out;

    static cudaStream_t s1, s2, s3;
    static cudaEvent_t e0, e1, e2, e3, e4, e5;
    static int res_init = 0;
    if (!res_init) {
        cudaStreamCreateWithFlags(&s1, cudaStreamNonBlocking);
        cudaStreamCreateWithFlags(&s2, cudaStreamNonBlocking);
        cudaStreamCreateWithFlags(&s3, cudaStreamNonBlocking);
        cudaEventCreateWithFlags(&e0, cudaEventDisableTiming);
        cudaEventCreateWithFlags(&e1, cudaEventDisableTiming);
        cudaEventCreateWithFlags(&e2, cudaEventDisableTiming);
        cudaEventCreateWithFlags(&e3, cudaEventDisableTiming);
        cudaEventCreateWithFlags(&e4, cudaEventDisableTiming);
        cudaEventCreateWithFlags(&e5, cudaEventDisableTiming);
        res_init = 1;
    }

    __half *pQH, *pKH, *pVT, *pWTQ, *pWTK, *pWTV, *pWTO, *pPU;
    float *pOH, *pOPRE, *pL;
    uint32_t* pBM;
    cudaGetSymbolAddress((void**)&pQH,   g_QH);
    cudaGetSymbolAddress((void**)&pKH,   g_KH);
    cudaGetSymbolAddress((void**)&pVT,   g_VT);
    cudaGetSymbolAddress((void**)&pOH,   g_OH);
    cudaGetSymbolAddress((void**)&pOPRE, g_OPRE);
    cudaGetSymbolAddress((void**)&pWTQ,  g_WTQ);
    cudaGetSymbolAddress((void**)&pWTK,  g_WTK);
    cudaGetSymbolAddress((void**)&pWTV,  g_WTV);
    cudaGetSymbolAddress((void**)&pWTO,  g_WTO);
    cudaGetSymbolAddress((void**)&pBM,   g_BM);
    cudaGetSymbolAddress((void**)&pL,    g_L);
    cudaGetSymbolAddress((void**)&pPU,   g_PU);

    const long long bld  = (long long)Bc * Lc * Dc;
    const long long bhll = (long long)BHc * Lc * Lc;
    int write_attn = ((long long)out_size >= bld + bhll) ? 1 : 0;
    float* attn_out = out + bld;

    cudaFuncSetAttribute(flash_k, cudaFuncAttributeMaxDynamicSharedMemorySize, FSMEM3);

    const float qscale = 0.125f * 1.44269504088896f;
    dim3 tb(32, 8), tg(32, 32), gp(16, 32), gf(Lc / 128, BHc);

    // ---- fork: three projection branches + main (w_o transpose, maskbits) ----
    cudaEventRecord(e0, 0);
    cudaStreamWaitEvent(s1, e0, 0);
    cudaStreamWaitEvent(s2, e0, 0);
    cudaStreamWaitEvent(s3, e0, 0);

    transpose_k<<<tg, tb, 0, s1>>>(w_q, pWTQ);
    gemm_h<0,1024><<<gp, 256, 0, s1>>>(q, pWTQ, pQH, nullptr, qscale);

    transpose_k<<<tg, tb, 0, s2>>>(w_k, pWTK);
    gemm_h<0,1024><<<gp, 256, 0, s2>>>(k, pWTK, pKH, nullptr, 1.0f);

    transpose_k<<<tg, tb, 0, s3>>>(w_v, pWTV);
    gemm_h<1,1024><<<gp, 256, 0, s3>>>(v, pWTV, pVT, nullptr, 1.0f);

    transpose_k<<<tg, tb>>>(w_o, pWTO);
    maskbits_k<<<Mrows / 8, 256>>>(mask, pBM);

    // ---- join before flash ----
    cudaEventRecord(e1, s1); cudaStreamWaitEvent(0, e1, 0);
    cudaEventRecord(e2, s2); cudaStreamWaitEvent(0, e2, 0);
    cudaEventRecord(e3, s3); cudaStreamWaitEvent(0, e3, 0);

    // ---- flash (scores + exp + unnormalized fp16 P + PV) ----
    flash_k<<<gf, 256, FSMEM3>>>(pQH, pKH, pVT, pBM, pOH, pPU, pL, write_attn);

    // ---- fork: rescale (DRAM-bound) || out-proj + LN (tensor-bound) ----
    cudaEventRecord(e4, 0);
    cudaStreamWaitEvent(s1, e4, 0);
    if (write_attn)
        rescale_k<<<BHc * Lc, 256, 0, s1>>>(pPU, attn_out, pL);

    gemm_h<4,1024><<<gp, 256>>>(pOH, pWTO, pOPRE, q, 1.0f);
    ln_k<<<Mrows, 256>>>(pOPRE, ln_g, ln_b, out);

    // ---- final join ----
    cudaEventRecord(e5, s1);
    cudaStreamWaitEvent(0, e5, 0);
}

// round 13
// speedup vs baseline: 1.3072x; 1.0530x over previous
#include <cuda_runtime.h>
#include <cuda_fp16.h>
#include <math.h>
#include <stddef.h>
#include <stdint.h>

// Problem constants
#define Bc 2
#define Lc 2048
#define Dc 1024
#define Hc 16
#define Mrows (Bc*Lc)            /* 4096 */
#define BHc (Bc*Hc)              /* 32 */

// ---------------------------------------------------------------------------
// Scratch (device globals -- no allocation allowed)
// ---------------------------------------------------------------------------
__device__ __align__(16) __half g_QH[(size_t)BHc*Lc*64];    // [B,H,L,64] fp16
__device__ __align__(16) __half g_KH[(size_t)BHc*Lc*64];    // [B,H,L,64] fp16
__device__ __align__(16) __half g_VT[(size_t)BHc*64*Lc];    // [B,H,64,L] fp16
__device__ __align__(16) float  g_OH[(size_t)Mrows*Dc];     // [B,L,H*DV]
__device__ __align__(16) float  g_OPRE[(size_t)Mrows*Dc];   // pre-LayerNorm
__device__ __align__(16) __half g_WTQ[(size_t)Dc*Dc];       // [N,K] fp16
__device__ __align__(16) __half g_WTK[(size_t)Dc*Dc];
__device__ __align__(16) __half g_WTV[(size_t)Dc*Dc];
__device__ __align__(16) __half g_WTO[(size_t)Dc*Dc];
__device__ __align__(16) uint32_t g_BM[(size_t)Mrows*64];   // mask bits [B*L][64]
__device__ __align__(16) float  g_L[(size_t)BHc*Lc];        // 1/rowsum
__device__ __align__(16) __half g_PU[(size_t)BHc*Lc*Lc];    // unnormalized P fp16

// ---------------------------------------------------------------------------
// helpers
// ---------------------------------------------------------------------------
__device__ __forceinline__ uint32_t h2(float a, float b) {
    __half2 h = __floats2half2_rn(a, b);
    return *(uint32_t*)&h;
}
__device__ __forceinline__ uint32_t ex2h2(uint32_t s) {
    uint32_t r;
    asm("ex2.approx.f16x2 %0, %1;" : "=r"(r) : "r"(s));
    return r;
}
__device__ __forceinline__ void mma16(float* c, const uint32_t* a, const uint32_t* b) {
    asm volatile(
        "mma.sync.aligned.m16n8k16.row.col.f32.f16.f16.f32 "
        "{%0,%1,%2,%3}, {%4,%5,%6,%7}, {%8,%9}, {%0,%1,%2,%3};"
        : "+f"(c[0]), "+f"(c[1]), "+f"(c[2]), "+f"(c[3])
        : "r"(a[0]), "r"(a[1]), "r"(a[2]), "r"(a[3]), "r"(b[0]), "r"(b[1]));
}
__device__ __forceinline__ void ldsm4(uint32_t* r, uint32_t addr) {
    asm volatile("ldmatrix.sync.aligned.m8n8.x4.shared.b16 {%0,%1,%2,%3}, [%4];"
        : "=r"(r[0]), "=r"(r[1]), "=r"(r[2]), "=r"(r[3]) : "r"(addr));
}
__device__ __forceinline__ uint32_t smem_u32(const void* p) {
    uint32_t a;
    asm("{ .reg .u64 t; cvta.to.shared.u64 t, %1; cvt.u32.u64 %0, t; }"
        : "=r"(a) : "l"(p));
    return a;
}
__device__ __forceinline__ void cpa16(uint32_t d, const void* s) {
    asm volatile("cp.async.cg.shared.global [%0], [%1], 16;" :: "r"(d), "l"(s));
}
__device__ __forceinline__ void cpa8(uint32_t d, const void* s) {
    asm volatile("cp.async.ca.shared.global [%0], [%1], 8;" :: "r"(d), "l"(s));
}
#define CPA_COMMIT() asm volatile("cp.async.commit_group;" ::: "memory")
#define CPA_WAIT0()  asm volatile("cp.async.wait_group 0;" ::: "memory")

// ---------------------------------------------------------------------------
// fp16 warp-MMA GEMM for projections, fragments via ldmatrix.
// ---------------------------------------------------------------------------
#define SPAD2 20   /* u32 row stride (80B = 5*16, ldmatrix-aligned) */

template<int EPI, int KTOT>
__global__ void __launch_bounds__(256, 2)
gemm_h(const float* __restrict__ A, const __half* __restrict__ Bh,
       void* __restrict__ Cv, const float* __restrict__ resid, float scale)
{
    constexpr int NC = KTOT / 32;
    __shared__ uint32_t As[128 * SPAD2];
    __shared__ uint32_t Bs[64 * SPAD2];

    const int tid = threadIdx.x;
    const int wid = tid >> 5, lane = tid & 31;
    const int wm  = wid >> 1, wn = wid & 1;
    const int g   = lane >> 2, tq = lane & 3;
    const int m0  = blockIdx.y * 128;
    const int n0  = blockIdx.x * 64;

    const uint32_t sbA = smem_u32(As), sbB = smem_u32(Bs);
    const int lm = lane >> 3, lr = lane & 7;
    // A quadrants: M0 rows0-7 k0-7, M1 rows8-15 k0-7, M2 rows0-7 k8-15, M3 rows8-15 k8-15
    const uint32_t aoff = (uint32_t)(((lm & 1) * 8 + lr) * SPAD2 + (lm >> 1) * 4) * 4;
    // B pairs: M0 rows0-7 k0-7, M1 rows0-7 k8-15, M2 rows8-15 k0-7, M3 rows8-15 k8-15
    const uint32_t boff = (uint32_t)(((lm >> 1) * 8 + lr) * SPAD2 + (lm & 1) * 4) * 4;

    const int arow = tid >> 3, ac4 = (tid & 7) * 4;
    const int brow = tid >> 2, bc4 = (tid & 3) * 4;
    const uint32_t* Bg = (const uint32_t*)Bh;

    float4 pa[4];
    uint4  pb;
    float acc[2][4][4] = {};

    auto g2r = [&](int c) {
        const int kc = c * 32;
#pragma unroll
        for (int j = 0; j < 4; j++)
            pa[j] = *(const float4*)(A + (size_t)(m0 + arow + j * 32) * KTOT + kc + ac4);
        pb = *(const uint4*)(Bg + (size_t)(n0 + brow) * (KTOT / 2) + c * 16 + bc4);
    };
    auto r2s = [&]() {
#pragma unroll
        for (int j = 0; j < 4; j++) {
            uint2 t = { h2(pa[j].x, pa[j].y), h2(pa[j].z, pa[j].w) };
            *(uint2*)&As[(arow + j * 32) * SPAD2 + ac4 / 2] = t;
        }
        *(uint4*)&Bs[brow * SPAD2 + bc4] = pb;
    };

    g2r(0);
    for (int c = 0; c < NC; c++) {
        r2s();
        __syncthreads();
        if (c + 1 < NC) g2r(c + 1);

#pragma unroll
        for (int ks = 0; ks < 2; ks++) {
            uint32_t af[2][4], bf[2][4];
#pragma unroll
            for (int mi = 0; mi < 2; mi++)
                ldsm4(af[mi], sbA + (uint32_t)((wm * 32 + mi * 16) * SPAD2 + ks * 8) * 4 + aoff);
#pragma unroll
            for (int nj = 0; nj < 2; nj++)
                ldsm4(bf[nj], sbB + (uint32_t)((wn * 32 + nj * 16) * SPAD2 + ks * 8) * 4 + boff);
#pragma unroll
            for (int mi = 0; mi < 2; mi++)
#pragma unroll
                for (int nj = 0; nj < 2; nj++) {
                    mma16(acc[mi][nj * 2],     af[mi], bf[nj]);
                    mma16(acc[mi][nj * 2 + 1], af[mi], bf[nj] + 2);
                }
        }
        __syncthreads();
    }

#pragma unroll
    for (int mi = 0; mi < 2; mi++) {
#pragma unroll
        for (int ni = 0; ni < 4; ni++) {
            const float* a = acc[mi][ni];
            int r0  = m0 + wm * 32 + mi * 16 + g;
            int col = n0 + wn * 32 + ni * 8 + 2 * tq;

            if (EPI == 0) {
                uint32_t* C = (uint32_t*)Cv;
                int h = col >> 6, dk = col & 63;
#pragma unroll
                for (int p = 0; p < 2; p++) {
                    int m = r0 + p * 8;
                    int b_ = m >> 11, l = m & (Lc - 1);
                    C[((((size_t)b_ * Hc + h) * Lc + l) * 64 + dk) >> 1] =
                        h2(a[2*p] * scale, a[2*p+1] * scale);
                }
            } else if (EPI == 1) {
                __half* C = (__half*)Cv;
                int h = col >> 6, dv = col & 63;
#pragma unroll
                for (int p = 0; p < 2; p++) {
                    int m = r0 + p * 8;
                    int b_ = m >> 11, l = m & (Lc - 1);
                    size_t base = ((size_t)b_ * Hc + h) * 64;
                    C[(base + dv)     * Lc + l] = __float2half(a[2*p]);
                    C[(base + dv + 1) * Lc + l] = __float2half(a[2*p+1]);
                }
            } else {
                float* C = (float*)Cv;
#pragma unroll
                for (int p = 0; p < 2; p++) {
                    int m = r0 + p * 8;
                    size_t off = (size_t)m * Dc + col;
                    float2 r4 = *(const float2*)&resid[off];
                    float2 o = { a[2*p] + r4.x, a[2*p+1] + r4.y };
                    *(float2*)&C[off] = o;
                }
            }
        }
    }
}

// ---------------------------------------------------------------------------
// Mask compress: int32 [B*L][2048] -> bits [B*L][64]
// ---------------------------------------------------------------------------
__global__ void __launch_bounds__(256)
maskbits_k(const int* __restrict__ mask, uint32_t* __restrict__ bm)
{
    const int w = threadIdx.x >> 5, lane = threadIdx.x & 31;
    const int row = blockIdx.x * 8 + w;
    const int* mr = mask + (size_t)row * Lc;
    uint32_t* br = bm + (size_t)row * 64;
#pragma unroll 8
    for (int it = 0; it < 64; it++) {
        int v = mr[it * 32 + lane];
        uint32_t bits = __ballot_sync(0xffffffffu, v != 0);
        if (lane == 0) br[it] = bits;
    }
}

// ---------------------------------------------------------------------------
// Flash v7 (register-P + ldmatrix fragments): unchanged structure from v6.1,
// K/V B-operand fragments now loaded via ldmatrix.x4 (4x fewer smem instrs).
// ---------------------------------------------------------------------------
#define KS3 36     /* K row stride (u32): 144B = 9*16, ldmatrix-aligned */
#define VS3 68     /* V row stride (u32): 272B = 17*16 */
#define OFF3_K   0                       /* [2][128][36] = 9216 u32 */
#define OFF3_V   9216                    /* [2][64][68]  = 8704 u32 */
#define OFF3_B   (9216 + 8704)           /* [2][512]     = 1024 u32 */
#define OFF3_SUM (OFF3_B + 1024)         /* [128] floats */
#define OFF3_INV (OFF3_SUM + 128)        /* [128] floats */
#define FSMEM3   ((OFF3_INV + 128) * 4)  /* 76800 bytes  */

__global__ void __launch_bounds__(256, 2)
flash_k(const __half* __restrict__ QH, const __half* __restrict__ KH,
        const __half* __restrict__ VT, const uint32_t* __restrict__ BM,
        float* __restrict__ OH, __half* __restrict__ PU,
        float* __restrict__ Linv, int write_attn)
{
    extern __shared__ uint32_t fs[];
    const uint32_t sb = smem_u32(fs);

    const int tid = threadIdx.x, w = tid >> 5, lane = tid & 31;
    const int g = lane >> 2, tq = lane & 3;
    const int z = blockIdx.y, m0 = blockIdx.x * 128;
    const int b_ = z >> 4, h = z & 15;
    const int r = w * 16 + g;               // local rows r, r+8

    // ldmatrix lane offsets: M pairs = (even n-block k-halves, odd n-block)
    const int lm = lane >> 3, lr = lane & 7;
    const uint32_t kfrag = (uint32_t)(((lm >> 1) * 8 + lr) * KS3 + (lm & 1) * 4) * 4;
    const uint32_t vfrag = (uint32_t)(((lm >> 1) * 8 + lr) * VS3 + (lm & 1) * 4) * 4;

    const uint32_t* Ku  = (const uint32_t*)KH + (size_t)z * Lc * 32;
    const uint32_t* Vu  = (const uint32_t*)VT + (size_t)z * 64 * (Lc / 2);
    const uint32_t* BMb = BM + ((size_t)b_ * Lc + m0) * 64;

    auto issue = [&](int kt, int buf) {
#pragma unroll
        for (int i = 0; i < 4; i++) {
            int slot = tid + i * 256, row = slot >> 3, q4 = slot & 7;
            cpa16(sb + (OFF3_K + buf * 4608 + row * KS3 + q4 * 4) * 4,
                  Ku + (size_t)kt * 128 * 32 + row * 32 + q4 * 4);
        }
#pragma unroll
        for (int i = 0; i < 4; i++) {
            int slot = tid + i * 256, dv = slot >> 4, q16 = slot & 15;
            cpa16(sb + (OFF3_V + buf * 4352 + dv * VS3 + q16 * 4) * 4,
                  Vu + (size_t)dv * (Lc / 2) + kt * 64 + q16 * 4);
        }
        {
            int row = tid >> 1, wsel = (tid & 1) * 2;
            cpa8(sb + (OFF3_B + buf * 512 + row * 4 + wsel) * 4,
                 BMb + (size_t)row * 64 + kt * 4 + wsel);
        }
        CPA_COMMIT();
    };

    issue(0, 0);

    // ---- Q fragments (registers, loaded once from gmem) ----
    uint32_t af[4][4];
    {
        const uint32_t* QHu = (const uint32_t*)QH + ((size_t)z * Lc + m0) * 32;
#pragma unroll
        for (int ks = 0; ks < 4; ks++) {
            af[ks][0] = QHu[(size_t)r * 32 + ks * 8 + tq];
            af[ks][1] = QHu[(size_t)(r + 8) * 32 + ks * 8 + tq];
            af[ks][2] = QHu[(size_t)r * 32 + ks * 8 + tq + 4];
            af[ks][3] = QHu[(size_t)(r + 8) * 32 + ks * 8 + tq + 4];
        }
    }

    uint32_t* pu0 = (uint32_t*)PU + ((size_t)z * Lc + m0 + r) * (Lc / 2);
    uint32_t* pu1 = pu0 + (size_t)8 * (Lc / 2);

    CPA_WAIT0();
    __syncthreads();

    float rs0 = 0.f, rs1 = 0.f;
    float oacc[8][4] = {};

    for (int kt = 0; kt < 16; kt++) {
        const int buf = kt & 1;
        if (kt + 1 < 16) issue(kt + 1, buf ^ 1);

        const uint32_t sbKc = sb + (OFF3_K + buf * 4608) * 4;
        const uint32_t sbVc = sb + (OFF3_V + buf * 4352) * 4;
        const uint32_t* Bb = fs + OFF3_B + buf * 512;

        uint32_t mw0[4], mw1[4];
#pragma unroll
        for (int i = 0; i < 4; i++) {
            mw0[i] = Bb[r * 4 + i];
            mw1[i] = Bb[(r + 8) * 4 + i];
        }

        uint32_t ap[8][4];
#pragma unroll
        for (int ni2 = 0; ni2 < 8; ni2++) {
            float aA[4] = { 0.f, 0.f, 0.f, 0.f };   // ni = 2*ni2
            float aB[4] = { 0.f, 0.f, 0.f, 0.f };   // ni = 2*ni2+1
#pragma unroll
            for (int ks = 0; ks < 4; ks++) {
                uint32_t bq[4];
                ldsm4(bq, sbKc + (uint32_t)(ni2 * 16 * KS3) * 4 + ks * 32 + kfrag);
                mma16(aA, af[ks], bq);
                mma16(aB, af[ks], bq + 2);
            }
#pragma unroll
            for (int half = 0; half < 2; half++) {
                const float* a4 = half ? aB : aA;
                const int ni = 2 * ni2 + half;
                const int sh = (ni & 3) * 8 + 2 * tq;
                uint32_t ba = mw0[ni >> 2] >> sh;
                uint32_t bb = mw1[ni >> 2] >> sh;
                uint32_t e01 = ex2h2(h2(a4[0], a4[1]));
                uint32_t e23 = ex2h2(h2(a4[2], a4[3]));
                e01 &= ((ba & 1) ? 0x0000FFFFu : 0u) | ((ba & 2) ? 0xFFFF0000u : 0u);
                e23 &= ((bb & 1) ? 0x0000FFFFu : 0u) | ((bb & 2) ? 0xFFFF0000u : 0u);
                float2 f01 = __half22float2(*(__half2*)&e01);
                float2 f23 = __half22float2(*(__half2*)&e23);
                rs0 += f01.x + f01.y;
                rs1 += f23.x + f23.y;
                if (write_attn) {
                    pu0[kt * 64 + ni * 4 + tq] = e01;
                    pu1[kt * 64 + ni * 4 + tq] = e23;
                }
                ap[ni2][half * 2]     = e01;
                ap[ni2][half * 2 + 1] = e23;
            }
        }

        // ---- PV: O += P @ V^T, A from registers, B via ldmatrix ----
#pragma unroll
        for (int ksb = 0; ksb < 8; ksb++) {
#pragma unroll
            for (int nv2 = 0; nv2 < 4; nv2++) {
                uint32_t bq[4];
                ldsm4(bq, sbVc + (uint32_t)(nv2 * 16 * VS3) * 4 + ksb * 32 + vfrag);
                mma16(oacc[nv2 * 2],     ap[ksb], bq);
                mma16(oacc[nv2 * 2 + 1], ap[ksb], bq + 2);
            }
        }

        if (kt + 1 < 16) CPA_WAIT0();
        __syncthreads();
    }

    // ---- rowsums -> 1/l (warp-local rows; quad reduce only) ----
    rs0 += __shfl_xor_sync(0xffffffffu, rs0, 1);
    rs0 += __shfl_xor_sync(0xffffffffu, rs0, 2);
    rs1 += __shfl_xor_sync(0xffffffffu, rs1, 1);
    rs1 += __shfl_xor_sync(0xffffffffu, rs1, 2);
    float* sSum = (float*)(fs + OFF3_SUM);
    float* sInv = (float*)(fs + OFF3_INV);
    if (tq == 0) { sSum[r] = rs0; sSum[r + 8] = rs1; }
    __syncthreads();
    if (tid < 128) {
        float inv = 1.f / sSum[tid];
        sInv[tid] = inv;
        Linv[(size_t)z * Lc + m0 + tid] = inv;
    }
    __syncthreads();

    // ---- O scaled by 1/l -> OH ----
    const float iv0 = sInv[r], iv1 = sInv[r + 8];
    float* O0 = OH + ((size_t)b_ * Lc + m0 + r) * Dc + h * 64;
    float* O1 = O0 + (size_t)8 * Dc;
#pragma unroll
    for (int nv = 0; nv < 8; nv++) {
        float2 t0 = { oacc[nv][0] * iv0, oacc[nv][1] * iv0 };
        float2 t1 = { oacc[nv][2] * iv1, oacc[nv][3] * iv1 };
        *(float2*)(O0 + nv * 8 + 2 * tq) = t0;
        *(float2*)(O1 + nv * 8 + 2 * tq) = t1;
    }
}

// ---------------------------------------------------------------------------
// rescale+expand: attn[row,:] = (float)PU[row,:] * Linv[row]
// ---------------------------------------------------------------------------
__global__ void __launch_bounds__(256)
rescale_k(const __half* __restrict__ pu, float* __restrict__ attn,
          const float* __restrict__ Linv)
{
    const float inv = Linv[blockIdx.x];
    const uint2* src = (const uint2*)(pu + (size_t)blockIdx.x * Lc);
    float4* dst = (float4*)(attn + (size_t)blockIdx.x * Lc);
#pragma unroll
    for (int i = 0; i < 2; i++) {
        int idx = threadIdx.x + i * 256;
        uint2 v = src[idx];
        float2 f0 = __half22float2(*(__half2*)&v.x);
        float2 f1 = __half22float2(*(__half2*)&v.y);
        float4 o = { f0.x * inv, f0.y * inv, f1.x * inv, f1.y * inv };
        dst[idx] = o;
    }
}

// ---------------------------------------------------------------------------
// 1024x1024 transpose + fp16 convert
// ---------------------------------------------------------------------------
__global__ void __launch_bounds__(256)
transpose_k(const float* __restrict__ in, __half* __restrict__ out)
{
    __shared__ float t[32][33];
    int x = blockIdx.x * 32 + threadIdx.x;
    int y0 = blockIdx.y * 32;
#pragma unroll
    for (int j = 0; j < 4; j++)
        t[threadIdx.y + j * 8][threadIdx.x] = in[(size_t)(y0 + threadIdx.y + j * 8) * 1024 + x];
    __syncthreads();
    int x2 = blockIdx.y * 32 + threadIdx.x;
    int y2 = blockIdx.x * 32;
#pragma unroll
    for (int j = 0; j < 4; j++)
        out[(size_t)(y2 + threadIdx.y + j * 8) * 1024 + x2] =
            __float2half(t[threadIdx.x][threadIdx.y + j * 8]);
}

// ---------------------------------------------------------------------------
// LayerNorm over rows of D=1024
// ---------------------------------------------------------------------------
__global__ void __launch_bounds__(256)
ln_k(const float* __restrict__ X, const float* __restrict__ g,
     const float* __restrict__ bta, float* __restrict__ O)
{
    const int t = threadIdx.x;
    const float* x = X + (size_t)blockIdx.x * Dc;
    float4 v = *(const float4*)&x[t * 4];
    float s  = v.x + v.y + v.z + v.w;
    float s2 = v.x * v.x + v.y * v.y + v.z * v.z + v.w * v.w;
#pragma unroll
    for (int o = 16; o; o >>= 1) {
        s  += __shfl_xor_sync(0xffffffffu, s, o);
        s2 += __shfl_xor_sync(0xffffffffu, s2, o);
    }
    __shared__ float rs[8], rs2[8];
    if ((t & 31) == 0) { rs[t >> 5] = s; rs2[t >> 5] = s2; }
    __syncthreads();
    float S = 0.f, S2 = 0.f;
#pragma unroll
    for (int i = 0; i < 8; i++) { S += rs[i]; S2 += rs2[i]; }
    float mean = S * (1.0f / Dc);
    float var  = S2 * (1.0f / Dc) - mean * mean;
    float inv  = rsqrtf(var + 1e-6f);

    float4 gg = *(const float4*)&g[t * 4];
    float4 bb = *(const float4*)&bta[t * 4];
    float4 r;
    r.x = (v.x - mean) * inv * gg.x + bb.x;
    r.y = (v.y - mean) * inv * gg.y + bb.y;
    r.z = (v.z - mean) * inv * gg.z + bb.z;
    r.w = (v.w - mean) * inv * gg.w + bb.w;
    *(float4*)&O[(size_t)blockIdx.x * Dc + t * 4] = r;
}

// ---------------------------------------------------------------------------
// Launch: fork-join DAG via capture-compatible events + side streams.
// ---------------------------------------------------------------------------
extern "C" void kernel_launch(void* const* d_in, const int* in_sizes, int n_in,
                              void* d_out, int out_size)
{
    const float* q    = (const float*)d_in[0];
    const float* k    = (const float*)d_in[1];
    const float* v    = (const float*)d_in[2];
    const int*   mask = (const int*)d_in[3];
    const float* w_q  = (const float*)d_in[4];
    const float* w_k  = (const float*)d_in[5];
    const float* w_v  = (const float*)d_in[6];
    const float* w_o  = (const float*)d_in[7];
    const float* ln_g = (const float*)d_in[8];
    const float* ln_b = (const float*)d_in[9];
    float* out = (float*)d_out;

    static cudaStream_t s1, s2, s3;
    static cudaEvent_t e0, e1, e2, e3, e4, e5;
    static int res_init = 0;
    if (!res_init) {
        cudaStreamCreateWithFlags(&s1, cudaStreamNonBlocking);
        cudaStreamCreateWithFlags(&s2, cudaStreamNonBlocking);
        cudaStreamCreateWithFlags(&s3, cudaStreamNonBlocking);
        cudaEventCreateWithFlags(&e0, cudaEventDisableTiming);
        cudaEventCreateWithFlags(&e1, cudaEventDisableTiming);
        cudaEventCreateWithFlags(&e2, cudaEventDisableTiming);
        cudaEventCreateWithFlags(&e3, cudaEventDisableTiming);
        cudaEventCreateWithFlags(&e4, cudaEventDisableTiming);
        cudaEventCreateWithFlags(&e5, cudaEventDisableTiming);
        res_init = 1;
    }

    __half *pQH, *pKH, *pVT, *pWTQ, *pWTK, *pWTV, *pWTO, *pPU;
    float *pOH, *pOPRE, *pL;
    uint32_t* pBM;
    cudaGetSymbolAddress((void**)&pQH,   g_QH);
    cudaGetSymbolAddress((void**)&pKH,   g_KH);
    cudaGetSymbolAddress((void**)&pVT,   g_VT);
    cudaGetSymbolAddress((void**)&pOH,   g_OH);
    cudaGetSymbolAddress((void**)&pOPRE, g_OPRE);
    cudaGetSymbolAddress((void**)&pWTQ,  g_WTQ);
    cudaGetSymbolAddress((void**)&pWTK,  g_WTK);
    cudaGetSymbolAddress((void**)&pWTV,  g_WTV);
    cudaGetSymbolAddress((void**)&pWTO,  g_WTO);
    cudaGetSymbolAddress((void**)&pBM,   g_BM);
    cudaGetSymbolAddress((void**)&pL,    g_L);
    cudaGetSymbolAddress((void**)&pPU,   g_PU);

    const long long bld  = (long long)Bc * Lc * Dc;
    const long long bhll = (long long)BHc * Lc * Lc;
    int write_attn = ((long long)out_size >= bld + bhll) ? 1 : 0;
    float* attn_out = out + bld;

    cudaFuncSetAttribute(flash_k, cudaFuncAttributeMaxDynamicSharedMemorySize, FSMEM3);

    const float qscale = 0.125f * 1.44269504088896f;
    dim3 tb(32, 8), tg(32, 32), gp(16, 32), gf(Lc / 128, BHc);

    // ---- fork: three projection branches + main (w_o transpose, maskbits) ----
    cudaEventRecord(e0, 0);
    cudaStreamWaitEvent(s1, e0, 0);
    cudaStreamWaitEvent(s2, e0, 0);
    cudaStreamWaitEvent(s3, e0, 0);

    transpose_k<<<tg, tb, 0, s1>>>(w_q, pWTQ);
    gemm_h<0,1024><<<gp, 256, 0, s1>>>(q, pWTQ, pQH, nullptr, qscale);

    transpose_k<<<tg, tb, 0, s2>>>(w_k, pWTK);
    gemm_h<0,1024><<<gp, 256, 0, s2>>>(k, pWTK, pKH, nullptr, 1.0f);

    transpose_k<<<tg, tb, 0, s3>>>(w_v, pWTV);
    gemm_h<1,1024><<<gp, 256, 0, s3>>>(v, pWTV, pVT, nullptr, 1.0f);

    transpose_k<<<tg, tb>>>(w_o, pWTO);
    maskbits_k<<<Mrows / 8, 256>>>(mask, pBM);

    // ---- join before flash ----
    cudaEventRecord(e1, s1); cudaStreamWaitEvent(0, e1, 0);
    cudaEventRecord(e2, s2); cudaStreamWaitEvent(0, e2, 0);
    cudaEventRecord(e3, s3); cudaStreamWaitEvent(0, e3, 0);

    // ---- flash (scores + exp + unnormalized fp16 P + PV) ----
    flash_k<<<gf, 256, FSMEM3>>>(pQH, pKH, pVT, pBM, pOH, pPU, pL, write_attn);

    // ---- fork: rescale (DRAM-bound) || out-proj + LN (tensor-bound) ----
    cudaEventRecord(e4, 0);
    cudaStreamWaitEvent(s1, e4, 0);
    if (write_attn)
        rescale_k<<<BHc * Lc, 256, 0, s1>>>(pPU, attn_out, pL);

    gemm_h<4,1024><<<gp, 256>>>(pOH, pWTO, pOPRE, q, 1.0f);
    ln_k<<<Mrows, 256>>>(pOPRE, ln_g, ln_b, out);

    // ---- final join ----
    cudaEventRecord(e5, s1);
    cudaStreamWaitEvent(0, e5, 0);
}

// round 14
// speedup vs baseline: 1.3715x; 1.0492x over previous
#include <cuda_runtime.h>
#include <cuda_fp16.h>
#include <math.h>
#include <stddef.h>
#include <stdint.h>

// Problem constants
#define Bc 2
#define Lc 2048
#define Dc 1024
#define Hc 16
#define Mrows (Bc*Lc)            /* 4096 */
#define BHc (Bc*Hc)              /* 32 */

// ---------------------------------------------------------------------------
// Scratch (device globals -- no allocation allowed)
// ---------------------------------------------------------------------------
__device__ __align__(16) __half g_QH[(size_t)BHc*Lc*64];    // [B,H,L,64] fp16
__device__ __align__(16) __half g_KH[(size_t)BHc*Lc*64];    // [B,H,L,64] fp16
__device__ __align__(16) __half g_VT[(size_t)BHc*64*Lc];    // [B,H,64,L] fp16
__device__ __align__(16) float  g_OH[(size_t)Mrows*Dc];     // [B,L,H*DV]
__device__ __align__(16) float  g_OPRE[(size_t)Mrows*Dc];   // pre-LayerNorm
__device__ __align__(16) __half g_WTQ[(size_t)Dc*Dc];       // [N,K] fp16
__device__ __align__(16) __half g_WTK[(size_t)Dc*Dc];
__device__ __align__(16) __half g_WTV[(size_t)Dc*Dc];
__device__ __align__(16) __half g_WTO[(size_t)Dc*Dc];
__device__ __align__(16) uint32_t g_BM[(size_t)Mrows*64];   // mask bits [B*L][64]
__device__ __align__(16) float  g_L[(size_t)BHc*Lc];        // 1/rowsum
__device__ __align__(16) __half g_PU[(size_t)BHc*Lc*Lc];    // unnormalized P fp16

// ---------------------------------------------------------------------------
// helpers
// ---------------------------------------------------------------------------
__device__ __forceinline__ uint32_t h2(float a, float b) {
    __half2 h = __floats2half2_rn(a, b);
    return *(uint32_t*)&h;
}
__device__ __forceinline__ uint32_t ex2h2(uint32_t s) {
    uint32_t r;
    asm("ex2.approx.f16x2 %0, %1;" : "=r"(r) : "r"(s));
    return r;
}
__device__ __forceinline__ void mma16(float* c, const uint32_t* a, const uint32_t* b) {
    asm volatile(
        "mma.sync.aligned.m16n8k16.row.col.f32.f16.f16.f32 "
        "{%0,%1,%2,%3}, {%4,%5,%6,%7}, {%8,%9}, {%0,%1,%2,%3};"
        : "+f"(c[0]), "+f"(c[1]), "+f"(c[2]), "+f"(c[3])
        : "r"(a[0]), "r"(a[1]), "r"(a[2]), "r"(a[3]), "r"(b[0]), "r"(b[1]));
}
__device__ __forceinline__ void ldsm4(uint32_t* r, uint32_t addr) {
    asm volatile("ldmatrix.sync.aligned.m8n8.x4.shared.b16 {%0,%1,%2,%3}, [%4];"
        : "=r"(r[0]), "=r"(r[1]), "=r"(r[2]), "=r"(r[3]) : "r"(addr));
}
__device__ __forceinline__ uint32_t smem_u32(const void* p) {
    uint32_t a;
    asm("{ .reg .u64 t; cvta.to.shared.u64 t, %1; cvt.u32.u64 %0, t; }"
        : "=r"(a) : "l"(p));
    return a;
}
__device__ __forceinline__ void cpa16(uint32_t d, const void* s) {
    asm volatile("cp.async.cg.shared.global [%0], [%1], 16;" :: "r"(d), "l"(s));
}
__device__ __forceinline__ void cpa8(uint32_t d, const void* s) {
    asm volatile("cp.async.ca.shared.global [%0], [%1], 8;" :: "r"(d), "l"(s));
}
#define CPA_COMMIT() asm volatile("cp.async.commit_group;" ::: "memory")
#define CPA_WAIT0()  asm volatile("cp.async.wait_group 0;" ::: "memory")

// ---------------------------------------------------------------------------
// fp16 warp-MMA GEMM for projections: BK=64 (half the syncs), ldmatrix frags.
// ---------------------------------------------------------------------------
#define SPAD2 36   /* u32 row stride (144B = 9*16, ldmatrix-aligned) */

template<int EPI, int KTOT>
__global__ void __launch_bounds__(256, 2)
gemm_h(const float* __restrict__ A, const __half* __restrict__ Bh,
       void* __restrict__ Cv, const float* __restrict__ resid, float scale)
{
    constexpr int NC = KTOT / 64;
    __shared__ uint32_t As[128 * SPAD2];
    __shared__ uint32_t Bs[64 * SPAD2];

    const int tid = threadIdx.x;
    const int wid = tid >> 5, lane = tid & 31;
    const int wm  = wid >> 1, wn = wid & 1;
    const int g   = lane >> 2, tq = lane & 3;
    const int m0  = blockIdx.y * 128;
    const int n0  = blockIdx.x * 64;

    const uint32_t sbA = smem_u32(As), sbB = smem_u32(Bs);
    const int lm = lane >> 3, lr = lane & 7;
    // A quadrants: M0/M1 row halves of k0-7, M2/M3 of k8-15
    const uint32_t aoff = (uint32_t)(((lm & 1) * 8 + lr) * SPAD2 + (lm >> 1) * 4) * 4;
    // B pairs: M0/M1 = k-halves of n-rows 0-7, M2/M3 of n-rows 8-15
    const uint32_t boff = (uint32_t)(((lm >> 1) * 8 + lr) * SPAD2 + (lm & 1) * 4) * 4;

    const int frow = tid >> 4, fc = tid & 15;      // A: 16 float4 per row
    const int brow = tid >> 2, bq = tid & 3;       // B: 8 uint4 per row
    const uint32_t* Bg = (const uint32_t*)Bh;

    float4 pa[8];
    uint4  pb[2];
    float acc[2][4][4] = {};

    auto g2r = [&](int c) {
        const int kc = c * 64;
#pragma unroll
        for (int j = 0; j < 8; j++)
            pa[j] = *(const float4*)(A + (size_t)(m0 + frow + j * 16) * KTOT + kc + fc * 4);
#pragma unroll
        for (int j = 0; j < 2; j++)
            pb[j] = *(const uint4*)(Bg + (size_t)(n0 + brow) * (KTOT / 2) + c * 32 + bq * 4 + j * 16);
    };
    auto r2s = [&]() {
#pragma unroll
        for (int j = 0; j < 8; j++) {
            uint2 t = { h2(pa[j].x, pa[j].y), h2(pa[j].z, pa[j].w) };
            *(uint2*)&As[(frow + j * 16) * SPAD2 + fc * 2] = t;
        }
#pragma unroll
        for (int j = 0; j < 2; j++)
            *(uint4*)&Bs[brow * SPAD2 + bq * 4 + j * 16] = pb[j];
    };

    g2r(0);
    for (int c = 0; c < NC; c++) {
        r2s();
        __syncthreads();
        if (c + 1 < NC) g2r(c + 1);

#pragma unroll
        for (int ks = 0; ks < 4; ks++) {
            uint32_t af[2][4], bf[2][4];
#pragma unroll
            for (int mi = 0; mi < 2; mi++)
                ldsm4(af[mi], sbA + (uint32_t)((wm * 32 + mi * 16) * SPAD2 + ks * 8) * 4 + aoff);
#pragma unroll
            for (int nj = 0; nj < 2; nj++)
                ldsm4(bf[nj], sbB + (uint32_t)((wn * 32 + nj * 16) * SPAD2 + ks * 8) * 4 + boff);
#pragma unroll
            for (int mi = 0; mi < 2; mi++)
#pragma unroll
                for (int nj = 0; nj < 2; nj++) {
                    mma16(acc[mi][nj * 2],     af[mi], bf[nj]);
                    mma16(acc[mi][nj * 2 + 1], af[mi], bf[nj] + 2);
                }
        }
        __syncthreads();
    }

#pragma unroll
    for (int mi = 0; mi < 2; mi++) {
#pragma unroll
        for (int ni = 0; ni < 4; ni++) {
            const float* a = acc[mi][ni];
            int r0  = m0 + wm * 32 + mi * 16 + g;
            int col = n0 + wn * 32 + ni * 8 + 2 * tq;

            if (EPI == 0) {
                uint32_t* C = (uint32_t*)Cv;
                int h = col >> 6, dk = col & 63;
#pragma unroll
                for (int p = 0; p < 2; p++) {
                    int m = r0 + p * 8;
                    int b_ = m >> 11, l = m & (Lc - 1);
                    C[((((size_t)b_ * Hc + h) * Lc + l) * 64 + dk) >> 1] =
                        h2(a[2*p] * scale, a[2*p+1] * scale);
                }
            } else if (EPI == 1) {
                __half* C = (__half*)Cv;
                int h = col >> 6, dv = col & 63;
#pragma unroll
                for (int p = 0; p < 2; p++) {
                    int m = r0 + p * 8;
                    int b_ = m >> 11, l = m & (Lc - 1);
                    size_t base = ((size_t)b_ * Hc + h) * 64;
                    C[(base + dv)     * Lc + l] = __float2half(a[2*p]);
                    C[(base + dv + 1) * Lc + l] = __float2half(a[2*p+1]);
                }
            } else {
                float* C = (float*)Cv;
#pragma unroll
                for (int p = 0; p < 2; p++) {
                    int m = r0 + p * 8;
                    size_t off = (size_t)m * Dc + col;
                    float2 r4 = *(const float2*)&resid[off];
                    float2 o = { a[2*p] + r4.x, a[2*p+1] + r4.y };
                    *(float2*)&C[off] = o;
                }
            }
        }
    }
}

// ---------------------------------------------------------------------------
// Mask compress: int32 [B*L][2048] -> bits [B*L][64]
// ---------------------------------------------------------------------------
__global__ void __launch_bounds__(256)
maskbits_k(const int* __restrict__ mask, uint32_t* __restrict__ bm)
{
    const int w = threadIdx.x >> 5, lane = threadIdx.x & 31;
    const int row = blockIdx.x * 8 + w;
    const int* mr = mask + (size_t)row * Lc;
    uint32_t* br = bm + (size_t)row * 64;
#pragma unroll 8
    for (int it = 0; it < 64; it++) {
        int v = mr[it * 32 + lane];
        uint32_t bits = __ballot_sync(0xffffffffu, v != 0);
        if (lane == 0) br[it] = bits;
    }
}

// ---------------------------------------------------------------------------
// Flash v8: register-P + ldmatrix fragments + smem-staged COALESCED PU stores
// (warp-private stage, STS during exp, row-contiguous STG.128 after PV).
// ---------------------------------------------------------------------------
#define KS3 36     /* K row stride (u32) */
#define VS3 68     /* V row stride (u32) */
#define PSTR 68    /* P stage row stride (u32): STS conflict-free */
#define OFF3_K   0                       /* [2][128][36] = 9216 u32 */
#define OFF3_V   9216                    /* [2][64][68]  = 8704 u32 */
#define OFF3_B   (9216 + 8704)           /* [2][512]     = 1024 u32 */
#define OFF3_SUM (OFF3_B + 1024)         /* [128] floats */
#define OFF3_INV (OFF3_SUM + 128)        /* [128] floats */
#define OFF3_PST (OFF3_INV + 128)        /* [8][16][68] = 8704 u32 */
#define FSMEM3   ((OFF3_PST + 8 * 16 * PSTR) * 4)   /* 111616 bytes */

__global__ void __launch_bounds__(256, 2)
flash_k(const __half* __restrict__ QH, const __half* __restrict__ KH,
        const __half* __restrict__ VT, const uint32_t* __restrict__ BM,
        float* __restrict__ OH, __half* __restrict__ PU,
        float* __restrict__ Linv, int write_attn)
{
    extern __shared__ uint32_t fs[];
    const uint32_t sb = smem_u32(fs);

    const int tid = threadIdx.x, w = tid >> 5, lane = tid & 31;
    const int g = lane >> 2, tq = lane & 3;
    const int z = blockIdx.y, m0 = blockIdx.x * 128;
    const int b_ = z >> 4, h = z & 15;
    const int r = w * 16 + g;               // local rows r, r+8

    const int lm = lane >> 3, lr = lane & 7;
    const uint32_t kfrag = (uint32_t)(((lm >> 1) * 8 + lr) * KS3 + (lm & 1) * 4) * 4;
    const uint32_t vfrag = (uint32_t)(((lm >> 1) * 8 + lr) * VS3 + (lm & 1) * 4) * 4;

    uint32_t* pstage = fs + OFF3_PST + w * 16 * PSTR;   // warp-private [16][68]

    const uint32_t* Ku  = (const uint32_t*)KH + (size_t)z * Lc * 32;
    const uint32_t* Vu  = (const uint32_t*)VT + (size_t)z * 64 * (Lc / 2);
    const uint32_t* BMb = BM + ((size_t)b_ * Lc + m0) * 64;

    auto issue = [&](int kt, int buf) {
#pragma unroll
        for (int i = 0; i < 4; i++) {
            int slot = tid + i * 256, row = slot >> 3, q4 = slot & 7;
            cpa16(sb + (OFF3_K + buf * 4608 + row * KS3 + q4 * 4) * 4,
                  Ku + (size_t)kt * 128 * 32 + row * 32 + q4 * 4);
        }
#pragma unroll
        for (int i = 0; i < 4; i++) {
            int slot = tid + i * 256, dv = slot >> 4, q16 = slot & 15;
            cpa16(sb + (OFF3_V + buf * 4352 + dv * VS3 + q16 * 4) * 4,
                  Vu + (size_t)dv * (Lc / 2) + kt * 64 + q16 * 4);
        }
        {
            int row = tid >> 1, wsel = (tid & 1) * 2;
            cpa8(sb + (OFF3_B + buf * 512 + row * 4 + wsel) * 4,
                 BMb + (size_t)row * 64 + kt * 4 + wsel);
        }
        CPA_COMMIT();
    };

    issue(0, 0);

    // ---- Q fragments (registers, loaded once from gmem) ----
    uint32_t af[4][4];
    {
        const uint32_t* QHu = (const uint32_t*)QH + ((size_t)z * Lc + m0) * 32;
#pragma unroll
        for (int ks = 0; ks < 4; ks++) {
            af[ks][0] = QHu[(size_t)r * 32 + ks * 8 + tq];
            af[ks][1] = QHu[(size_t)(r + 8) * 32 + ks * 8 + tq];
            af[ks][2] = QHu[(size_t)r * 32 + ks * 8 + tq + 4];
            af[ks][3] = QHu[(size_t)(r + 8) * 32 + ks * 8 + tq + 4];
        }
    }

    CPA_WAIT0();
    __syncthreads();

    float rs0 = 0.f, rs1 = 0.f;
    float oacc[8][4] = {};

    for (int kt = 0; kt < 16; kt++) {
        const int buf = kt & 1;
        if (kt + 1 < 16) issue(kt + 1, buf ^ 1);

        const uint32_t sbKc = sb + (OFF3_K + buf * 4608) * 4;
        const uint32_t sbVc = sb + (OFF3_V + buf * 4352) * 4;
        const uint32_t* Bb = fs + OFF3_B + buf * 512;

        uint32_t mw0[4], mw1[4];
#pragma unroll
        for (int i = 0; i < 4; i++) {
            mw0[i] = Bb[r * 4 + i];
            mw1[i] = Bb[(r + 8) * 4 + i];
        }

        uint32_t ap[8][4];
#pragma unroll
        for (int ni2 = 0; ni2 < 8; ni2++) {
            float aA[4] = { 0.f, 0.f, 0.f, 0.f };   // ni = 2*ni2
            float aB[4] = { 0.f, 0.f, 0.f, 0.f };   // ni = 2*ni2+1
#pragma unroll
            for (int ks = 0; ks < 4; ks++) {
                uint32_t bq[4];
                ldsm4(bq, sbKc + (uint32_t)(ni2 * 16 * KS3) * 4 + ks * 32 + kfrag);
                mma16(aA, af[ks], bq);
                mma16(aB, af[ks], bq + 2);
            }
#pragma unroll
            for (int half = 0; half < 2; half++) {
                const float* a4 = half ? aB : aA;
                const int ni = 2 * ni2 + half;
                const int sh = (ni & 3) * 8 + 2 * tq;
                uint32_t ba = mw0[ni >> 2] >> sh;
                uint32_t bb = mw1[ni >> 2] >> sh;
                uint32_t e01 = ex2h2(h2(a4[0], a4[1]));
                uint32_t e23 = ex2h2(h2(a4[2], a4[3]));
                e01 &= ((ba & 1) ? 0x0000FFFFu : 0u) | ((ba & 2) ? 0xFFFF0000u : 0u);
                e23 &= ((bb & 1) ? 0x0000FFFFu : 0u) | ((bb & 2) ? 0xFFFF0000u : 0u);
                float2 f01 = __half22float2(*(__half2*)&e01);
                float2 f23 = __half22float2(*(__half2*)&e23);
                rs0 += f01.x + f01.y;
                rs1 += f23.x + f23.y;
                if (write_attn) {
                    pstage[g * PSTR + ni * 4 + tq]       = e01;   // local row g
                    pstage[(g + 8) * PSTR + ni * 4 + tq] = e23;   // local row g+8
                }
                ap[ni2][half * 2]     = e01;
                ap[ni2][half * 2 + 1] = e23;
            }
        }

        // ---- PV: O += P @ V^T, A from registers, B via ldmatrix ----
#pragma unroll
        for (int ksb = 0; ksb < 8; ksb++) {
#pragma unroll
            for (int nv2 = 0; nv2 < 4; nv2++) {
                uint32_t bq[4];
                ldsm4(bq, sbVc + (uint32_t)(nv2 * 16 * VS3) * 4 + ksb * 32 + vfrag);
                mma16(oacc[nv2 * 2],     ap[ksb], bq);
                mma16(oacc[nv2 * 2 + 1], ap[ksb], bq + 2);
            }
        }

        // ---- coalesced PU copy-out: lane pair covers 32B per row ----
        if (write_attn) {
            __syncwarp();
            const int srow = lane >> 1, c2 = lane & 1;
            const uint32_t* sp = pstage + srow * PSTR + c2 * 4;
            uint32_t* pp = (uint32_t*)PU
                + ((size_t)z * Lc + m0 + w * 16 + srow) * (Lc / 2)
                + kt * 64 + c2 * 4;
#pragma unroll
            for (int j = 0; j < 8; j++) {
                uint4 t = *(const uint4*)(sp + j * 8);
                *(uint4*)(pp + j * 8) = t;
            }
            __syncwarp();
        }

        if (kt + 1 < 16) CPA_WAIT0();
        __syncthreads();
    }

    // ---- rowsums -> 1/l (warp-local rows; quad reduce only) ----
    rs0 += __shfl_xor_sync(0xffffffffu, rs0, 1);
    rs0 += __shfl_xor_sync(0xffffffffu, rs0, 2);
    rs1 += __shfl_xor_sync(0xffffffffu, rs1, 1);
    rs1 += __shfl_xor_sync(0xffffffffu, rs1, 2);
    float* sSum = (float*)(fs + OFF3_SUM);
    float* sInv = (float*)(fs + OFF3_INV);
    if (tq == 0) { sSum[r] = rs0; sSum[r + 8] = rs1; }
    __syncthreads();
    if (tid < 128) {
        float inv = 1.f / sSum[tid];
        sInv[tid] = inv;
        Linv[(size_t)z * Lc + m0 + tid] = inv;
    }
    __syncthreads();

    // ---- O scaled by 1/l -> OH ----
    const float iv0 = sInv[r], iv1 = sInv[r + 8];
    float* O0 = OH + ((size_t)b_ * Lc + m0 + r) * Dc + h * 64;
    float* O1 = O0 + (size_t)8 * Dc;
#pragma unroll
    for (int nv = 0; nv < 8; nv++) {
        float2 t0 = { oacc[nv][0] * iv0, oacc[nv][1] * iv0 };
        float2 t1 = { oacc[nv][2] * iv1, oacc[nv][3] * iv1 };
        *(float2*)(O0 + nv * 8 + 2 * tq) = t0;
        *(float2*)(O1 + nv * 8 + 2 * tq) = t1;
    }
}

// ---------------------------------------------------------------------------
// rescale+expand: attn[row,:] = (float)PU[row,:] * Linv[row]
// ---------------------------------------------------------------------------
__global__ void __launch_bounds__(256)
rescale_k(const __half* __restrict__ pu, float* __restrict__ attn,
          const float* __restrict__ Linv)
{
    const float inv = Linv[blockIdx.x];
    const uint2* src = (const uint2*)(pu + (size_t)blockIdx.x * Lc);
    float4* dst = (float4*)(attn + (size_t)blockIdx.x * Lc);
#pragma unroll
    for (int i = 0; i < 2; i++) {
        int idx = threadIdx.x + i * 256;
        uint2 v = src[idx];
        float2 f0 = __half22float2(*(__half2*)&v.x);
        float2 f1 = __half22float2(*(__half2*)&v.y);
        float4 o = { f0.x * inv, f0.y * inv, f1.x * inv, f1.y * inv };
        dst[idx] = o;
    }
}

// ---------------------------------------------------------------------------
// 1024x1024 transpose + fp16 convert
// ---------------------------------------------------------------------------
__global__ void __launch_bounds__(256)
transpose_k(const float* __restrict__ in, __half* __restrict__ out)
{
    __shared__ float t[32][33];
    int x = blockIdx.x * 32 + threadIdx.x;
    int y0 = blockIdx.y * 32;
#pragma unroll
    for (int j = 0; j < 4; j++)
        t[threadIdx.y + j * 8][threadIdx.x] = in[(size_t)(y0 + threadIdx.y + j * 8) * 1024 + x];
    __syncthreads();
    int x2 = blockIdx.y * 32 + threadIdx.x;
    int y2 = blockIdx.x * 32;
#pragma unroll
    for (int j = 0; j < 4; j++)
        out[(size_t)(y2 + threadIdx.y + j * 8) * 1024 + x2] =
            __float2half(t[threadIdx.x][threadIdx.y + j * 8]);
}

// ---------------------------------------------------------------------------
// LayerNorm over rows of D=1024
// ---------------------------------------------------------------------------
__global__ void __launch_bounds__(256)
ln_k(const float* __restrict__ X, const float* __restrict__ g,
     const float* __restrict__ bta, float* __restrict__ O)
{
    const int t = threadIdx.x;
    const float* x = X + (size_t)blockIdx.x * Dc;
    float4 v = *(const float4*)&x[t * 4];
    float s  = v.x + v.y + v.z + v.w;
    float s2 = v.x * v.x + v.y * v.y + v.z * v.z + v.w * v.w;
#pragma unroll
    for (int o = 16; o; o >>= 1) {
        s  += __shfl_xor_sync(0xffffffffu, s, o);
        s2 += __shfl_xor_sync(0xffffffffu, s2, o);
    }
    __shared__ float rs[8], rs2[8];
    if ((t & 31) == 0) { rs[t >> 5] = s; rs2[t >> 5] = s2; }
    __syncthreads();
    float S = 0.f, S2 = 0.f;
#pragma unroll
    for (int i = 0; i < 8; i++) { S += rs[i]; S2 += rs2[i]; }
    float mean = S * (1.0f / Dc);
    float var  = S2 * (1.0f / Dc) - mean * mean;
    float inv  = rsqrtf(var + 1e-6f);

    float4 gg = *(const float4*)&g[t * 4];
    float4 bb = *(const float4*)&bta[t * 4];
    float4 r;
    r.x = (v.x - mean) * inv * gg.x + bb.x;
    r.y = (v.y - mean) * inv * gg.y + bb.y;
    r.z = (v.z - mean) * inv * gg.z + bb.z;
    r.w = (v.w - mean) * inv * gg.w + bb.w;
    *(float4*)&O[(size_t)blockIdx.x * Dc + t * 4] = r;
}

// ---------------------------------------------------------------------------
// Launch: fork-join DAG via capture-compatible events + side streams.
// ---------------------------------------------------------------------------
extern "C" void kernel_launch(void* const* d_in, const int* in_sizes, int n_in,
                              void* d_out, int out_size)
{
    const float* q    = (const float*)d_in[0];
    const float* k    = (const float*)d_in[1];
    const float* v    = (const float*)d_in[2];
    const int*   mask = (const int*)d_in[3];
    const float* w_q  = (const float*)d_in[4];
    const float* w_k  = (const float*)d_in[5];
    const float* w_v  = (const float*)d_in[6];
    const float* w_o  = (const float*)d_in[7];
    const float* ln_g = (const float*)d_in[8];
    const float* ln_b = (const float*)d_in[9];
    float* out = (float*)d_out;

    static cudaStream_t s1, s2, s3;
    static cudaEvent_t e0, e1, e2, e3, e4, e5;
    static int res_init = 0;
    if (!res_init) {
        cudaStreamCreateWithFlags(&s1, cudaStreamNonBlocking);
        cudaStreamCreateWithFlags(&s2, cudaStreamNonBlocking);
        cudaStreamCreateWithFlags(&s3, cudaStreamNonBlocking);
        cudaEventCreateWithFlags(&e0, cudaEventDisableTiming);
        cudaEventCreateWithFlags(&e1, cudaEventDisableTiming);
        cudaEventCreateWithFlags(&e2, cudaEventDisableTiming);
        cudaEventCreateWithFlags(&e3, cudaEventDisableTiming);
        cudaEventCreateWithFlags(&e4, cudaEventDisableTiming);
        cudaEventCreateWithFlags(&e5, cudaEventDisableTiming);
        res_init = 1;
    }

    __half *pQH, *pKH, *pVT, *pWTQ, *pWTK, *pWTV, *pWTO, *pPU;
    float *pOH, *pOPRE, *pL;
    uint32_t* pBM;
    cudaGetSymbolAddress((void**)&pQH,   g_QH);
    cudaGetSymbolAddress((void**)&pKH,   g_KH);
    cudaGetSymbolAddress((void**)&pVT,   g_VT);
    cudaGetSymbolAddress((void**)&pOH,   g_OH);
    cudaGetSymbolAddress((void**)&pOPRE, g_OPRE);
    cudaGetSymbolAddress((void**)&pWTQ,  g_WTQ);
    cudaGetSymbolAddress((void**)&pWTK,  g_WTK);
    cudaGetSymbolAddress((void**)&pWTV,  g_WTV);
    cudaGetSymbolAddress((void**)&pWTO,  g_WTO);
    cudaGetSymbolAddress((void**)&pBM,   g_BM);
    cudaGetSymbolAddress((void**)&pL,    g_L);
    cudaGetSymbolAddress((void**)&pPU,   g_PU);

    const long long bld  = (long long)Bc * Lc * Dc;
    const long long bhll = (long long)BHc * Lc * Lc;
    int write_attn = ((long long)out_size >= bld + bhll) ? 1 : 0;
    float* attn_out = out + bld;

    cudaFuncSetAttribute(flash_k, cudaFuncAttributeMaxDynamicSharedMemorySize, FSMEM3);

    const float qscale = 0.125f * 1.44269504088896f;
    dim3 tb(32, 8), tg(32, 32), gp(16, 32), gf(Lc / 128, BHc);

    // ---- fork: three projection branches + main (w_o transpose, maskbits) ----
    cudaEventRecord(e0, 0);
    cudaStreamWaitEvent(s1, e0, 0);
    cudaStreamWaitEvent(s2, e0, 0);
    cudaStreamWaitEvent(s3, e0, 0);

    transpose_k<<<tg, tb, 0, s1>>>(w_q, pWTQ);
    gemm_h<0,1024><<<gp, 256, 0, s1>>>(q, pWTQ, pQH, nullptr, qscale);

    transpose_k<<<tg, tb, 0, s2>>>(w_k, pWTK);
    gemm_h<0,1024><<<gp, 256, 0, s2>>>(k, pWTK, pKH, nullptr, 1.0f);

    transpose_k<<<tg, tb, 0, s3>>>(w_v, pWTV);
    gemm_h<1,1024><<<gp, 256, 0, s3>>>(v, pWTV, pVT, nullptr, 1.0f);

    transpose_k<<<tg, tb>>>(w_o, pWTO);
    maskbits_k<<<Mrows / 8, 256>>>(mask, pBM);

    // ---- join before flash ----
    cudaEventRecord(e1, s1); cudaStreamWaitEvent(0, e1, 0);
    cudaEventRecord(e2, s2); cudaStreamWaitEvent(0, e2, 0);
    cudaEventRecord(e3, s3); cudaStreamWaitEvent(0, e3, 0);

    // ---- flash (scores + exp + coalesced unnormalized fp16 P + PV) ----
    flash_k<<<gf, 256, FSMEM3>>>(pQH, pKH, pVT, pBM, pOH, pPU, pL, write_attn);

    // ---- fork: rescale (DRAM-bound) || out-proj + LN (tensor-bound) ----
    cudaEventRecord(e4, 0);
    cudaStreamWaitEvent(s1, e4, 0);
    if (write_attn)
        rescale_k<<<BHc * Lc, 256, 0, s1>>>(pPU, attn_out, pL);

    gemm_h<4,1024><<<gp, 256>>>(pOH, pWTO, pOPRE, q, 1.0f);
    ln_k<<<Mrows, 256>>>(pOPRE, ln_g, ln_b, out);

    // ---- final join ----
    cudaEventRecord(e5, s1);
    cudaStreamWaitEvent(0, e5, 0);
}

// round 15
// speedup vs baseline: 1.3895x; 1.0131x over previous
#include <cuda_runtime.h>
#include <cuda_fp16.h>
#include <math.h>
#include <stddef.h>
#include <stdint.h>

// Problem constants
#define Bc 2
#define Lc 2048
#define Dc 1024
#define Hc 16
#define Mrows (Bc*Lc)            /* 4096 */
#define BHc (Bc*Hc)              /* 32 */

// ---------------------------------------------------------------------------
// Scratch (device globals -- no allocation allowed)
// ---------------------------------------------------------------------------
__device__ __align__(16) __half g_QH[(size_t)BHc*Lc*64];    // [B,H,L,64] fp16
__device__ __align__(16) __half g_KH[(size_t)BHc*Lc*64];    // [B,H,L,64] fp16
__device__ __align__(16) __half g_VT[(size_t)BHc*64*Lc];    // [B,H,64,L] fp16
__device__ __align__(16) float  g_OH[(size_t)Mrows*Dc];     // [B,L,H*DV]
__device__ __align__(16) float  g_OPRE[(size_t)Mrows*Dc];   // pre-LayerNorm
__device__ __align__(16) __half g_WTQ[(size_t)Dc*Dc];       // [N,K] fp16
__device__ __align__(16) __half g_WTK[(size_t)Dc*Dc];
__device__ __align__(16) __half g_WTV[(size_t)Dc*Dc];
__device__ __align__(16) __half g_WTO[(size_t)Dc*Dc];
__device__ __align__(16) uint32_t g_BM[(size_t)Mrows*64];   // mask bits [B*L][64]
__device__ __align__(16) float  g_L[(size_t)BHc*Lc];        // 1/rowsum
__device__ __align__(16) __half g_PU[(size_t)BHc*Lc*Lc];    // unnormalized P fp16

// ---------------------------------------------------------------------------
// helpers
// ---------------------------------------------------------------------------
__device__ __forceinline__ uint32_t h2(float a, float b) {
    __half2 h = __floats2half2_rn(a, b);
    return *(uint32_t*)&h;
}
__device__ __forceinline__ uint32_t ex2h2(uint32_t s) {
    uint32_t r;
    asm("ex2.approx.f16x2 %0, %1;" : "=r"(r) : "r"(s));
    return r;
}
__device__ __forceinline__ void mma16(float* c, const uint32_t* a, const uint32_t* b) {
    asm volatile(
        "mma.sync.aligned.m16n8k16.row.col.f32.f16.f16.f32 "
        "{%0,%1,%2,%3}, {%4,%5,%6,%7}, {%8,%9}, {%0,%1,%2,%3};"
        : "+f"(c[0]), "+f"(c[1]), "+f"(c[2]), "+f"(c[3])
        : "r"(a[0]), "r"(a[1]), "r"(a[2]), "r"(a[3]), "r"(b[0]), "r"(b[1]));
}
__device__ __forceinline__ void ldsm4(uint32_t* r, uint32_t addr) {
    asm volatile("ldmatrix.sync.aligned.m8n8.x4.shared.b16 {%0,%1,%2,%3}, [%4];"
        : "=r"(r[0]), "=r"(r[1]), "=r"(r[2]), "=r"(r[3]) : "r"(addr));
}
__device__ __forceinline__ uint32_t smem_u32(const void* p) {
    uint32_t a;
    asm("{ .reg .u64 t; cvta.to.shared.u64 t, %1; cvt.u32.u64 %0, t; }"
        : "=r"(a) : "l"(p));
    return a;
}
__device__ __forceinline__ void cpa16(uint32_t d, const void* s) {
    asm volatile("cp.async.cg.shared.global [%0], [%1], 16;" :: "r"(d), "l"(s));
}
__device__ __forceinline__ void cpa8(uint32_t d, const void* s) {
    asm volatile("cp.async.ca.shared.global [%0], [%1], 8;" :: "r"(d), "l"(s));
}
#define CPA_COMMIT() asm volatile("cp.async.commit_group;" ::: "memory")
#define CPA_WAIT0()  asm volatile("cp.async.wait_group 0;" ::: "memory")

// ---------------------------------------------------------------------------
// fp16 warp-MMA GEMM for projections: BK=64, ldmatrix frags.
// ---------------------------------------------------------------------------
#define SPAD2 36   /* u32 row stride (144B = 9*16, ldmatrix-aligned) */

template<int EPI, int KTOT>
__global__ void __launch_bounds__(256, 2)
gemm_h(const float* __restrict__ A, const __half* __restrict__ Bh,
       void* __restrict__ Cv, const float* __restrict__ resid, float scale)
{
    constexpr int NC = KTOT / 64;
    __shared__ uint32_t As[128 * SPAD2];
    __shared__ uint32_t Bs[64 * SPAD2];

    const int tid = threadIdx.x;
    const int wid = tid >> 5, lane = tid & 31;
    const int wm  = wid >> 1, wn = wid & 1;
    const int g   = lane >> 2, tq = lane & 3;
    const int m0  = blockIdx.y * 128;
    const int n0  = blockIdx.x * 64;

    const uint32_t sbA = smem_u32(As), sbB = smem_u32(Bs);
    const int lm = lane >> 3, lr = lane & 7;
    const uint32_t aoff = (uint32_t)(((lm & 1) * 8 + lr) * SPAD2 + (lm >> 1) * 4) * 4;
    const uint32_t boff = (uint32_t)(((lm >> 1) * 8 + lr) * SPAD2 + (lm & 1) * 4) * 4;

    const int frow = tid >> 4, fc = tid & 15;      // A: 16 float4 per row
    const int brow = tid >> 2, bq = tid & 3;       // B: 8 uint4 per row
    const uint32_t* Bg = (const uint32_t*)Bh;

    float4 pa[8];
    uint4  pb[2];
    float acc[2][4][4] = {};

    auto g2r = [&](int c) {
        const int kc = c * 64;
#pragma unroll
        for (int j = 0; j < 8; j++)
            pa[j] = *(const float4*)(A + (size_t)(m0 + frow + j * 16) * KTOT + kc + fc * 4);
#pragma unroll
        for (int j = 0; j < 2; j++)
            pb[j] = *(const uint4*)(Bg + (size_t)(n0 + brow) * (KTOT / 2) + c * 32 + bq * 4 + j * 16);
    };
    auto r2s = [&]() {
#pragma unroll
        for (int j = 0; j < 8; j++) {
            uint2 t = { h2(pa[j].x, pa[j].y), h2(pa[j].z, pa[j].w) };
            *(uint2*)&As[(frow + j * 16) * SPAD2 + fc * 2] = t;
        }
#pragma unroll
        for (int j = 0; j < 2; j++)
            *(uint4*)&Bs[brow * SPAD2 + bq * 4 + j * 16] = pb[j];
    };

    g2r(0);
    for (int c = 0; c < NC; c++) {
        r2s();
        __syncthreads();
        if (c + 1 < NC) g2r(c + 1);

#pragma unroll
        for (int ks = 0; ks < 4; ks++) {
            uint32_t af[2][4], bf[2][4];
#pragma unroll
            for (int mi = 0; mi < 2; mi++)
                ldsm4(af[mi], sbA + (uint32_t)((wm * 32 + mi * 16) * SPAD2 + ks * 8) * 4 + aoff);
#pragma unroll
            for (int nj = 0; nj < 2; nj++)
                ldsm4(bf[nj], sbB + (uint32_t)((wn * 32 + nj * 16) * SPAD2 + ks * 8) * 4 + boff);
#pragma unroll
            for (int mi = 0; mi < 2; mi++)
#pragma unroll
                for (int nj = 0; nj < 2; nj++) {
                    mma16(acc[mi][nj * 2],     af[mi], bf[nj]);
                    mma16(acc[mi][nj * 2 + 1], af[mi], bf[nj] + 2);
                }
        }
        __syncthreads();
    }

#pragma unroll
    for (int mi = 0; mi < 2; mi++) {
#pragma unroll
        for (int ni = 0; ni < 4; ni++) {
            const float* a = acc[mi][ni];
            int r0  = m0 + wm * 32 + mi * 16 + g;
            int col = n0 + wn * 32 + ni * 8 + 2 * tq;

            if (EPI == 0) {
                uint32_t* C = (uint32_t*)Cv;
                int h = col >> 6, dk = col & 63;
#pragma unroll
                for (int p = 0; p < 2; p++) {
                    int m = r0 + p * 8;
                    int b_ = m >> 11, l = m & (Lc - 1);
                    C[((((size_t)b_ * Hc + h) * Lc + l) * 64 + dk) >> 1] =
                        h2(a[2*p] * scale, a[2*p+1] * scale);
                }
            } else if (EPI == 1) {
                __half* C = (__half*)Cv;
                int h = col >> 6, dv = col & 63;
#pragma unroll
                for (int p = 0; p < 2; p++) {
                    int m = r0 + p * 8;
                    int b_ = m >> 11, l = m & (Lc - 1);
                    size_t base = ((size_t)b_ * Hc + h) * 64;
                    C[(base + dv)     * Lc + l] = __float2half(a[2*p]);
                    C[(base + dv + 1) * Lc + l] = __float2half(a[2*p+1]);
                }
            } else {
                float* C = (float*)Cv;
#pragma unroll
                for (int p = 0; p < 2; p++) {
                    int m = r0 + p * 8;
                    size_t off = (size_t)m * Dc + col;
                    float2 r4 = *(const float2*)&resid[off];
                    float2 o = { a[2*p] + r4.x, a[2*p+1] + r4.y };
                    *(float2*)&C[off] = o;
                }
            }
        }
    }
}

// ---------------------------------------------------------------------------
// Mask compress: int32 [B*L][2048] -> bits [B*L][64]
// ---------------------------------------------------------------------------
__global__ void __launch_bounds__(256)
maskbits_k(const int* __restrict__ mask, uint32_t* __restrict__ bm)
{
    const int w = threadIdx.x >> 5, lane = threadIdx.x & 31;
    const int row = blockIdx.x * 8 + w;
    const int* mr = mask + (size_t)row * Lc;
    uint32_t* br = bm + (size_t)row * 64;
#pragma unroll 8
    for (int it = 0; it < 64; it++) {
        int v = mr[it * 32 + lane];
        uint32_t bits = __ballot_sync(0xffffffffu, v != 0);
        if (lane == 0) br[it] = bits;
    }
}

// ---------------------------------------------------------------------------
// Flash v8.1: register-P + ldmatrix + coalesced PU stores; zbase param for
// half-grid pipeline splitting.
// ---------------------------------------------------------------------------
#define KS3 36     /* K row stride (u32) */
#define VS3 68     /* V row stride (u32) */
#define PSTR 68    /* P stage row stride (u32) */
#define OFF3_K   0                       /* [2][128][36] = 9216 u32 */
#define OFF3_V   9216                    /* [2][64][68]  = 8704 u32 */
#define OFF3_B   (9216 + 8704)           /* [2][512]     = 1024 u32 */
#define OFF3_SUM (OFF3_B + 1024)         /* [128] floats */
#define OFF3_INV (OFF3_SUM + 128)        /* [128] floats */
#define OFF3_PST (OFF3_INV + 128)        /* [8][16][68] = 8704 u32 */
#define FSMEM3   ((OFF3_PST + 8 * 16 * PSTR) * 4)   /* 111616 bytes */

__global__ void __launch_bounds__(256, 2)
flash_k(const __half* __restrict__ QH, const __half* __restrict__ KH,
        const __half* __restrict__ VT, const uint32_t* __restrict__ BM,
        float* __restrict__ OH, __half* __restrict__ PU,
        float* __restrict__ Linv, int write_attn, int zbase)
{
    extern __shared__ uint32_t fs[];
    const uint32_t sb = smem_u32(fs);

    const int tid = threadIdx.x, w = tid >> 5, lane = tid & 31;
    const int g = lane >> 2, tq = lane & 3;
    const int z = blockIdx.y + zbase, m0 = blockIdx.x * 128;
    const int b_ = z >> 4, h = z & 15;
    const int r = w * 16 + g;               // local rows r, r+8

    const int lm = lane >> 3, lr = lane & 7;
    const uint32_t kfrag = (uint32_t)(((lm >> 1) * 8 + lr) * KS3 + (lm & 1) * 4) * 4;
    const uint32_t vfrag = (uint32_t)(((lm >> 1) * 8 + lr) * VS3 + (lm & 1) * 4) * 4;

    uint32_t* pstage = fs + OFF3_PST + w * 16 * PSTR;   // warp-private [16][68]

    const uint32_t* Ku  = (const uint32_t*)KH + (size_t)z * Lc * 32;
    const uint32_t* Vu  = (const uint32_t*)VT + (size_t)z * 64 * (Lc / 2);
    const uint32_t* BMb = BM + ((size_t)b_ * Lc + m0) * 64;

    auto issue = [&](int kt, int buf) {
#pragma unroll
        for (int i = 0; i < 4; i++) {
            int slot = tid + i * 256, row = slot >> 3, q4 = slot & 7;
            cpa16(sb + (OFF3_K + buf * 4608 + row * KS3 + q4 * 4) * 4,
                  Ku + (size_t)kt * 128 * 32 + row * 32 + q4 * 4);
        }
#pragma unroll
        for (int i = 0; i < 4; i++) {
            int slot = tid + i * 256, dv = slot >> 4, q16 = slot & 15;
            cpa16(sb + (OFF3_V + buf * 4352 + dv * VS3 + q16 * 4) * 4,
                  Vu + (size_t)dv * (Lc / 2) + kt * 64 + q16 * 4);
        }
        {
            int row = tid >> 1, wsel = (tid & 1) * 2;
            cpa8(sb + (OFF3_B + buf * 512 + row * 4 + wsel) * 4,
                 BMb + (size_t)row * 64 + kt * 4 + wsel);
        }
        CPA_COMMIT();
    };

    issue(0, 0);

    // ---- Q fragments (registers, loaded once from gmem) ----
    uint32_t af[4][4];
    {
        const uint32_t* QHu = (const uint32_t*)QH + ((size_t)z * Lc + m0) * 32;
#pragma unroll
        for (int ks = 0; ks < 4; ks++) {
            af[ks][0] = QHu[(size_t)r * 32 + ks * 8 + tq];
            af[ks][1] = QHu[(size_t)(r + 8) * 32 + ks * 8 + tq];
            af[ks][2] = QHu[(size_t)r * 32 + ks * 8 + tq + 4];
            af[ks][3] = QHu[(size_t)(r + 8) * 32 + ks * 8 + tq + 4];
        }
    }

    CPA_WAIT0();
    __syncthreads();

    float rs0 = 0.f, rs1 = 0.f;
    float oacc[8][4] = {};

    for (int kt = 0; kt < 16; kt++) {
        const int buf = kt & 1;
        if (kt + 1 < 16) issue(kt + 1, buf ^ 1);

        const uint32_t sbKc = sb + (OFF3_K + buf * 4608) * 4;
        const uint32_t sbVc = sb + (OFF3_V + buf * 4352) * 4;
        const uint32_t* Bb = fs + OFF3_B + buf * 512;

        uint32_t mw0[4], mw1[4];
#pragma unroll
        for (int i = 0; i < 4; i++) {
            mw0[i] = Bb[r * 4 + i];
            mw1[i] = Bb[(r + 8) * 4 + i];
        }

        uint32_t ap[8][4];
#pragma unroll
        for (int ni2 = 0; ni2 < 8; ni2++) {
            float aA[4] = { 0.f, 0.f, 0.f, 0.f };
            float aB[4] = { 0.f, 0.f, 0.f, 0.f };
#pragma unroll
            for (int ks = 0; ks < 4; ks++) {
                uint32_t bq[4];
                ldsm4(bq, sbKc + (uint32_t)(ni2 * 16 * KS3) * 4 + ks * 32 + kfrag);
                mma16(aA, af[ks], bq);
                mma16(aB, af[ks], bq + 2);
            }
#pragma unroll
            for (int half = 0; half < 2; half++) {
                const float* a4 = half ? aB : aA;
                const int ni = 2 * ni2 + half;
                const int sh = (ni & 3) * 8 + 2 * tq;
                uint32_t ba = mw0[ni >> 2] >> sh;
                uint32_t bb = mw1[ni >> 2] >> sh;
                uint32_t e01 = ex2h2(h2(a4[0], a4[1]));
                uint32_t e23 = ex2h2(h2(a4[2], a4[3]));
                e01 &= ((ba & 1) ? 0x0000FFFFu : 0u) | ((ba & 2) ? 0xFFFF0000u : 0u);
                e23 &= ((bb & 1) ? 0x0000FFFFu : 0u) | ((bb & 2) ? 0xFFFF0000u : 0u);
                float2 f01 = __half22float2(*(__half2*)&e01);
                float2 f23 = __half22float2(*(__half2*)&e23);
                rs0 += f01.x + f01.y;
                rs1 += f23.x + f23.y;
                if (write_attn) {
                    pstage[g * PSTR + ni * 4 + tq]       = e01;
                    pstage[(g + 8) * PSTR + ni * 4 + tq] = e23;
                }
                ap[ni2][half * 2]     = e01;
                ap[ni2][half * 2 + 1] = e23;
            }
        }

        // ---- PV: O += P @ V^T ----
#pragma unroll
        for (int ksb = 0; ksb < 8; ksb++) {
#pragma unroll
            for (int nv2 = 0; nv2 < 4; nv2++) {
                uint32_t bq[4];
                ldsm4(bq, sbVc + (uint32_t)(nv2 * 16 * VS3) * 4 + ksb * 32 + vfrag);
                mma16(oacc[nv2 * 2],     ap[ksb], bq);
                mma16(oacc[nv2 * 2 + 1], ap[ksb], bq + 2);
            }
        }

        // ---- coalesced PU copy-out ----
        if (write_attn) {
            __syncwarp();
            const int srow = lane >> 1, c2 = lane & 1;
            const uint32_t* sp = pstage + srow * PSTR + c2 * 4;
            uint32_t* pp = (uint32_t*)PU
                + ((size_t)z * Lc + m0 + w * 16 + srow) * (Lc / 2)
                + kt * 64 + c2 * 4;
#pragma unroll
            for (int j = 0; j < 8; j++) {
                uint4 t = *(const uint4*)(sp + j * 8);
                *(uint4*)(pp + j * 8) = t;
            }
            __syncwarp();
        }

        if (kt + 1 < 16) CPA_WAIT0();
        __syncthreads();
    }

    // ---- rowsums -> 1/l ----
    rs0 += __shfl_xor_sync(0xffffffffu, rs0, 1);
    rs0 += __shfl_xor_sync(0xffffffffu, rs0, 2);
    rs1 += __shfl_xor_sync(0xffffffffu, rs1, 1);
    rs1 += __shfl_xor_sync(0xffffffffu, rs1, 2);
    float* sSum = (float*)(fs + OFF3_SUM);
    float* sInv = (float*)(fs + OFF3_INV);
    if (tq == 0) { sSum[r] = rs0; sSum[r + 8] = rs1; }
    __syncthreads();
    if (tid < 128) {
        float inv = 1.f / sSum[tid];
        sInv[tid] = inv;
        Linv[(size_t)z * Lc + m0 + tid] = inv;
    }
    __syncthreads();

    // ---- O scaled by 1/l -> OH ----
    const float iv0 = sInv[r], iv1 = sInv[r + 8];
    float* O0 = OH + ((size_t)b_ * Lc + m0 + r) * Dc + h * 64;
    float* O1 = O0 + (size_t)8 * Dc;
#pragma unroll
    for (int nv = 0; nv < 8; nv++) {
        float2 t0 = { oacc[nv][0] * iv0, oacc[nv][1] * iv0 };
        float2 t1 = { oacc[nv][2] * iv1, oacc[nv][3] * iv1 };
        *(float2*)(O0 + nv * 8 + 2 * tq) = t0;
        *(float2*)(O1 + nv * 8 + 2 * tq) = t1;
    }
}

// ---------------------------------------------------------------------------
// rescale+expand: attn[row,:] = (float)PU[row,:] * Linv[row]; row0 offset
// ---------------------------------------------------------------------------
__global__ void __launch_bounds__(256)
rescale_k(const __half* __restrict__ pu, float* __restrict__ attn,
          const float* __restrict__ Linv, int row0)
{
    const int row = blockIdx.x + row0;
    const float inv = Linv[row];
    const uint2* src = (const uint2*)(pu + (size_t)row * Lc);
    float4* dst = (float4*)(attn + (size_t)row * Lc);
#pragma unroll
    for (int i = 0; i < 2; i++) {
        int idx = threadIdx.x + i * 256;
        uint2 v = src[idx];
        float2 f0 = __half22float2(*(__half2*)&v.x);
        float2 f1 = __half22float2(*(__half2*)&v.y);
        float4 o = { f0.x * inv, f0.y * inv, f1.x * inv, f1.y * inv };
        dst[idx] = o;
    }
}

// ---------------------------------------------------------------------------
// 1024x1024 transpose + fp16 convert
// ---------------------------------------------------------------------------
__global__ void __launch_bounds__(256)
transpose_k(const float* __restrict__ in, __half* __restrict__ out)
{
    __shared__ float t[32][33];
    int x = blockIdx.x * 32 + threadIdx.x;
    int y0 = blockIdx.y * 32;
#pragma unroll
    for (int j = 0; j < 4; j++)
        t[threadIdx.y + j * 8][threadIdx.x] = in[(size_t)(y0 + threadIdx.y + j * 8) * 1024 + x];
    __syncthreads();
    int x2 = blockIdx.y * 32 + threadIdx.x;
    int y2 = blockIdx.x * 32;
#pragma unroll
    for (int j = 0; j < 4; j++)
        out[(size_t)(y2 + threadIdx.y + j * 8) * 1024 + x2] =
            __float2half(t[threadIdx.x][threadIdx.y + j * 8]);
}

// ---------------------------------------------------------------------------
// LayerNorm over rows of D=1024
// ---------------------------------------------------------------------------
__global__ void __launch_bounds__(256)
ln_k(const float* __restrict__ X, const float* __restrict__ g,
     const float* __restrict__ bta, float* __restrict__ O)
{
    const int t = threadIdx.x;
    const float* x = X + (size_t)blockIdx.x * Dc;
    float4 v = *(const float4*)&x[t * 4];
    float s  = v.x + v.y + v.z + v.w;
    float s2 = v.x * v.x + v.y * v.y + v.z * v.z + v.w * v.w;
#pragma unroll
    for (int o = 16; o; o >>= 1) {
        s  += __shfl_xor_sync(0xffffffffu, s, o);
        s2 += __shfl_xor_sync(0xffffffffu, s2, o);
    }
    __shared__ float rs[8], rs2[8];
    if ((t & 31) == 0) { rs[t >> 5] = s; rs2[t >> 5] = s2; }
    __syncthreads();
    float S = 0.f, S2 = 0.f;
#pragma unroll
    for (int i = 0; i < 8; i++) { S += rs[i]; S2 += rs2[i]; }
    float mean = S * (1.0f / Dc);
    float var  = S2 * (1.0f / Dc) - mean * mean;
    float inv  = rsqrtf(var + 1e-6f);

    float4 gg = *(const float4*)&g[t * 4];
    float4 bb = *(const float4*)&bta[t * 4];
    float4 r;
    r.x = (v.x - mean) * inv * gg.x + bb.x;
    r.y = (v.y - mean) * inv * gg.y + bb.y;
    r.z = (v.z - mean) * inv * gg.z + bb.z;
    r.w = (v.w - mean) * inv * gg.w + bb.w;
    *(float4*)&O[(size_t)blockIdx.x * Dc + t * 4] = r;
}

// ---------------------------------------------------------------------------
// Launch: fork-join DAG; flash split into 2 half-grids so rescale half 1
// overlaps flash half 2.
// ---------------------------------------------------------------------------
extern "C" void kernel_launch(void* const* d_in, const int* in_sizes, int n_in,
                              void* d_out, int out_size)
{
    const float* q    = (const float*)d_in[0];
    const float* k    = (const float*)d_in[1];
    const float* v    = (const float*)d_in[2];
    const int*   mask = (const int*)d_in[3];
    const float* w_q  = (const float*)d_in[4];
    const float* w_k  = (const float*)d_in[5];
    const float* w_v  = (const float*)d_in[6];
    const float* w_o  = (const float*)d_in[7];
    const float* ln_g = (const float*)d_in[8];
    const float* ln_b = (const float*)d_in[9];
    float* out = (float*)d_out;

    static cudaStream_t s1, s2, s3;
    static cudaEvent_t e0, e1, e2, e3, e4, e5, e6, e7;
    static int res_init = 0;
    if (!res_init) {
        cudaStreamCreateWithFlags(&s1, cudaStreamNonBlocking);
        cudaStreamCreateWithFlags(&s2, cudaStreamNonBlocking);
        cudaStreamCreateWithFlags(&s3, cudaStreamNonBlocking);
        cudaEventCreateWithFlags(&e0, cudaEventDisableTiming);
        cudaEventCreateWithFlags(&e1, cudaEventDisableTiming);
        cudaEventCreateWithFlags(&e2, cudaEventDisableTiming);
        cudaEventCreateWithFlags(&e3, cudaEventDisableTiming);
        cudaEventCreateWithFlags(&e4, cudaEventDisableTiming);
        cudaEventCreateWithFlags(&e5, cudaEventDisableTiming);
        cudaEventCreateWithFlags(&e6, cudaEventDisableTiming);
        cudaEventCreateWithFlags(&e7, cudaEventDisableTiming);
        res_init = 1;
    }

    __half *pQH, *pKH, *pVT, *pWTQ, *pWTK, *pWTV, *pWTO, *pPU;
    float *pOH, *pOPRE, *pL;
    uint32_t* pBM;
    cudaGetSymbolAddress((void**)&pQH,   g_QH);
    cudaGetSymbolAddress((void**)&pKH,   g_KH);
    cudaGetSymbolAddress((void**)&pVT,   g_VT);
    cudaGetSymbolAddress((void**)&pOH,   g_OH);
    cudaGetSymbolAddress((void**)&pOPRE, g_OPRE);
    cudaGetSymbolAddress((void**)&pWTQ,  g_WTQ);
    cudaGetSymbolAddress((void**)&pWTK,  g_WTK);
    cudaGetSymbolAddress((void**)&pWTV,  g_WTV);
    cudaGetSymbolAddress((void**)&pWTO,  g_WTO);
    cudaGetSymbolAddress((void**)&pBM,   g_BM);
    cudaGetSymbolAddress((void**)&pL,    g_L);
    cudaGetSymbolAddress((void**)&pPU,   g_PU);

    const long long bld  = (long long)Bc * Lc * Dc;
    const long long bhll = (long long)BHc * Lc * Lc;
    int write_attn = ((long long)out_size >= bld + bhll) ? 1 : 0;
    float* attn_out = out + bld;

    cudaFuncSetAttribute(flash_k, cudaFuncAttributeMaxDynamicSharedMemorySize, FSMEM3);

    const float qscale = 0.125f * 1.44269504088896f;
    dim3 tb(32, 8), tg(32, 32), gp(16, 32);
    dim3 gfh(Lc / 128, BHc / 2);               // half grid over heads

    // ---- fork: three projection branches + main (w_o transpose, maskbits) ----
    cudaEventRecord(e0, 0);
    cudaStreamWaitEvent(s1, e0, 0);
    cudaStreamWaitEvent(s2, e0, 0);
    cudaStreamWaitEvent(s3, e0, 0);

    transpose_k<<<tg, tb, 0, s1>>>(w_q, pWTQ);
    gemm_h<0,1024><<<gp, 256, 0, s1>>>(q, pWTQ, pQH, nullptr, qscale);

    transpose_k<<<tg, tb, 0, s2>>>(w_k, pWTK);
    gemm_h<0,1024><<<gp, 256, 0, s2>>>(k, pWTK, pKH, nullptr, 1.0f);

    transpose_k<<<tg, tb, 0, s3>>>(w_v, pWTV);
    gemm_h<1,1024><<<gp, 256, 0, s3>>>(v, pWTV, pVT, nullptr, 1.0f);

    transpose_k<<<tg, tb>>>(w_o, pWTO);
    maskbits_k<<<Mrows / 8, 256>>>(mask, pBM);

    // ---- join before flash ----
    cudaEventRecord(e1, s1); cudaStreamWaitEvent(0, e1, 0);
    cudaEventRecord(e2, s2); cudaStreamWaitEvent(0, e2, 0);
    cudaEventRecord(e3, s3); cudaStreamWaitEvent(0, e3, 0);

    // ---- flash half 1 (z 0..15) ----
    flash_k<<<gfh, 256, FSMEM3>>>(pQH, pKH, pVT, pBM, pOH, pPU, pL, write_attn, 0);
    cudaEventRecord(e6, 0);

    // ---- flash half 2 (z 16..31), while rescale half 1 runs on s1 ----
    flash_k<<<gfh, 256, FSMEM3>>>(pQH, pKH, pVT, pBM, pOH, pPU, pL, write_attn,
                                  BHc / 2);
    cudaStreamWaitEvent(s1, e6, 0);
    if (write_attn)
        rescale_k<<<(BHc / 2) * Lc, 256, 0, s1>>>(pPU, attn_out, pL, 0);

    // ---- after flash half 2: rescale half 2 on s2 || out-proj + LN on main ----
    cudaEventRecord(e4, 0);
    cudaStreamWaitEvent(s2, e4, 0);
    if (write_attn)
        rescale_k<<<(BHc / 2) * Lc, 256, 0, s2>>>(pPU, attn_out, pL,
                                                  (BHc / 2) * Lc);

    gemm_h<4,1024><<<gp, 256>>>(pOH, pWTO, pOPRE, q, 1.0f);
    ln_k<<<Mrows, 256>>>(pOPRE, ln_g, ln_b, out);

    // ---- final join ----
    cudaEventRecord(e5, s1);
    cudaStreamWaitEvent(0, e5, 0);
    cudaEventRecord(e7, s2);
    cudaStreamWaitEvent(0, e7, 0);
}

// round 16
// speedup vs baseline: 1.5330x; 1.1033x over previous
#include <cuda_runtime.h>
#include <cuda_fp16.h>
#include <math.h>
#include <stddef.h>
#include <stdint.h>

// Problem constants
#define Bc 2
#define Lc 2048
#define Dc 1024
#define Hc 16
#define Mrows (Bc*Lc)            /* 4096 */
#define BHc (Bc*Hc)              /* 32 */

// ---------------------------------------------------------------------------
// Scratch (device globals -- no allocation allowed)
// ---------------------------------------------------------------------------
__device__ __align__(16) __half g_QF[(size_t)Mrows*Dc];     // q fp16
__device__ __align__(16) __half g_KF[(size_t)Mrows*Dc];     // k fp16
__device__ __align__(16) __half g_VF[(size_t)Mrows*Dc];     // v fp16
__device__ __align__(16) __half g_QH[(size_t)BHc*Lc*64];    // [B,H,L,64] fp16
__device__ __align__(16) __half g_KH[(size_t)BHc*Lc*64];    // [B,H,L,64] fp16
__device__ __align__(16) __half g_VT[(size_t)BHc*64*Lc];    // [B,H,64,L] fp16
__device__ __align__(16) __half g_OHh[(size_t)Mrows*Dc];    // attn out fp16
__device__ __align__(16) float  g_OPRE[(size_t)Mrows*Dc];   // pre-LayerNorm
__device__ __align__(16) __half g_WTQ[(size_t)Dc*Dc];       // [N,K] fp16
__device__ __align__(16) __half g_WTK[(size_t)Dc*Dc];
__device__ __align__(16) __half g_WTV[(size_t)Dc*Dc];
__device__ __align__(16) __half g_WTO[(size_t)Dc*Dc];
__device__ __align__(16) uint32_t g_BM[(size_t)Mrows*64];   // mask bits [B*L][64]
__device__ __align__(16) float  g_L[(size_t)BHc*Lc];        // 1/rowsum
__device__ __align__(16) __half g_PU[(size_t)BHc*Lc*Lc];    // unnormalized P fp16

// ---------------------------------------------------------------------------
// helpers
// ---------------------------------------------------------------------------
__device__ __forceinline__ uint32_t h2(float a, float b) {
    __half2 h = __floats2half2_rn(a, b);
    return *(uint32_t*)&h;
}
__device__ __forceinline__ uint32_t ex2h2(uint32_t s) {
    uint32_t r;
    asm("ex2.approx.f16x2 %0, %1;" : "=r"(r) : "r"(s));
    return r;
}
__device__ __forceinline__ void mma16(float* c, const uint32_t* a, const uint32_t* b) {
    asm volatile(
        "mma.sync.aligned.m16n8k16.row.col.f32.f16.f16.f32 "
        "{%0,%1,%2,%3}, {%4,%5,%6,%7}, {%8,%9}, {%0,%1,%2,%3};"
        : "+f"(c[0]), "+f"(c[1]), "+f"(c[2]), "+f"(c[3])
        : "r"(a[0]), "r"(a[1]), "r"(a[2]), "r"(a[3]), "r"(b[0]), "r"(b[1]));
}
__device__ __forceinline__ void ldsm4(uint32_t* r, uint32_t addr) {
    asm volatile("ldmatrix.sync.aligned.m8n8.x4.shared.b16 {%0,%1,%2,%3}, [%4];"
        : "=r"(r[0]), "=r"(r[1]), "=r"(r[2]), "=r"(r[3]) : "r"(addr));
}
__device__ __forceinline__ uint32_t smem_u32(const void* p) {
    uint32_t a;
    asm("{ .reg .u64 t; cvta.to.shared.u64 t, %1; cvt.u32.u64 %0, t; }"
        : "=r"(a) : "l"(p));
    return a;
}
__device__ __forceinline__ void cpa16(uint32_t d, const void* s) {
    asm volatile("cp.async.cg.shared.global [%0], [%1], 16;" :: "r"(d), "l"(s));
}
__device__ __forceinline__ void cpa8(uint32_t d, const void* s) {
    asm volatile("cp.async.ca.shared.global [%0], [%1], 8;" :: "r"(d), "l"(s));
}
#define CPA_COMMIT() asm volatile("cp.async.commit_group;" ::: "memory")
#define CPA_WAIT0()  asm volatile("cp.async.wait_group 0;" ::: "memory")

// ---------------------------------------------------------------------------
// fp32 -> fp16 convert (8 elems/thread)
// ---------------------------------------------------------------------------
__global__ void __launch_bounds__(256)
f2h_k(const float* __restrict__ in, __half* __restrict__ out)
{
    size_t idx = ((size_t)blockIdx.x * 256 + threadIdx.x) * 8;
    float4 a = *(const float4*)(in + idx);
    float4 b = *(const float4*)(in + idx + 4);
    uint4 t = { h2(a.x, a.y), h2(a.z, a.w), h2(b.x, b.y), h2(b.z, b.w) };
    *(uint4*)(out + idx) = t;
}

// ---------------------------------------------------------------------------
// fp16 warp-MMA GEMM: A fp16 [M,K], B fp16 [N,K], cp.async staging,
// double-buffered, BK=64, ldmatrix fragments, 3 CTAs/SM.
// EPI 0: head scatter *scale   EPI 1: VT scatter   EPI 4: fp32 out + residual
// ---------------------------------------------------------------------------
#define SPAD2 36   /* u32 row stride (144B = 9*16, ldmatrix-aligned) */

template<int EPI, int KTOT>
__global__ void __launch_bounds__(256, 3)
gemm_h(const __half* __restrict__ Ah, const __half* __restrict__ Bh,
       void* __restrict__ Cv, const float* __restrict__ resid, float scale)
{
    constexpr int NC = KTOT / 64;
    __shared__ uint32_t As[2 * 128 * SPAD2];
    __shared__ uint32_t Bs[2 * 64 * SPAD2];

    const int tid = threadIdx.x;
    const int wid = tid >> 5, lane = tid & 31;
    const int wm  = wid >> 1, wn = wid & 1;
    const int g   = lane >> 2, tq = lane & 3;
    const int m0  = blockIdx.y * 128;
    const int n0  = blockIdx.x * 64;

    const uint32_t sbA = smem_u32(As), sbB = smem_u32(Bs);
    const int lm = lane >> 3, lr = lane & 7;
    const uint32_t aoff = (uint32_t)(((lm & 1) * 8 + lr) * SPAD2 + (lm >> 1) * 4) * 4;
    const uint32_t boff = (uint32_t)(((lm >> 1) * 8 + lr) * SPAD2 + (lm & 1) * 4) * 4;

    const uint32_t* Au = (const uint32_t*)Ah;   // row stride KTOT/2 u32
    const uint32_t* Bu = (const uint32_t*)Bh;

    float acc[2][4][4] = {};

    auto issueG = [&](int c, int buf) {
#pragma unroll
        for (int i = 0; i < 4; i++) {
            int slot = tid + i * 256, row = slot >> 3, q4 = slot & 7;
            cpa16(sbA + (uint32_t)(buf * 128 * SPAD2 + row * SPAD2 + q4 * 4) * 4,
                  Au + (size_t)(m0 + row) * (KTOT / 2) + c * 32 + q4 * 4);
        }
#pragma unroll
        for (int i = 0; i < 2; i++) {
            int slot = tid + i * 256, row = slot >> 3, q4 = slot & 7;
            cpa16(sbB + (uint32_t)(buf * 64 * SPAD2 + row * SPAD2 + q4 * 4) * 4,
                  Bu + (size_t)(n0 + row) * (KTOT / 2) + c * 32 + q4 * 4);
        }
        CPA_COMMIT();
    };

    issueG(0, 0);
    CPA_WAIT0();
    __syncthreads();

    for (int c = 0; c < NC; c++) {
        const int buf = c & 1;
        if (c + 1 < NC) issueG(c + 1, buf ^ 1);

        const uint32_t baseA = sbA + (uint32_t)(buf * 128 * SPAD2) * 4;
        const uint32_t baseB = sbB + (uint32_t)(buf * 64 * SPAD2) * 4;
#pragma unroll
        for (int ks = 0; ks < 4; ks++) {
            uint32_t af[2][4], bf[2][4];
#pragma unroll
            for (int mi = 0; mi < 2; mi++)
                ldsm4(af[mi], baseA + (uint32_t)((wm * 32 + mi * 16) * SPAD2 + ks * 8) * 4 + aoff);
#pragma unroll
            for (int nj = 0; nj < 2; nj++)
                ldsm4(bf[nj], baseB + (uint32_t)((wn * 32 + nj * 16) * SPAD2 + ks * 8) * 4 + boff);
#pragma unroll
            for (int mi = 0; mi < 2; mi++)
#pragma unroll
                for (int nj = 0; nj < 2; nj++) {
                    mma16(acc[mi][nj * 2],     af[mi], bf[nj]);
                    mma16(acc[mi][nj * 2 + 1], af[mi], bf[nj] + 2);
                }
        }
        if (c + 1 < NC) CPA_WAIT0();
        __syncthreads();
    }

#pragma unroll
    for (int mi = 0; mi < 2; mi++) {
#pragma unroll
        for (int ni = 0; ni < 4; ni++) {
            const float* a = acc[mi][ni];
            int r0  = m0 + wm * 32 + mi * 16 + g;
            int col = n0 + wn * 32 + ni * 8 + 2 * tq;

            if (EPI == 0) {
                uint32_t* C = (uint32_t*)Cv;
                int h = col >> 6, dk = col & 63;
#pragma unroll
                for (int p = 0; p < 2; p++) {
                    int m = r0 + p * 8;
                    int b_ = m >> 11, l = m & (Lc - 1);
                    C[((((size_t)b_ * Hc + h) * Lc + l) * 64 + dk) >> 1] =
                        h2(a[2*p] * scale, a[2*p+1] * scale);
                }
            } else if (EPI == 1) {
                __half* C = (__half*)Cv;
                int h = col >> 6, dv = col & 63;
#pragma unroll
                for (int p = 0; p < 2; p++) {
                    int m = r0 + p * 8;
                    int b_ = m >> 11, l = m & (Lc - 1);
                    size_t base = ((size_t)b_ * Hc + h) * 64;
                    C[(base + dv)     * Lc + l] = __float2half(a[2*p]);
                    C[(base + dv + 1) * Lc + l] = __float2half(a[2*p+1]);
                }
            } else {
                float* C = (float*)Cv;
#pragma unroll
                for (int p = 0; p < 2; p++) {
                    int m = r0 + p * 8;
                    size_t off = (size_t)m * Dc + col;
                    float2 r4 = *(const float2*)&resid[off];
                    float2 o = { a[2*p] + r4.x, a[2*p+1] + r4.y };
                    *(float2*)&C[off] = o;
                }
            }
        }
    }
}

// ---------------------------------------------------------------------------
// Mask compress: int32 [B*L][2048] -> bits [B*L][64]
// ---------------------------------------------------------------------------
__global__ void __launch_bounds__(256)
maskbits_k(const int* __restrict__ mask, uint32_t* __restrict__ bm)
{
    const int w = threadIdx.x >> 5, lane = threadIdx.x & 31;
    const int row = blockIdx.x * 8 + w;
    const int* mr = mask + (size_t)row * Lc;
    uint32_t* br = bm + (size_t)row * 64;
#pragma unroll 8
    for (int it = 0; it < 64; it++) {
        int v = mr[it * 32 + lane];
        uint32_t bits = __ballot_sync(0xffffffffu, v != 0);
        if (lane == 0) br[it] = bits;
    }
}

// ---------------------------------------------------------------------------
// Flash v8.2: register-P + ldmatrix + coalesced PU stores; OH written fp16.
// ---------------------------------------------------------------------------
#define KS3 36     /* K row stride (u32) */
#define VS3 68     /* V row stride (u32) */
#define PSTR 68    /* P stage row stride (u32) */
#define OFF3_K   0                       /* [2][128][36] = 9216 u32 */
#define OFF3_V   9216                    /* [2][64][68]  = 8704 u32 */
#define OFF3_B   (9216 + 8704)           /* [2][512]     = 1024 u32 */
#define OFF3_SUM (OFF3_B + 1024)         /* [128] floats */
#define OFF3_INV (OFF3_SUM + 128)        /* [128] floats */
#define OFF3_PST (OFF3_INV + 128)        /* [8][16][68] = 8704 u32 */
#define FSMEM3   ((OFF3_PST + 8 * 16 * PSTR) * 4)   /* 111616 bytes */

__global__ void __launch_bounds__(256, 2)
flash_k(const __half* __restrict__ QH, const __half* __restrict__ KH,
        const __half* __restrict__ VT, const uint32_t* __restrict__ BM,
        __half* __restrict__ OH, __half* __restrict__ PU,
        float* __restrict__ Linv, int write_attn, int zbase)
{
    extern __shared__ uint32_t fs[];
    const uint32_t sb = smem_u32(fs);

    const int tid = threadIdx.x, w = tid >> 5, lane = tid & 31;
    const int g = lane >> 2, tq = lane & 3;
    const int z = blockIdx.y + zbase, m0 = blockIdx.x * 128;
    const int b_ = z >> 4, h = z & 15;
    const int r = w * 16 + g;               // local rows r, r+8

    const int lm = lane >> 3, lr = lane & 7;
    const uint32_t kfrag = (uint32_t)(((lm >> 1) * 8 + lr) * KS3 + (lm & 1) * 4) * 4;
    const uint32_t vfrag = (uint32_t)(((lm >> 1) * 8 + lr) * VS3 + (lm & 1) * 4) * 4;

    uint32_t* pstage = fs + OFF3_PST + w * 16 * PSTR;   // warp-private [16][68]

    const uint32_t* Ku  = (const uint32_t*)KH + (size_t)z * Lc * 32;
    const uint32_t* Vu  = (const uint32_t*)VT + (size_t)z * 64 * (Lc / 2);
    const uint32_t* BMb = BM + ((size_t)b_ * Lc + m0) * 64;

    auto issue = [&](int kt, int buf) {
#pragma unroll
        for (int i = 0; i < 4; i++) {
            int slot = tid + i * 256, row = slot >> 3, q4 = slot & 7;
            cpa16(sb + (OFF3_K + buf * 4608 + row * KS3 + q4 * 4) * 4,
                  Ku + (size_t)kt * 128 * 32 + row * 32 + q4 * 4);
        }
#pragma unroll
        for (int i = 0; i < 4; i++) {
            int slot = tid + i * 256, dv = slot >> 4, q16 = slot & 15;
            cpa16(sb + (OFF3_V + buf * 4352 + dv * VS3 + q16 * 4) * 4,
                  Vu + (size_t)dv * (Lc / 2) + kt * 64 + q16 * 4);
        }
        {
            int row = tid >> 1, wsel = (tid & 1) * 2;
            cpa8(sb + (OFF3_B + buf * 512 + row * 4 + wsel) * 4,
                 BMb + (size_t)row * 64 + kt * 4 + wsel);
        }
        CPA_COMMIT();
    };

    issue(0, 0);

    // ---- Q fragments (registers, loaded once from gmem) ----
    uint32_t af[4][4];
    {
        const uint32_t* QHu = (const uint32_t*)QH + ((size_t)z * Lc + m0) * 32;
#pragma unroll
        for (int ks = 0; ks < 4; ks++) {
            af[ks][0] = QHu[(size_t)r * 32 + ks * 8 + tq];
            af[ks][1] = QHu[(size_t)(r + 8) * 32 + ks * 8 + tq];
            af[ks][2] = QHu[(size_t)r * 32 + ks * 8 + tq + 4];
            af[ks][3] = QHu[(size_t)(r + 8) * 32 + ks * 8 + tq + 4];
        }
    }

    CPA_WAIT0();
    __syncthreads();

    float rs0 = 0.f, rs1 = 0.f;
    float oacc[8][4] = {};

    for (int kt = 0; kt < 16; kt++) {
        const int buf = kt & 1;
        if (kt + 1 < 16) issue(kt + 1, buf ^ 1);

        const uint32_t sbKc = sb + (OFF3_K + buf * 4608) * 4;
        const uint32_t sbVc = sb + (OFF3_V + buf * 4352) * 4;
        const uint32_t* Bb = fs + OFF3_B + buf * 512;

        uint32_t mw0[4], mw1[4];
#pragma unroll
        for (int i = 0; i < 4; i++) {
            mw0[i] = Bb[r * 4 + i];
            mw1[i] = Bb[(r + 8) * 4 + i];
        }

        uint32_t ap[8][4];
#pragma unroll
        for (int ni2 = 0; ni2 < 8; ni2++) {
            float aA[4] = { 0.f, 0.f, 0.f, 0.f };
            float aB[4] = { 0.f, 0.f, 0.f, 0.f };
#pragma unroll
            for (int ks = 0; ks < 4; ks++) {
                uint32_t bq[4];
                ldsm4(bq, sbKc + (uint32_t)(ni2 * 16 * KS3) * 4 + ks * 32 + kfrag);
                mma16(aA, af[ks], bq);
                mma16(aB, af[ks], bq + 2);
            }
#pragma unroll
            for (int half = 0; half < 2; half++) {
                const float* a4 = half ? aB : aA;
                const int ni = 2 * ni2 + half;
                const int sh = (ni & 3) * 8 + 2 * tq;
                uint32_t ba = mw0[ni >> 2] >> sh;
                uint32_t bb = mw1[ni >> 2] >> sh;
                uint32_t e01 = ex2h2(h2(a4[0], a4[1]));
                uint32_t e23 = ex2h2(h2(a4[2], a4[3]));
                e01 &= ((ba & 1) ? 0x0000FFFFu : 0u) | ((ba & 2) ? 0xFFFF0000u : 0u);
                e23 &= ((bb & 1) ? 0x0000FFFFu : 0u) | ((bb & 2) ? 0xFFFF0000u : 0u);
                float2 f01 = __half22float2(*(__half2*)&e01);
                float2 f23 = __half22float2(*(__half2*)&e23);
                rs0 += f01.x + f01.y;
                rs1 += f23.x + f23.y;
                if (write_attn) {
                    pstage[g * PSTR + ni * 4 + tq]       = e01;
                    pstage[(g + 8) * PSTR + ni * 4 + tq] = e23;
                }
                ap[ni2][half * 2]     = e01;
                ap[ni2][half * 2 + 1] = e23;
            }
        }

        // ---- PV: O += P @ V^T ----
#pragma unroll
        for (int ksb = 0; ksb < 8; ksb++) {
#pragma unroll
            for (int nv2 = 0; nv2 < 4; nv2++) {
                uint32_t bq[4];
                ldsm4(bq, sbVc + (uint32_t)(nv2 * 16 * VS3) * 4 + ksb * 32 + vfrag);
                mma16(oacc[nv2 * 2],     ap[ksb], bq);
                mma16(oacc[nv2 * 2 + 1], ap[ksb], bq + 2);
            }
        }

        // ---- coalesced PU copy-out ----
        if (write_attn) {
            __syncwarp();
            const int srow = lane >> 1, c2 = lane & 1;
            const uint32_t* sp = pstage + srow * PSTR + c2 * 4;
            uint32_t* pp = (uint32_t*)PU
                + ((size_t)z * Lc + m0 + w * 16 + srow) * (Lc / 2)
                + kt * 64 + c2 * 4;
#pragma unroll
            for (int j = 0; j < 8; j++) {
                uint4 t = *(const uint4*)(sp + j * 8);
                *(uint4*)(pp + j * 8) = t;
            }
            __syncwarp();
        }

        if (kt + 1 < 16) CPA_WAIT0();
        __syncthreads();
    }

    // ---- rowsums -> 1/l ----
    rs0 += __shfl_xor_sync(0xffffffffu, rs0, 1);
    rs0 += __shfl_xor_sync(0xffffffffu, rs0, 2);
    rs1 += __shfl_xor_sync(0xffffffffu, rs1, 1);
    rs1 += __shfl_xor_sync(0xffffffffu, rs1, 2);
    float* sSum = (float*)(fs + OFF3_SUM);
    float* sInv = (float*)(fs + OFF3_INV);
    if (tq == 0) { sSum[r] = rs0; sSum[r + 8] = rs1; }
    __syncthreads();
    if (tid < 128) {
        float inv = 1.f / sSum[tid];
        sInv[tid] = inv;
        Linv[(size_t)z * Lc + m0 + tid] = inv;
    }
    __syncthreads();

    // ---- O scaled by 1/l -> OH (fp16) ----
    const float iv0 = sInv[r], iv1 = sInv[r + 8];
    uint32_t* O0 = (uint32_t*)OH + (((size_t)b_ * Lc + m0 + r) * Dc + h * 64) / 2;
    uint32_t* O1 = O0 + (size_t)8 * (Dc / 2);
#pragma unroll
    for (int nv = 0; nv < 8; nv++) {
        O0[nv * 4 + tq] = h2(oacc[nv][0] * iv0, oacc[nv][1] * iv0);
        O1[nv * 4 + tq] = h2(oacc[nv][2] * iv1, oacc[nv][3] * iv1);
    }
}

// ---------------------------------------------------------------------------
// rescale+expand: attn[row,:] = (float)PU[row,:] * Linv[row]; row0 offset
// ---------------------------------------------------------------------------
__global__ void __launch_bounds__(256)
rescale_k(const __half* __restrict__ pu, float* __restrict__ attn,
          const float* __restrict__ Linv, int row0)
{
    const int row = blockIdx.x + row0;
    const float inv = Linv[row];
    const uint2* src = (const uint2*)(pu + (size_t)row * Lc);
    float4* dst = (float4*)(attn + (size_t)row * Lc);
#pragma unroll
    for (int i = 0; i < 2; i++) {
        int idx = threadIdx.x + i * 256;
        uint2 v = src[idx];
        float2 f0 = __half22float2(*(__half2*)&v.x);
        float2 f1 = __half22float2(*(__half2*)&v.y);
        float4 o = { f0.x * inv, f0.y * inv, f1.x * inv, f1.y * inv };
        dst[idx] = o;
    }
}

// ---------------------------------------------------------------------------
// 1024x1024 transpose + fp16 convert
// ---------------------------------------------------------------------------
__global__ void __launch_bounds__(256)
transpose_k(const float* __restrict__ in, __half* __restrict__ out)
{
    __shared__ float t[32][33];
    int x = blockIdx.x * 32 + threadIdx.x;
    int y0 = blockIdx.y * 32;
#pragma unroll
    for (int j = 0; j < 4; j++)
        t[threadIdx.y + j * 8][threadIdx.x] = in[(size_t)(y0 + threadIdx.y + j * 8) * 1024 + x];
    __syncthreads();
    int x2 = blockIdx.y * 32 + threadIdx.x;
    int y2 = blockIdx.x * 32;
#pragma unroll
    for (int j = 0; j < 4; j++)
        out[(size_t)(y2 + threadIdx.y + j * 8) * 1024 + x2] =
            __float2half(t[threadIdx.x][threadIdx.y + j * 8]);
}

// ---------------------------------------------------------------------------
// LayerNorm over rows of D=1024
// ---------------------------------------------------------------------------
__global__ void __launch_bounds__(256)
ln_k(const float* __restrict__ X, const float* __restrict__ g,
     const float* __restrict__ bta, float* __restrict__ O)
{
    const int t = threadIdx.x;
    const float* x = X + (size_t)blockIdx.x * Dc;
    float4 v = *(const float4*)&x[t * 4];
    float s  = v.x + v.y + v.z + v.w;
    float s2 = v.x * v.x + v.y * v.y + v.z * v.z + v.w * v.w;
#pragma unroll
    for (int o = 16; o; o >>= 1) {
        s  += __shfl_xor_sync(0xffffffffu, s, o);
        s2 += __shfl_xor_sync(0xffffffffu, s2, o);
    }
    __shared__ float rs[8], rs2[8];
    if ((t & 31) == 0) { rs[t >> 5] = s; rs2[t >> 5] = s2; }
    __syncthreads();
    float S = 0.f, S2 = 0.f;
#pragma unroll
    for (int i = 0; i < 8; i++) { S += rs[i]; S2 += rs2[i]; }
    float mean = S * (1.0f / Dc);
    float var  = S2 * (1.0f / Dc) - mean * mean;
    float inv  = rsqrtf(var + 1e-6f);

    float4 gg = *(const float4*)&g[t * 4];
    float4 bb = *(const float4*)&bta[t * 4];
    float4 r;
    r.x = (v.x - mean) * inv * gg.x + bb.x;
    r.y = (v.y - mean) * inv * gg.y + bb.y;
    r.z = (v.z - mean) * inv * gg.z + bb.z;
    r.w = (v.w - mean) * inv * gg.w + bb.w;
    *(float4*)&O[(size_t)blockIdx.x * Dc + t * 4] = r;
}

// ---------------------------------------------------------------------------
// Launch: fork-join DAG; flash split into 2 half-grids so rescale half 1
// overlaps flash half 2.
// ---------------------------------------------------------------------------
extern "C" void kernel_launch(void* const* d_in, const int* in_sizes, int n_in,
                              void* d_out, int out_size)
{
    const float* q    = (const float*)d_in[0];
    const float* k    = (const float*)d_in[1];
    const float* v    = (const float*)d_in[2];
    const int*   mask = (const int*)d_in[3];
    const float* w_q  = (const float*)d_in[4];
    const float* w_k  = (const float*)d_in[5];
    const float* w_v  = (const float*)d_in[6];
    const float* w_o  = (const float*)d_in[7];
    const float* ln_g = (const float*)d_in[8];
    const float* ln_b = (const float*)d_in[9];
    float* out = (float*)d_out;

    static cudaStream_t s1, s2, s3;
    static cudaEvent_t e0, e1, e2, e3, e4, e5, e6, e7;
    static int res_init = 0;
    if (!res_init) {
        cudaStreamCreateWithFlags(&s1, cudaStreamNonBlocking);
        cudaStreamCreateWithFlags(&s2, cudaStreamNonBlocking);
        cudaStreamCreateWithFlags(&s3, cudaStreamNonBlocking);
        cudaEventCreateWithFlags(&e0, cudaEventDisableTiming);
        cudaEventCreateWithFlags(&e1, cudaEventDisableTiming);
        cudaEventCreateWithFlags(&e2, cudaEventDisableTiming);
        cudaEventCreateWithFlags(&e3, cudaEventDisableTiming);
        cudaEventCreateWithFlags(&e4, cudaEventDisableTiming);
        cudaEventCreateWithFlags(&e5, cudaEventDisableTiming);
        cudaEventCreateWithFlags(&e6, cudaEventDisableTiming);
        cudaEventCreateWithFlags(&e7, cudaEventDisableTiming);
        res_init = 1;
    }

    __half *pQF, *pKF, *pVF, *pQH, *pKH, *pVT, *pWTQ, *pWTK, *pWTV, *pWTO, *pPU, *pOHh;
    float *pOPRE, *pL;
    uint32_t* pBM;
    cudaGetSymbolAddress((void**)&pQF,   g_QF);
    cudaGetSymbolAddress((void**)&pKF,   g_KF);
    cudaGetSymbolAddress((void**)&pVF,   g_VF);
    cudaGetSymbolAddress((void**)&pQH,   g_QH);
    cudaGetSymbolAddress((void**)&pKH,   g_KH);
    cudaGetSymbolAddress((void**)&pVT,   g_VT);
    cudaGetSymbolAddress((void**)&pOHh,  g_OHh);
    cudaGetSymbolAddress((void**)&pOPRE, g_OPRE);
    cudaGetSymbolAddress((void**)&pWTQ,  g_WTQ);
    cudaGetSymbolAddress((void**)&pWTK,  g_WTK);
    cudaGetSymbolAddress((void**)&pWTV,  g_WTV);
    cudaGetSymbolAddress((void**)&pWTO,  g_WTO);
    cudaGetSymbolAddress((void**)&pBM,   g_BM);
    cudaGetSymbolAddress((void**)&pL,    g_L);
    cudaGetSymbolAddress((void**)&pPU,   g_PU);

    const long long bld  = (long long)Bc * Lc * Dc;
    const long long bhll = (long long)BHc * Lc * Lc;
    int write_attn = ((long long)out_size >= bld + bhll) ? 1 : 0;
    float* attn_out = out + bld;

    cudaFuncSetAttribute(flash_k, cudaFuncAttributeMaxDynamicSharedMemorySize, FSMEM3);

    const float qscale = 0.125f * 1.44269504088896f;
    dim3 tb(32, 8), tg(32, 32), gp(16, 32);
    dim3 gfh(Lc / 128, BHc / 2);               // half grid over heads
    const int cvb = Mrows * Dc / (256 * 8);    // 2048 blocks

    // ---- fork: three projection branches + main (w_o transpose, maskbits) ----
    cudaEventRecord(e0, 0);
    cudaStreamWaitEvent(s1, e0, 0);
    cudaStreamWaitEvent(s2, e0, 0);
    cudaStreamWaitEvent(s3, e0, 0);

    f2h_k<<<cvb, 256, 0, s1>>>(q, pQF);
    transpose_k<<<tg, tb, 0, s1>>>(w_q, pWTQ);
    gemm_h<0,1024><<<gp, 256, 0, s1>>>(pQF, pWTQ, pQH, nullptr, qscale);

    f2h_k<<<cvb, 256, 0, s2>>>(k, pKF);
    transpose_k<<<tg, tb, 0, s2>>>(w_k, pWTK);
    gemm_h<0,1024><<<gp, 256, 0, s2>>>(pKF, pWTK, pKH, nullptr, 1.0f);

    f2h_k<<<cvb, 256, 0, s3>>>(v, pVF);
    transpose_k<<<tg, tb, 0, s3>>>(w_v, pWTV);
    gemm_h<1,1024><<<gp, 256, 0, s3>>>(pVF, pWTV, pVT, nullptr, 1.0f);

    transpose_k<<<tg, tb>>>(w_o, pWTO);
    maskbits_k<<<Mrows / 8, 256>>>(mask, pBM);

    // ---- join before flash ----
    cudaEventRecord(e1, s1); cudaStreamWaitEvent(0, e1, 0);
    cudaEventRecord(e2, s2); cudaStreamWaitEvent(0, e2, 0);
    cudaEventRecord(e3, s3); cudaStreamWaitEvent(0, e3, 0);

    // ---- flash half 1 (z 0..15) ----
    flash_k<<<gfh, 256, FSMEM3>>>(pQH, pKH, pVT, pBM, pOHh, pPU, pL, write_attn, 0);
    cudaEventRecord(e6, 0);

    // ---- flash half 2 (z 16..31), while rescale half 1 runs on s1 ----
    flash_k<<<gfh, 256, FSMEM3>>>(pQH, pKH, pVT, pBM, pOHh, pPU, pL, write_attn,
                                  BHc / 2);
    cudaStreamWaitEvent(s1, e6, 0);
    if (write_attn)
        rescale_k<<<(BHc / 2) * Lc, 256, 0, s1>>>(pPU, attn_out, pL, 0);

    // ---- after flash half 2: rescale half 2 on s2 || out-proj + LN on main ----
    cudaEventRecord(e4, 0);
    cudaStreamWaitEvent(s2, e4, 0);
    if (write_attn)
        rescale_k<<<(BHc / 2) * Lc, 256, 0, s2>>>(pPU, attn_out, pL,
                                                  (BHc / 2) * Lc);

    gemm_h<4,1024><<<gp, 256>>>(pOHh, pWTO, pOPRE, q, 1.0f);
    ln_k<<<Mrows, 256>>>(pOPRE, ln_g, ln_b, out);

    // ---- final join ----
    cudaEventRecord(e5, s1);
    cudaStreamWaitEvent(0, e5, 0);
    cudaEventRecord(e7, s2);
    cudaStreamWaitEvent(0, e7, 0);
}